// round 7
// baseline (speedup 1.0000x reference)
#include <cuda_runtime.h>
#include <cuda_fp16.h>
#include <math.h>
#include <stdint.h>

// ---------------- problem constants ----------------
#define B_    2
#define S_    2048
#define DIN   2048
#define DOUT  2048
#define NH    16
#define HD    128
#define LAT   256
#define ROWS  (B_ * S_)            // 4096
#define ATT_SCALE 0.08838834764831845f   // 1/sqrt(128)

// ---------------- scratch ----------------
__device__ float g_q[ROWS * DOUT];
__device__ float g_lat[ROWS * LAT];
__device__ float g_k[ROWS * DOUT];
__device__ float g_v[ROWS * DOUT];
__device__ float g_ctx[ROWS * DOUT];

__device__ __forceinline__ uint32_t f2tf32(float x) {
    uint32_t r;
    asm("cvt.rna.tf32.f32 %0, %1;" : "=r"(r) : "f"(x));
    return r;
}

__device__ __forceinline__ void mma_tf32(float* d, const uint32_t* a, const uint32_t* b) {
    asm volatile(
        "mma.sync.aligned.m16n8k8.row.col.f32.tf32.tf32.f32 "
        "{%0,%1,%2,%3}, {%4,%5,%6,%7}, {%8,%9}, {%0,%1,%2,%3};"
        : "+f"(d[0]), "+f"(d[1]), "+f"(d[2]), "+f"(d[3])
        : "r"(a[0]), "r"(a[1]), "r"(a[2]), "r"(a[3]), "r"(b[0]), "r"(b[1]));
}

__device__ __forceinline__ void mma_f16(float* d, const uint32_t* a, const uint32_t* b) {
    asm volatile(
        "mma.sync.aligned.m16n8k16.row.col.f32.f16.f16.f32 "
        "{%0,%1,%2,%3}, {%4,%5,%6,%7}, {%8,%9}, {%0,%1,%2,%3};"
        : "+f"(d[0]), "+f"(d[1]), "+f"(d[2]), "+f"(d[3])
        : "r"(a[0]), "r"(a[1]), "r"(a[2]), "r"(a[3]), "r"(b[0]), "r"(b[1]));
}

// packed-pair slot: pair p -> u32 index so LDS.64 at (kk*8 + 2*tg) yields
// (pair tg, pair tg+4) = mma b0/b1.
__device__ __forceinline__ int ppos(int p) {
    int pp = p & 7;
    int slot = (pp < 4) ? (2 * pp) : (2 * (pp - 4) + 1);
    return ((p >> 3) << 3) + slot;
}

__device__ __forceinline__ uint32_t h2pack(float lo, float hi) {
    __half2 h = __halves2half2(__float2half_rn(lo), __float2half_rn(hi));
    return *reinterpret_cast<uint32_t*>(&h);
}

// split (x,y) into fp16 hi-pair and fp16 lo-pair
__device__ __forceinline__ void splitpack(float x, float y, uint32_t& ph, uint32_t& pl) {
    __half hx = __float2half_rn(x), hy = __float2half_rn(y);
    __half lx = __float2half_rn(x - __half2float(hx));
    __half ly = __float2half_rn(y - __half2float(hy));
    __half2 a = __halves2half2(hx, hy);
    __half2 c = __halves2half2(lx, ly);
    ph = *reinterpret_cast<uint32_t*>(&a);
    pl = *reinterpret_cast<uint32_t*>(&c);
}

// ====================================================================
// TF32 tensor-core GEMM (unchanged)
// ====================================================================
#define AS_STRIDE 36
#define BS_STRIDE 136

__global__ __launch_bounds__(256) void tf32_gemm(
    const float* __restrict__ A, const float* __restrict__ Bm,
    float* __restrict__ C, const float* __restrict__ bias,
    int M, int N, int K)
{
    __shared__ uint32_t As[128 * AS_STRIDE];
    __shared__ uint32_t Bs[32 * BS_STRIDE];

    const int t    = threadIdx.x;
    const int lane = t & 31;
    const int warp = t >> 5;
    const int bm   = blockIdx.y * 128;
    const int bn   = blockIdx.x * 128;

    const int wm = (warp >> 1) * 32;
    const int wn = (warp & 1) * 64;
    const int g  = lane >> 2;
    const int tg = lane & 3;

    const int arow = t >> 3;
    const int acol = (t & 7) * 4;
    const int brow = t >> 5;
    const int bcol = (t & 31) * 4;

    const float* Ag = A  + (size_t)(bm + arow) * K + acol;
    const float* Bg = Bm + (size_t)brow * N + bn + bcol;

    float acc[2][8][4];
#pragma unroll
    for (int mt = 0; mt < 2; mt++)
#pragma unroll
        for (int nt = 0; nt < 8; nt++)
#pragma unroll
            for (int r = 0; r < 4; r++) acc[mt][nt][r] = 0.f;

    float4 pa[4], pb[4];

#define LDAB(k0)                                                            \
    {                                                                       \
        _Pragma("unroll")                                                   \
        for (int i = 0; i < 4; i++)                                         \
            pa[i] = *(const float4*)(Ag + (size_t)(i * 32) * K + (k0));     \
        _Pragma("unroll")                                                   \
        for (int i = 0; i < 4; i++)                                         \
            pb[i] = *(const float4*)(Bg + (size_t)((k0) + i * 8) * N);      \
    }

#define STAB()                                                              \
    {                                                                       \
        _Pragma("unroll")                                                   \
        for (int i = 0; i < 4; i++) {                                       \
            uint32_t* p = &As[(arow + 32 * i) * AS_STRIDE + acol];          \
            uint4 v;                                                        \
            v.x = f2tf32(pa[i].x); v.y = f2tf32(pa[i].y);                   \
            v.z = f2tf32(pa[i].z); v.w = f2tf32(pa[i].w);                   \
            *(uint4*)p = v;                                                 \
        }                                                                   \
        _Pragma("unroll")                                                   \
        for (int i = 0; i < 4; i++) {                                       \
            uint32_t* p = &Bs[(brow + 8 * i) * BS_STRIDE + bcol];           \
            uint4 v;                                                        \
            v.x = f2tf32(pb[i].x); v.y = f2tf32(pb[i].y);                   \
            v.z = f2tf32(pb[i].z); v.w = f2tf32(pb[i].w);                   \
            *(uint4*)p = v;                                                 \
        }                                                                   \
    }

    const int nkt = K >> 5;

    LDAB(0);
    STAB();
    __syncthreads();

    for (int kt = 0; kt < nkt; kt++) {
        if (kt + 1 < nkt) LDAB((kt + 1) * 32);

#pragma unroll
        for (int k8 = 0; k8 < 32; k8 += 8) {
            uint32_t af[2][4];
            uint32_t bf[8][2];
#pragma unroll
            for (int mt = 0; mt < 2; mt++) {
                int mb = wm + mt * 16;
                af[mt][0] = As[(mb + g) * AS_STRIDE + k8 + tg];
                af[mt][1] = As[(mb + g + 8) * AS_STRIDE + k8 + tg];
                af[mt][2] = As[(mb + g) * AS_STRIDE + k8 + tg + 4];
                af[mt][3] = As[(mb + g + 8) * AS_STRIDE + k8 + tg + 4];
            }
#pragma unroll
            for (int nt = 0; nt < 8; nt++) {
                int nb = wn + nt * 8 + g;
                bf[nt][0] = Bs[(k8 + tg) * BS_STRIDE + nb];
                bf[nt][1] = Bs[(k8 + tg + 4) * BS_STRIDE + nb];
            }
#pragma unroll
            for (int mt = 0; mt < 2; mt++)
#pragma unroll
                for (int nt = 0; nt < 8; nt++)
                    mma_tf32(acc[mt][nt], af[mt], bf[nt]);
        }
        __syncthreads();
        if (kt + 1 < nkt) {
            STAB();
            __syncthreads();
        }
    }

#pragma unroll
    for (int mt = 0; mt < 2; mt++) {
        int row0 = bm + wm + mt * 16 + g;
#pragma unroll
        for (int nt = 0; nt < 8; nt++) {
            int col = bn + wn + nt * 8 + tg * 2;
            float b0 = 0.f, b1 = 0.f;
            if (bias) { b0 = bias[col]; b1 = bias[col + 1]; }
            float2 v0, v1;
            v0.x = acc[mt][nt][0] + b0;
            v0.y = acc[mt][nt][1] + b1;
            v1.x = acc[mt][nt][2] + b0;
            v1.y = acc[mt][nt][3] + b1;
            *(float2*)(C + (size_t)row0 * N + col)       = v0;
            *(float2*)(C + (size_t)(row0 + 8) * N + col) = v1;
        }
    }
#undef LDAB
#undef STAB
}

// ====================================================================
// fp16 register-resident causal flash attention (FA-2 style).
// 128 threads / 4 warps, Q tile 64 rows; warp w owns rows 16w..16w+15.
// Small CTA -> 2 independent CTAs co-resident per SM, so one CTA's
// MMA work covers the other's softmax/load latency (phase decorrelation).
// QK^T: fp16x3; softmax in registers; PV: fp16 single.
// K/V tile 32 rows, double-buffered, one __syncthreads per tile.
// ====================================================================
#define FBM 64
#define FBN 32
#define KS 72     // u32 stride: 64 pair-slots + 8 pad (stride%32==8)
#define VS 40     // u32 stride: 16 pair-slots + pad (stride%32==8)
#define FA_U32 (2*32*KS*2 + 2*128*VS)
#define FA_SMEM_BYTES (FA_U32 * 4)

__global__ __launch_bounds__(128) void flash_attn_reg(
    const float* __restrict__ Qg, const float* __restrict__ Kg,
    const float* __restrict__ Vg, float* __restrict__ Ctx)
{
    extern __shared__ uint32_t smu[];
    uint32_t* Kh = smu;                  // [2][32][KS]
    uint32_t* Kl = Kh + 2 * 32 * KS;     // [2][32][KS]
    uint32_t* Vt = Kl + 2 * 32 * KS;     // [2][128][VS] transposed packed pairs

    const int t    = threadIdx.x;
    const int lane = t & 31;
    const int warp = t >> 5;
    const int g    = lane >> 2;
    const int tg   = lane & 3;

    // longest blocks first
    const int qt = gridDim.x - 1 - blockIdx.x;
    const int qb = qt * FBM;
    const int bh = blockIdx.y;
    const int b  = bh >> 4;
    const int h  = bh & 15;

    const float* Kbase = Kg + (size_t)b * S_ * DOUT + (size_t)h * HD;
    const float* Vbase = Vg + (size_t)b * S_ * DOUT + (size_t)h * HD;

    const int gr0  = qb + warp * 16 + g;     // lane's fragment rows: gr0, gr0+8
    const int wmax = qb + warp * 16 + 15;    // warp's max row

    // ---- Q into register A-fragments (scaled, split hi/lo) ----
    uint32_t qh[8][4], ql[8][4];
    {
        const float* q0 = Qg + ((size_t)b * S_ + gr0) * DOUT + (size_t)h * HD;
        const float* q1 = q0 + (size_t)8 * DOUT;
#pragma unroll
        for (int kk = 0; kk < 8; kk++) {
            int c = 16 * kk + 2 * tg;
            float2 a0 = *(const float2*)(q0 + c);
            float2 a1 = *(const float2*)(q1 + c);
            float2 a2 = *(const float2*)(q0 + c + 8);
            float2 a3 = *(const float2*)(q1 + c + 8);
            splitpack(a0.x * ATT_SCALE, a0.y * ATT_SCALE, qh[kk][0], ql[kk][0]);
            splitpack(a1.x * ATT_SCALE, a1.y * ATT_SCALE, qh[kk][1], ql[kk][1]);
            splitpack(a2.x * ATT_SCALE, a2.y * ATT_SCALE, qh[kk][2], ql[kk][2]);
            splitpack(a3.x * ATT_SCALE, a3.y * ATT_SCALE, qh[kk][3], ql[kk][3]);
        }
    }

    float oacc[16][4];
#pragma unroll
    for (int nt = 0; nt < 16; nt++)
#pragma unroll
        for (int r = 0; r < 4; r++) oacc[nt][r] = 0.f;
    float m0 = -INFINITY, m1 = -INFINITY, l0 = 0.f, l1 = 0.f;

    // loader mappings (128 threads)
    const int vrp = t & 15;          // V row-pair 0..15
    const int vcg = (t >> 4) * 4;    // V col-group base (0,4,..,28)
    float4 pk[8], pv[8];

#define LDKV(kb_)                                                                     \
    {                                                                                 \
        _Pragma("unroll")                                                             \
        for (int i = 0; i < 8; i++) {                                                 \
            int idx = t + 128 * i;                                                    \
            int r   = idx >> 5;                                                       \
            int c4  = (idx & 31) * 4;                                                 \
            pk[i] = *(const float4*)(Kbase + (size_t)((kb_) + r) * DOUT + c4);        \
        }                                                                             \
        _Pragma("unroll")                                                             \
        for (int j = 0; j < 4; j++) {                                                 \
            pv[2 * j]     = *(const float4*)(Vbase + (size_t)((kb_) + 2 * vrp) * DOUT + (vcg + j) * 4); \
            pv[2 * j + 1] = *(const float4*)(Vbase + (size_t)((kb_) + 2 * vrp + 1) * DOUT + (vcg + j) * 4); \
        }                                                                             \
    }

#define STKV(buf)                                                                     \
    {                                                                                 \
        _Pragma("unroll")                                                             \
        for (int i = 0; i < 8; i++) {                                                 \
            int idx = t + 128 * i;                                                    \
            int r   = idx >> 5;                                                       \
            int c4  = (idx & 31) * 4;                                                 \
            int p0  = c4 >> 1;                                                        \
            uint32_t* kh = Kh + (buf) * 32 * KS + r * KS;                             \
            uint32_t* kl = Kl + (buf) * 32 * KS + r * KS;                             \
            int j0 = ppos(p0), j1 = ppos(p0 + 1);                                     \
            uint32_t ph, pl;                                                          \
            splitpack(pk[i].x, pk[i].y, ph, pl); kh[j0] = ph; kl[j0] = pl;            \
            splitpack(pk[i].z, pk[i].w, ph, pl); kh[j1] = ph; kl[j1] = pl;            \
        }                                                                             \
        {                                                                             \
            uint32_t* vp = Vt + (buf) * 128 * VS;                                     \
            int jv = ppos(vrp);                                                       \
            _Pragma("unroll")                                                         \
            for (int j = 0; j < 4; j++) {                                             \
                vp[((vcg + j) * 4 + 0) * VS + jv] = h2pack(pv[2 * j].x, pv[2 * j + 1].x); \
                vp[((vcg + j) * 4 + 1) * VS + jv] = h2pack(pv[2 * j].y, pv[2 * j + 1].y); \
                vp[((vcg + j) * 4 + 2) * VS + jv] = h2pack(pv[2 * j].z, pv[2 * j + 1].z); \
                vp[((vcg + j) * 4 + 3) * VS + jv] = h2pack(pv[2 * j].w, pv[2 * j + 1].w); \
            }                                                                         \
        }                                                                             \
    }

    const int nkt = qb / FBN + 2;   // causal: cover cols up to qb+63

    LDKV(0);
    STKV(0);
    __syncthreads();

    for (int kt = 0; kt < nkt; kt++) {
        const int kb  = kt * FBN;
        const int cur = kt & 1;
        if (kt + 1 < nkt) LDKV(kb + FBN);

        if (kb <= wmax) {   // warp has at least one unmasked column here
            const uint32_t* khb = Kh + cur * 32 * KS;
            const uint32_t* klb = Kl + cur * 32 * KS;

            // ---- S = Q K^T, fp16x3, split accumulator chains ----
            float shh[4][4], shx[4][4];
#pragma unroll
            for (int nt = 0; nt < 4; nt++)
#pragma unroll
                for (int r = 0; r < 4; r++) { shh[nt][r] = 0.f; shx[nt][r] = 0.f; }

#pragma unroll
            for (int kk = 0; kk < 8; kk++) {
#pragma unroll
                for (int nt = 0; nt < 4; nt++) {
                    int row = (nt * 8 + g) * KS + kk * 8 + 2 * tg;
                    uint2 bh2 = *(const uint2*)&khb[row];
                    uint2 bl2 = *(const uint2*)&klb[row];
                    uint32_t bhv[2] = {bh2.x, bh2.y};
                    uint32_t blv[2] = {bl2.x, bl2.y};
                    mma_f16(shh[nt], qh[kk], bhv);
                    mma_f16(shx[nt], ql[kk], bhv);
                    mma_f16(shx[nt], qh[kk], blv);
                }
            }

            // ---- combine + causal mask ----
            float s[4][4];
#pragma unroll
            for (int nt = 0; nt < 4; nt++) {
#pragma unroll
                for (int r = 0; r < 4; r++) s[nt][r] = shh[nt][r] + shx[nt][r];
                if (kb + FBN - 1 > qb + warp * 16) {
                    int cb = kb + nt * 8 + 2 * tg;
                    if (cb     > gr0)     s[nt][0] = -INFINITY;
                    if (cb + 1 > gr0)     s[nt][1] = -INFINITY;
                    if (cb     > gr0 + 8) s[nt][2] = -INFINITY;
                    if (cb + 1 > gr0 + 8) s[nt][3] = -INFINITY;
                }
            }

            // ---- online softmax in registers ----
            float mx0 = -INFINITY, mx1 = -INFINITY;
#pragma unroll
            for (int nt = 0; nt < 4; nt++) {
                mx0 = fmaxf(mx0, fmaxf(s[nt][0], s[nt][1]));
                mx1 = fmaxf(mx1, fmaxf(s[nt][2], s[nt][3]));
            }
            mx0 = fmaxf(mx0, __shfl_xor_sync(0xffffffffu, mx0, 1));
            mx0 = fmaxf(mx0, __shfl_xor_sync(0xffffffffu, mx0, 2));
            mx1 = fmaxf(mx1, __shfl_xor_sync(0xffffffffu, mx1, 1));
            mx1 = fmaxf(mx1, __shfl_xor_sync(0xffffffffu, mx1, 2));

            float nm0 = fmaxf(m0, mx0), nm1 = fmaxf(m1, mx1);
            float f0 = __expf(m0 - nm0), f1 = __expf(m1 - nm1);
            m0 = nm0; m1 = nm1;

            uint32_t pa[2][4];   // PV A-fragments (== S C-fragment relayout)
            float s0 = 0.f, s1 = 0.f;
#pragma unroll
            for (int nt = 0; nt < 4; nt++) {
                float p0 = __expf(s[nt][0] - nm0);
                float p1 = __expf(s[nt][1] - nm0);
                float p2 = __expf(s[nt][2] - nm1);
                float p3 = __expf(s[nt][3] - nm1);
                s0 += p0 + p1;
                s1 += p2 + p3;
                pa[nt >> 1][(nt & 1) * 2 + 0] = h2pack(p0, p1);
                pa[nt >> 1][(nt & 1) * 2 + 1] = h2pack(p2, p3);
            }
            s0 += __shfl_xor_sync(0xffffffffu, s0, 1);
            s0 += __shfl_xor_sync(0xffffffffu, s0, 2);
            s1 += __shfl_xor_sync(0xffffffffu, s1, 1);
            s1 += __shfl_xor_sync(0xffffffffu, s1, 2);
            l0 = l0 * f0 + s0;
            l1 = l1 * f1 + s1;

#pragma unroll
            for (int nt = 0; nt < 16; nt++) {
                oacc[nt][0] *= f0; oacc[nt][1] *= f0;
                oacc[nt][2] *= f1; oacc[nt][3] *= f1;
            }

            // ---- O += P V (fp16), 16 independent n-chains ----
            const uint32_t* vpb = Vt + cur * 128 * VS;
#pragma unroll
            for (int kk = 0; kk < 2; kk++) {
#pragma unroll
                for (int nt = 0; nt < 16; nt++) {
                    uint2 bv = *(const uint2*)&vpb[(nt * 8 + g) * VS + kk * 8 + 2 * tg];
                    uint32_t bb[2] = {bv.x, bv.y};
                    mma_f16(oacc[nt], pa[kk], bb);
                }
            }
        }

        if (kt + 1 < nkt) STKV(cur ^ 1);
        __syncthreads();
    }

    // ---- epilogue ----
    float inv0 = 1.f / l0, inv1 = 1.f / l1;
    float* o0 = Ctx + ((size_t)b * S_ + gr0) * DOUT + (size_t)h * HD;
    float* o1 = o0 + (size_t)8 * DOUT;
#pragma unroll
    for (int nt = 0; nt < 16; nt++) {
        int c = nt * 8 + 2 * tg;
        *(float2*)(o0 + c) = make_float2(oacc[nt][0] * inv0, oacc[nt][1] * inv0);
        *(float2*)(o1 + c) = make_float2(oacc[nt][2] * inv1, oacc[nt][3] * inv1);
    }
#undef LDKV
#undef STKV
}

// ====================================================================
// launch
// ====================================================================
extern "C" void kernel_launch(void* const* d_in, const int* in_sizes, int n_in,
                              void* d_out, int out_size)
{
    const float* x    = (const float*)d_in[0];
    const float* Wq   = (const float*)d_in[1];
    const float* Wdkv = (const float*)d_in[2];
    const float* Wuk  = (const float*)d_in[3];
    const float* Wuv  = (const float*)d_in[4];
    const float* Wout = (const float*)d_in[5];
    const float* bout = (const float*)d_in[6];
    float* out = (float*)d_out;

    float *q, *lat, *k, *v, *ctx;
    cudaGetSymbolAddress((void**)&q,   g_q);
    cudaGetSymbolAddress((void**)&lat, g_lat);
    cudaGetSymbolAddress((void**)&k,   g_k);
    cudaGetSymbolAddress((void**)&v,   g_v);
    cudaGetSymbolAddress((void**)&ctx, g_ctx);

    cudaFuncSetAttribute(flash_attn_reg,
                         cudaFuncAttributeMaxDynamicSharedMemorySize,
                         FA_SMEM_BYTES);

    tf32_gemm<<<dim3(DOUT / 128, ROWS / 128), 256>>>(x, Wq, q, nullptr, ROWS, DOUT, DIN);
    tf32_gemm<<<dim3(LAT / 128, ROWS / 128), 256>>>(x, Wdkv, lat, nullptr, ROWS, LAT, DIN);
    tf32_gemm<<<dim3(DOUT / 128, ROWS / 128), 256>>>(lat, Wuk, k, nullptr, ROWS, DOUT, LAT);
    tf32_gemm<<<dim3(DOUT / 128, ROWS / 128), 256>>>(lat, Wuv, v, nullptr, ROWS, DOUT, LAT);
    flash_attn_reg<<<dim3(S_ / FBM, B_ * NH), 128, FA_SMEM_BYTES>>>(q, k, v, ctx);
    tf32_gemm<<<dim3(DOUT / 128, ROWS / 128), 256>>>(ctx, Wout, out, bout, ROWS, DOUT, DOUT);
}

// round 8
// speedup vs baseline: 1.0777x; 1.0777x over previous
#include <cuda_runtime.h>
#include <cuda_fp16.h>
#include <math.h>
#include <stdint.h>

// ---------------- problem constants ----------------
#define B_    2
#define S_    2048
#define DIN   2048
#define DOUT  2048
#define NH    16
#define HD    128
#define LAT   256
#define ROWS  (B_ * S_)            // 4096
#define ATT_SCALE 0.08838834764831845f   // 1/sqrt(128)

// ---------------- scratch ----------------
__device__ float g_q[ROWS * DOUT];
__device__ float g_lat[ROWS * LAT];
__device__ float g_k[ROWS * DOUT];
__device__ float g_v[ROWS * DOUT];
__device__ float g_ctx[ROWS * DOUT];

__device__ __forceinline__ uint32_t f2tf32(float x) {
    uint32_t r;
    asm("cvt.rna.tf32.f32 %0, %1;" : "=r"(r) : "f"(x));
    return r;
}

__device__ __forceinline__ void mma_tf32(float* d, const uint32_t* a, const uint32_t* b) {
    asm volatile(
        "mma.sync.aligned.m16n8k8.row.col.f32.tf32.tf32.f32 "
        "{%0,%1,%2,%3}, {%4,%5,%6,%7}, {%8,%9}, {%0,%1,%2,%3};"
        : "+f"(d[0]), "+f"(d[1]), "+f"(d[2]), "+f"(d[3])
        : "r"(a[0]), "r"(a[1]), "r"(a[2]), "r"(a[3]), "r"(b[0]), "r"(b[1]));
}

__device__ __forceinline__ void mma_f16(float* d, const uint32_t* a, const uint32_t* b) {
    asm volatile(
        "mma.sync.aligned.m16n8k16.row.col.f32.f16.f16.f32 "
        "{%0,%1,%2,%3}, {%4,%5,%6,%7}, {%8,%9}, {%0,%1,%2,%3};"
        : "+f"(d[0]), "+f"(d[1]), "+f"(d[2]), "+f"(d[3])
        : "r"(a[0]), "r"(a[1]), "r"(a[2]), "r"(a[3]), "r"(b[0]), "r"(b[1]));
}

// packed-pair slot: pair p -> u32 index so LDS.64 at (kk*8 + 2*tg) yields
// (pair tg, pair tg+4) = mma b0/b1.
__device__ __forceinline__ int ppos(int p) {
    int pp = p & 7;
    int slot = (pp < 4) ? (2 * pp) : (2 * (pp - 4) + 1);
    return ((p >> 3) << 3) + slot;
}

__device__ __forceinline__ uint32_t h2pack(float lo, float hi) {
    __half2 h = __halves2half2(__float2half_rn(lo), __float2half_rn(hi));
    return *reinterpret_cast<uint32_t*>(&h);
}

// split (x,y) into fp16 hi-pair and fp16 lo-pair
__device__ __forceinline__ void splitpack(float x, float y, uint32_t& ph, uint32_t& pl) {
    __half hx = __float2half_rn(x), hy = __float2half_rn(y);
    __half lx = __float2half_rn(x - __half2float(hx));
    __half ly = __float2half_rn(y - __half2float(hy));
    __half2 a = __halves2half2(hx, hy);
    __half2 c = __halves2half2(lx, ly);
    ph = *reinterpret_cast<uint32_t*>(&a);
    pl = *reinterpret_cast<uint32_t*>(&c);
}

// no-op: shifts launch indices so ncu (-s 5) profiles flash_attn
__global__ void noop_k() {}

// ====================================================================
// TF32 tensor-core GEMM (unchanged)
// ====================================================================
#define AS_STRIDE 36
#define BS_STRIDE 136

__global__ __launch_bounds__(256) void tf32_gemm(
    const float* __restrict__ A, const float* __restrict__ Bm,
    float* __restrict__ C, const float* __restrict__ bias,
    int M, int N, int K)
{
    __shared__ uint32_t As[128 * AS_STRIDE];
    __shared__ uint32_t Bs[32 * BS_STRIDE];

    const int t    = threadIdx.x;
    const int lane = t & 31;
    const int warp = t >> 5;
    const int bm   = blockIdx.y * 128;
    const int bn   = blockIdx.x * 128;

    const int wm = (warp >> 1) * 32;
    const int wn = (warp & 1) * 64;
    const int g  = lane >> 2;
    const int tg = lane & 3;

    const int arow = t >> 3;
    const int acol = (t & 7) * 4;
    const int brow = t >> 5;
    const int bcol = (t & 31) * 4;

    const float* Ag = A  + (size_t)(bm + arow) * K + acol;
    const float* Bg = Bm + (size_t)brow * N + bn + bcol;

    float acc[2][8][4];
#pragma unroll
    for (int mt = 0; mt < 2; mt++)
#pragma unroll
        for (int nt = 0; nt < 8; nt++)
#pragma unroll
            for (int r = 0; r < 4; r++) acc[mt][nt][r] = 0.f;

    float4 pa[4], pb[4];

#define LDAB(k0)                                                            \
    {                                                                       \
        _Pragma("unroll")                                                   \
        for (int i = 0; i < 4; i++)                                         \
            pa[i] = *(const float4*)(Ag + (size_t)(i * 32) * K + (k0));     \
        _Pragma("unroll")                                                   \
        for (int i = 0; i < 4; i++)                                         \
            pb[i] = *(const float4*)(Bg + (size_t)((k0) + i * 8) * N);      \
    }

#define STAB()                                                              \
    {                                                                       \
        _Pragma("unroll")                                                   \
        for (int i = 0; i < 4; i++) {                                       \
            uint32_t* p = &As[(arow + 32 * i) * AS_STRIDE + acol];          \
            uint4 v;                                                        \
            v.x = f2tf32(pa[i].x); v.y = f2tf32(pa[i].y);                   \
            v.z = f2tf32(pa[i].z); v.w = f2tf32(pa[i].w);                   \
            *(uint4*)p = v;                                                 \
        }                                                                   \
        _Pragma("unroll")                                                   \
        for (int i = 0; i < 4; i++) {                                       \
            uint32_t* p = &Bs[(brow + 8 * i) * BS_STRIDE + bcol];           \
            uint4 v;                                                        \
            v.x = f2tf32(pb[i].x); v.y = f2tf32(pb[i].y);                   \
            v.z = f2tf32(pb[i].z); v.w = f2tf32(pb[i].w);                   \
            *(uint4*)p = v;                                                 \
        }                                                                   \
    }

    const int nkt = K >> 5;

    LDAB(0);
    STAB();
    __syncthreads();

    for (int kt = 0; kt < nkt; kt++) {
        if (kt + 1 < nkt) LDAB((kt + 1) * 32);

#pragma unroll
        for (int k8 = 0; k8 < 32; k8 += 8) {
            uint32_t af[2][4];
            uint32_t bf[8][2];
#pragma unroll
            for (int mt = 0; mt < 2; mt++) {
                int mb = wm + mt * 16;
                af[mt][0] = As[(mb + g) * AS_STRIDE + k8 + tg];
                af[mt][1] = As[(mb + g + 8) * AS_STRIDE + k8 + tg];
                af[mt][2] = As[(mb + g) * AS_STRIDE + k8 + tg + 4];
                af[mt][3] = As[(mb + g + 8) * AS_STRIDE + k8 + tg + 4];
            }
#pragma unroll
            for (int nt = 0; nt < 8; nt++) {
                int nb = wn + nt * 8 + g;
                bf[nt][0] = Bs[(k8 + tg) * BS_STRIDE + nb];
                bf[nt][1] = Bs[(k8 + tg + 4) * BS_STRIDE + nb];
            }
#pragma unroll
            for (int mt = 0; mt < 2; mt++)
#pragma unroll
                for (int nt = 0; nt < 8; nt++)
                    mma_tf32(acc[mt][nt], af[mt], bf[nt]);
        }
        __syncthreads();
        if (kt + 1 < nkt) {
            STAB();
            __syncthreads();
        }
    }

#pragma unroll
    for (int mt = 0; mt < 2; mt++) {
        int row0 = bm + wm + mt * 16 + g;
#pragma unroll
        for (int nt = 0; nt < 8; nt++) {
            int col = bn + wn + nt * 8 + tg * 2;
            float b0 = 0.f, b1 = 0.f;
            if (bias) { b0 = bias[col]; b1 = bias[col + 1]; }
            float2 v0, v1;
            v0.x = acc[mt][nt][0] + b0;
            v0.y = acc[mt][nt][1] + b1;
            v1.x = acc[mt][nt][2] + b0;
            v1.y = acc[mt][nt][3] + b1;
            *(float2*)(C + (size_t)row0 * N + col)       = v0;
            *(float2*)(C + (size_t)(row0 + 8) * N + col) = v1;
        }
    }
#undef LDAB
#undef STAB
}

// ====================================================================
// fp16 register-resident causal flash attention (round-6 structure).
// 256 threads / 8 warps. Q tile 128 rows; warp w owns rows 16w..16w+15.
// Q in registers (fp16 hi/lo A-fragments); QK^T fp16x3; register softmax
// with DEFERRED l-reduction; conditional O rescale; STKV overlapped
// with PV. K/V tile 32, double-buffered, one __syncthreads per tile.
// ====================================================================
#define FBM 128
#define FBN 32
#define KS 72     // u32 stride: 64 pair-slots + 8 pad (stride%32==8)
#define VS 40     // u32 stride: 16 pair-slots + pad (stride%32==8)
#define FA_U32 (2*32*KS*2 + 2*128*VS)
#define FA_SMEM_BYTES (FA_U32 * 4)

__global__ __launch_bounds__(256) void flash_attn_reg(
    const float* __restrict__ Qg, const float* __restrict__ Kg,
    const float* __restrict__ Vg, float* __restrict__ Ctx)
{
    extern __shared__ uint32_t smu[];
    uint32_t* Kh = smu;                  // [2][32][KS]
    uint32_t* Kl = Kh + 2 * 32 * KS;     // [2][32][KS]
    uint32_t* Vt = Kl + 2 * 32 * KS;     // [2][128][VS] transposed packed pairs

    const int t    = threadIdx.x;
    const int lane = t & 31;
    const int warp = t >> 5;
    const int g    = lane >> 2;
    const int tg   = lane & 3;

    // longest blocks first
    const int qt = gridDim.x - 1 - blockIdx.x;
    const int qb = qt * FBM;
    const int bh = blockIdx.y;
    const int b  = bh >> 4;
    const int h  = bh & 15;

    const float* Kbase = Kg + (size_t)b * S_ * DOUT + (size_t)h * HD;
    const float* Vbase = Vg + (size_t)b * S_ * DOUT + (size_t)h * HD;

    const int gr0  = qb + warp * 16 + g;     // lane's fragment rows: gr0, gr0+8
    const int wmax = qb + warp * 16 + 15;    // warp's max row

    // ---- Q into register A-fragments (scaled, split hi/lo) ----
    uint32_t qh[8][4], ql[8][4];
    {
        const float* q0 = Qg + ((size_t)b * S_ + gr0) * DOUT + (size_t)h * HD;
        const float* q1 = q0 + (size_t)8 * DOUT;
#pragma unroll
        for (int kk = 0; kk < 8; kk++) {
            int c = 16 * kk + 2 * tg;
            float2 a0 = *(const float2*)(q0 + c);
            float2 a1 = *(const float2*)(q1 + c);
            float2 a2 = *(const float2*)(q0 + c + 8);
            float2 a3 = *(const float2*)(q1 + c + 8);
            splitpack(a0.x * ATT_SCALE, a0.y * ATT_SCALE, qh[kk][0], ql[kk][0]);
            splitpack(a1.x * ATT_SCALE, a1.y * ATT_SCALE, qh[kk][1], ql[kk][1]);
            splitpack(a2.x * ATT_SCALE, a2.y * ATT_SCALE, qh[kk][2], ql[kk][2]);
            splitpack(a3.x * ATT_SCALE, a3.y * ATT_SCALE, qh[kk][3], ql[kk][3]);
        }
    }

    float oacc[16][4];
#pragma unroll
    for (int nt = 0; nt < 16; nt++)
#pragma unroll
        for (int r = 0; r < 4; r++) oacc[nt][r] = 0.f;
    float m0 = -INFINITY, m1 = -INFINITY;
    float l0 = 0.f, l1 = 0.f;          // PER-LANE partial row sums (deferred reduce)

    // loader mappings (256 threads)
    const int vrp  = t & 15;          // V row-pair 0..15
    const int vcg  = (t >> 4) * 2;    // V col-group base (0,2,..,30)
    float4 pk[4], pv[4];

#define LDKV(kb_)                                                                     \
    {                                                                                 \
        _Pragma("unroll")                                                             \
        for (int i = 0; i < 4; i++) {                                                 \
            int idx = t + 256 * i;                                                    \
            int r   = idx >> 5;                                                       \
            int c4  = (idx & 31) * 4;                                                 \
            pk[i] = *(const float4*)(Kbase + (size_t)((kb_) + r) * DOUT + c4);        \
        }                                                                             \
        pv[0] = *(const float4*)(Vbase + (size_t)((kb_) + 2 * vrp) * DOUT + vcg * 4); \
        pv[1] = *(const float4*)(Vbase + (size_t)((kb_) + 2 * vrp + 1) * DOUT + vcg * 4); \
        pv[2] = *(const float4*)(Vbase + (size_t)((kb_) + 2 * vrp) * DOUT + (vcg + 1) * 4); \
        pv[3] = *(const float4*)(Vbase + (size_t)((kb_) + 2 * vrp + 1) * DOUT + (vcg + 1) * 4); \
    }

#define STKV(buf)                                                                     \
    {                                                                                 \
        _Pragma("unroll")                                                             \
        for (int i = 0; i < 4; i++) {                                                 \
            int idx = t + 256 * i;                                                    \
            int r   = idx >> 5;                                                       \
            int c4  = (idx & 31) * 4;                                                 \
            int p0  = c4 >> 1;                                                        \
            uint32_t* kh = Kh + (buf) * 32 * KS + r * KS;                             \
            uint32_t* kl = Kl + (buf) * 32 * KS + r * KS;                             \
            int j0 = ppos(p0), j1 = ppos(p0 + 1);                                     \
            uint32_t ph, pl;                                                          \
            splitpack(pk[i].x, pk[i].y, ph, pl); kh[j0] = ph; kl[j0] = pl;            \
            splitpack(pk[i].z, pk[i].w, ph, pl); kh[j1] = ph; kl[j1] = pl;            \
        }                                                                             \
        {                                                                             \
            uint32_t* vp = Vt + (buf) * 128 * VS;                                     \
            int jv = ppos(vrp);                                                       \
            vp[(vcg * 4 + 0) * VS + jv] = h2pack(pv[0].x, pv[1].x);                   \
            vp[(vcg * 4 + 1) * VS + jv] = h2pack(pv[0].y, pv[1].y);                   \
            vp[(vcg * 4 + 2) * VS + jv] = h2pack(pv[0].z, pv[1].z);                   \
            vp[(vcg * 4 + 3) * VS + jv] = h2pack(pv[0].w, pv[1].w);                   \
            vp[((vcg + 1) * 4 + 0) * VS + jv] = h2pack(pv[2].x, pv[3].x);             \
            vp[((vcg + 1) * 4 + 1) * VS + jv] = h2pack(pv[2].y, pv[3].y);             \
            vp[((vcg + 1) * 4 + 2) * VS + jv] = h2pack(pv[2].z, pv[3].z);             \
            vp[((vcg + 1) * 4 + 3) * VS + jv] = h2pack(pv[2].w, pv[3].w);             \
        }                                                                             \
    }

    const int nkt = qb / FBN + 4;

    LDKV(0);
    STKV(0);
    __syncthreads();

    for (int kt = 0; kt < nkt; kt++) {
        const int kb  = kt * FBN;
        const int cur = kt & 1;
        const bool more = (kt + 1 < nkt);
        if (more) LDKV(kb + FBN);

        if (kb <= wmax) {   // warp has at least one unmasked column here
            const uint32_t* khb = Kh + cur * 32 * KS;
            const uint32_t* klb = Kl + cur * 32 * KS;

            // ---- S = Q K^T, fp16x3, split accumulator chains ----
            float shh[4][4], shx[4][4];
#pragma unroll
            for (int nt = 0; nt < 4; nt++)
#pragma unroll
                for (int r = 0; r < 4; r++) { shh[nt][r] = 0.f; shx[nt][r] = 0.f; }

#pragma unroll
            for (int kk = 0; kk < 8; kk++) {
#pragma unroll
                for (int nt = 0; nt < 4; nt++) {
                    int row = (nt * 8 + g) * KS + kk * 8 + 2 * tg;
                    uint2 bh2 = *(const uint2*)&khb[row];
                    uint2 bl2 = *(const uint2*)&klb[row];
                    uint32_t bhv[2] = {bh2.x, bh2.y};
                    uint32_t blv[2] = {bl2.x, bl2.y};
                    mma_f16(shh[nt], qh[kk], bhv);
                    mma_f16(shx[nt], ql[kk], bhv);
                    mma_f16(shx[nt], qh[kk], blv);
                }
            }

            // ---- combine + causal mask ----
            float s[4][4];
#pragma unroll
            for (int nt = 0; nt < 4; nt++) {
#pragma unroll
                for (int r = 0; r < 4; r++) s[nt][r] = shh[nt][r] + shx[nt][r];
                if (kb + FBN - 1 > qb + warp * 16) {
                    int cb = kb + nt * 8 + 2 * tg;
                    if (cb     > gr0)     s[nt][0] = -INFINITY;
                    if (cb + 1 > gr0)     s[nt][1] = -INFINITY;
                    if (cb     > gr0 + 8) s[nt][2] = -INFINITY;
                    if (cb + 1 > gr0 + 8) s[nt][3] = -INFINITY;
                }
            }

            // ---- online softmax (max via shuffles; l kept as lane partials) ----
            float mx0 = -INFINITY, mx1 = -INFINITY;
#pragma unroll
            for (int nt = 0; nt < 4; nt++) {
                mx0 = fmaxf(mx0, fmaxf(s[nt][0], s[nt][1]));
                mx1 = fmaxf(mx1, fmaxf(s[nt][2], s[nt][3]));
            }
            mx0 = fmaxf(mx0, __shfl_xor_sync(0xffffffffu, mx0, 1));
            mx0 = fmaxf(mx0, __shfl_xor_sync(0xffffffffu, mx0, 2));
            mx1 = fmaxf(mx1, __shfl_xor_sync(0xffffffffu, mx1, 1));
            mx1 = fmaxf(mx1, __shfl_xor_sync(0xffffffffu, mx1, 2));

            float nm0 = fmaxf(m0, mx0), nm1 = fmaxf(m1, mx1);
            float f0 = __expf(m0 - nm0), f1 = __expf(m1 - nm1);
            m0 = nm0; m1 = nm1;

            uint32_t pa[2][4];   // PV A-fragments (== S C-fragment relayout)
            float s0 = 0.f, s1 = 0.f;
#pragma unroll
            for (int nt = 0; nt < 4; nt++) {
                float p0 = __expf(s[nt][0] - nm0);
                float p1 = __expf(s[nt][1] - nm0);
                float p2 = __expf(s[nt][2] - nm1);
                float p3 = __expf(s[nt][3] - nm1);
                s0 += p0 + p1;
                s1 += p2 + p3;
                pa[nt >> 1][(nt & 1) * 2 + 0] = h2pack(p0, p1);
                pa[nt >> 1][(nt & 1) * 2 + 1] = h2pack(p2, p3);
            }
            l0 = l0 * f0 + s0;   // lane-partial; reduced at epilogue
            l1 = l1 * f1 + s1;

            // ---- store next K/V tile while softmax results settle ----
            if (more) STKV(cur ^ 1);

            // ---- conditional O rescale ----
            if (!__all_sync(0xffffffffu, (f0 == 1.f) && (f1 == 1.f))) {
#pragma unroll
                for (int nt = 0; nt < 16; nt++) {
                    oacc[nt][0] *= f0; oacc[nt][1] *= f0;
                    oacc[nt][2] *= f1; oacc[nt][3] *= f1;
                }
            }

            // ---- O += P V (fp16), 16 independent n-chains ----
            const uint32_t* vpb = Vt + cur * 128 * VS;
#pragma unroll
            for (int kk = 0; kk < 2; kk++) {
#pragma unroll
                for (int nt = 0; nt < 16; nt++) {
                    uint2 bv = *(const uint2*)&vpb[(nt * 8 + g) * VS + kk * 8 + 2 * tg];
                    uint32_t bb[2] = {bv.x, bv.y};
                    mma_f16(oacc[nt], pa[kk], bb);
                }
            }
        } else {
            if (more) STKV(cur ^ 1);
        }

        __syncthreads();
    }

    // ---- epilogue: reduce l partials, normalize, store ----
    l0 += __shfl_xor_sync(0xffffffffu, l0, 1);
    l0 += __shfl_xor_sync(0xffffffffu, l0, 2);
    l1 += __shfl_xor_sync(0xffffffffu, l1, 1);
    l1 += __shfl_xor_sync(0xffffffffu, l1, 2);
    float inv0 = 1.f / l0, inv1 = 1.f / l1;
    float* o0 = Ctx + ((size_t)b * S_ + gr0) * DOUT + (size_t)h * HD;
    float* o1 = o0 + (size_t)8 * DOUT;
#pragma unroll
    for (int nt = 0; nt < 16; nt++) {
        int c = nt * 8 + 2 * tg;
        *(float2*)(o0 + c) = make_float2(oacc[nt][0] * inv0, oacc[nt][1] * inv0);
        *(float2*)(o1 + c) = make_float2(oacc[nt][2] * inv1, oacc[nt][3] * inv1);
    }
#undef LDKV
#undef STKV
}

// ====================================================================
// launch
// ====================================================================
extern "C" void kernel_launch(void* const* d_in, const int* in_sizes, int n_in,
                              void* d_out, int out_size)
{
    const float* x    = (const float*)d_in[0];
    const float* Wq   = (const float*)d_in[1];
    const float* Wdkv = (const float*)d_in[2];
    const float* Wuk  = (const float*)d_in[3];
    const float* Wuv  = (const float*)d_in[4];
    const float* Wout = (const float*)d_in[5];
    const float* bout = (const float*)d_in[6];
    float* out = (float*)d_out;

    float *q, *lat, *k, *v, *ctx;
    cudaGetSymbolAddress((void**)&q,   g_q);
    cudaGetSymbolAddress((void**)&lat, g_lat);
    cudaGetSymbolAddress((void**)&k,   g_k);
    cudaGetSymbolAddress((void**)&v,   g_v);
    cudaGetSymbolAddress((void**)&ctx, g_ctx);

    cudaFuncSetAttribute(flash_attn_reg,
                         cudaFuncAttributeMaxDynamicSharedMemorySize,
                         FA_SMEM_BYTES);

    // launch index shift: noop makes flash_attn the 6th launch (ncu -s 5)
    noop_k<<<1, 32>>>();
    tf32_gemm<<<dim3(DOUT / 128, ROWS / 128), 256>>>(x, Wq, q, nullptr, ROWS, DOUT, DIN);
    tf32_gemm<<<dim3(LAT / 128, ROWS / 128), 256>>>(x, Wdkv, lat, nullptr, ROWS, LAT, DIN);
    tf32_gemm<<<dim3(DOUT / 128, ROWS / 128), 256>>>(lat, Wuk, k, nullptr, ROWS, DOUT, LAT);
    tf32_gemm<<<dim3(DOUT / 128, ROWS / 128), 256>>>(lat, Wuv, v, nullptr, ROWS, DOUT, LAT);
    flash_attn_reg<<<dim3(S_ / FBM, B_ * NH), 256, FA_SMEM_BYTES>>>(q, k, v, ctx);
    tf32_gemm<<<dim3(DOUT / 128, ROWS / 128), 256>>>(ctx, Wout, out, bout, ROWS, DOUT, DOUT);
}

// round 9
// speedup vs baseline: 1.0892x; 1.0107x over previous
#include <cuda_runtime.h>
#include <cuda_fp16.h>
#include <math.h>
#include <stdint.h>

// ---------------- problem constants ----------------
#define B_    2
#define S_    2048
#define DIN   2048
#define DOUT  2048
#define NH    16
#define HD    128
#define LAT   256
#define ROWS  (B_ * S_)            // 4096
#define ATT_SCALE 0.08838834764831845f          // 1/sqrt(128)
#define QK_SCALE  (0.08838834764831845f * 1.4426950408889634f)  // fold log2(e): softmax in base-2

// ---------------- scratch ----------------
__device__ float g_q[ROWS * DOUT];
__device__ float g_lat[ROWS * LAT];
__device__ float g_k[ROWS * DOUT];
__device__ float g_v[ROWS * DOUT];
__device__ float g_ctx[ROWS * DOUT];

__device__ __forceinline__ uint32_t f2tf32(float x) {
    uint32_t r;
    asm("cvt.rna.tf32.f32 %0, %1;" : "=r"(r) : "f"(x));
    return r;
}

__device__ __forceinline__ void mma_tf32(float* d, const uint32_t* a, const uint32_t* b) {
    asm volatile(
        "mma.sync.aligned.m16n8k8.row.col.f32.tf32.tf32.f32 "
        "{%0,%1,%2,%3}, {%4,%5,%6,%7}, {%8,%9}, {%0,%1,%2,%3};"
        : "+f"(d[0]), "+f"(d[1]), "+f"(d[2]), "+f"(d[3])
        : "r"(a[0]), "r"(a[1]), "r"(a[2]), "r"(a[3]), "r"(b[0]), "r"(b[1]));
}

__device__ __forceinline__ void mma_f16(float* d, const uint32_t* a, const uint32_t* b) {
    asm volatile(
        "mma.sync.aligned.m16n8k16.row.col.f32.f16.f16.f32 "
        "{%0,%1,%2,%3}, {%4,%5,%6,%7}, {%8,%9}, {%0,%1,%2,%3};"
        : "+f"(d[0]), "+f"(d[1]), "+f"(d[2]), "+f"(d[3])
        : "r"(a[0]), "r"(a[1]), "r"(a[2]), "r"(a[3]), "r"(b[0]), "r"(b[1]));
}

// packed-pair slot: pair p -> u32 index so LDS.64 at (kk*8 + 2*tg) yields
// (pair tg, pair tg+4) = mma b0/b1.
__device__ __forceinline__ int ppos(int p) {
    int pp = p & 7;
    int slot = (pp < 4) ? (2 * pp) : (2 * (pp - 4) + 1);
    return ((p >> 3) << 3) + slot;
}

// single-instruction pack: {lo, hi} -> f16x2 (lo in bits [15:0])
__device__ __forceinline__ uint32_t h2pack(float lo, float hi) {
    uint32_t r;
    asm("cvt.rn.f16x2.f32 %0, %1, %2;" : "=r"(r) : "f"(hi), "f"(lo));
    return r;
}

// split (x,y) into fp16 hi-pair and fp16 lo-pair (error compensation)
__device__ __forceinline__ void splitpack(float x, float y, uint32_t& ph, uint32_t& pl) {
    ph = h2pack(x, y);
    float hx = __half2float(__ushort_as_half((unsigned short)(ph & 0xffffu)));
    float hy = __half2float(__ushort_as_half((unsigned short)(ph >> 16)));
    pl = h2pack(x - hx, y - hy);
}

// ====================================================================
// TF32 tensor-core GEMM (unchanged)
// ====================================================================
#define AS_STRIDE 36
#define BS_STRIDE 136

__global__ __launch_bounds__(256) void tf32_gemm(
    const float* __restrict__ A, const float* __restrict__ Bm,
    float* __restrict__ C, const float* __restrict__ bias,
    int M, int N, int K)
{
    __shared__ uint32_t As[128 * AS_STRIDE];
    __shared__ uint32_t Bs[32 * BS_STRIDE];

    const int t    = threadIdx.x;
    const int lane = t & 31;
    const int warp = t >> 5;
    const int bm   = blockIdx.y * 128;
    const int bn   = blockIdx.x * 128;

    const int wm = (warp >> 1) * 32;
    const int wn = (warp & 1) * 64;
    const int g  = lane >> 2;
    const int tg = lane & 3;

    const int arow = t >> 3;
    const int acol = (t & 7) * 4;
    const int brow = t >> 5;
    const int bcol = (t & 31) * 4;

    const float* Ag = A  + (size_t)(bm + arow) * K + acol;
    const float* Bg = Bm + (size_t)brow * N + bn + bcol;

    float acc[2][8][4];
#pragma unroll
    for (int mt = 0; mt < 2; mt++)
#pragma unroll
        for (int nt = 0; nt < 8; nt++)
#pragma unroll
            for (int r = 0; r < 4; r++) acc[mt][nt][r] = 0.f;

    float4 pa[4], pb[4];

#define LDAB(k0)                                                            \
    {                                                                       \
        _Pragma("unroll")                                                   \
        for (int i = 0; i < 4; i++)                                         \
            pa[i] = *(const float4*)(Ag + (size_t)(i * 32) * K + (k0));     \
        _Pragma("unroll")                                                   \
        for (int i = 0; i < 4; i++)                                         \
            pb[i] = *(const float4*)(Bg + (size_t)((k0) + i * 8) * N);      \
    }

#define STAB()                                                              \
    {                                                                       \
        _Pragma("unroll")                                                   \
        for (int i = 0; i < 4; i++) {                                       \
            uint32_t* p = &As[(arow + 32 * i) * AS_STRIDE + acol];          \
            uint4 v;                                                        \
            v.x = f2tf32(pa[i].x); v.y = f2tf32(pa[i].y);                   \
            v.z = f2tf32(pa[i].z); v.w = f2tf32(pa[i].w);                   \
            *(uint4*)p = v;                                                 \
        }                                                                   \
        _Pragma("unroll")                                                   \
        for (int i = 0; i < 4; i++) {                                       \
            uint32_t* p = &Bs[(brow + 8 * i) * BS_STRIDE + bcol];           \
            uint4 v;                                                        \
            v.x = f2tf32(pb[i].x); v.y = f2tf32(pb[i].y);                   \
            v.z = f2tf32(pb[i].z); v.w = f2tf32(pb[i].w);                   \
            *(uint4*)p = v;                                                 \
        }                                                                   \
    }

    const int nkt = K >> 5;

    LDAB(0);
    STAB();
    __syncthreads();

    for (int kt = 0; kt < nkt; kt++) {
        if (kt + 1 < nkt) LDAB((kt + 1) * 32);

#pragma unroll
        for (int k8 = 0; k8 < 32; k8 += 8) {
            uint32_t af[2][4];
            uint32_t bf[8][2];
#pragma unroll
            for (int mt = 0; mt < 2; mt++) {
                int mb = wm + mt * 16;
                af[mt][0] = As[(mb + g) * AS_STRIDE + k8 + tg];
                af[mt][1] = As[(mb + g + 8) * AS_STRIDE + k8 + tg];
                af[mt][2] = As[(mb + g) * AS_STRIDE + k8 + tg + 4];
                af[mt][3] = As[(mb + g + 8) * AS_STRIDE + k8 + tg + 4];
            }
#pragma unroll
            for (int nt = 0; nt < 8; nt++) {
                int nb = wn + nt * 8 + g;
                bf[nt][0] = Bs[(k8 + tg) * BS_STRIDE + nb];
                bf[nt][1] = Bs[(k8 + tg + 4) * BS_STRIDE + nb];
            }
#pragma unroll
            for (int mt = 0; mt < 2; mt++)
#pragma unroll
                for (int nt = 0; nt < 8; nt++)
                    mma_tf32(acc[mt][nt], af[mt], bf[nt]);
        }
        __syncthreads();
        if (kt + 1 < nkt) {
            STAB();
            __syncthreads();
        }
    }

#pragma unroll
    for (int mt = 0; mt < 2; mt++) {
        int row0 = bm + wm + mt * 16 + g;
#pragma unroll
        for (int nt = 0; nt < 8; nt++) {
            int col = bn + wn + nt * 8 + tg * 2;
            float b0 = 0.f, b1 = 0.f;
            if (bias) { b0 = bias[col]; b1 = bias[col + 1]; }
            float2 v0, v1;
            v0.x = acc[mt][nt][0] + b0;
            v0.y = acc[mt][nt][1] + b1;
            v1.x = acc[mt][nt][2] + b0;
            v1.y = acc[mt][nt][3] + b1;
            *(float2*)(C + (size_t)row0 * N + col)       = v0;
            *(float2*)(C + (size_t)(row0 + 8) * N + col) = v1;
        }
    }
#undef LDAB
#undef STAB
}

// profiler marker: writes 128 floats of ctx (fully overwritten by flash)
__global__ void mark_k(float* p) { p[threadIdx.x] = 0.f; }

// ====================================================================
// fp16 register-resident causal flash attention.
// 256 threads / 8 warps. Q tile 128 rows; warp w owns rows 16w..16w+15.
// Q in registers (fp16 hi/lo A-fragments, pre-scaled by 1/sqrt(hd)*log2e).
// QK^T fp16x3 with THREE independent accumulator chains (no back-to-back
// same-accumulator MMAs). Base-2 register softmax (exp2f), deferred
// l-reduction, conditional O rescale, STKV overlapped with PV.
// K/V tile 32, double-buffered, one __syncthreads per tile.
// ====================================================================
#define FBM 128
#define FBN 32
#define KS 72     // u32 stride: 64 pair-slots + 8 pad
#define VS 40     // u32 stride: 16 pair-slots + pad
#define FA_U32 (2*32*KS*2 + 2*128*VS)
#define FA_SMEM_BYTES (FA_U32 * 4)

__global__ __launch_bounds__(256) void flash_attn_reg(
    const float* __restrict__ Qg, const float* __restrict__ Kg,
    const float* __restrict__ Vg, float* __restrict__ Ctx)
{
    extern __shared__ uint32_t smu[];
    uint32_t* Kh = smu;                  // [2][32][KS]
    uint32_t* Kl = Kh + 2 * 32 * KS;     // [2][32][KS]
    uint32_t* Vt = Kl + 2 * 32 * KS;     // [2][128][VS] transposed packed pairs

    const int t    = threadIdx.x;
    const int lane = t & 31;
    const int warp = t >> 5;
    const int g    = lane >> 2;
    const int tg   = lane & 3;

    // longest blocks first
    const int qt = gridDim.x - 1 - blockIdx.x;
    const int qb = qt * FBM;
    const int bh = blockIdx.y;
    const int b  = bh >> 4;
    const int h  = bh & 15;

    const float* Kbase = Kg + (size_t)b * S_ * DOUT + (size_t)h * HD;
    const float* Vbase = Vg + (size_t)b * S_ * DOUT + (size_t)h * HD;

    const int gr0  = qb + warp * 16 + g;     // lane's fragment rows: gr0, gr0+8
    const int wmax = qb + warp * 16 + 15;    // warp's max row

    // ---- Q into register A-fragments (scaled to base-2 domain, split) ----
    uint32_t qh[8][4], ql[8][4];
    {
        const float* q0 = Qg + ((size_t)b * S_ + gr0) * DOUT + (size_t)h * HD;
        const float* q1 = q0 + (size_t)8 * DOUT;
#pragma unroll
        for (int kk = 0; kk < 8; kk++) {
            int c = 16 * kk + 2 * tg;
            float2 a0 = *(const float2*)(q0 + c);
            float2 a1 = *(const float2*)(q1 + c);
            float2 a2 = *(const float2*)(q0 + c + 8);
            float2 a3 = *(const float2*)(q1 + c + 8);
            splitpack(a0.x * QK_SCALE, a0.y * QK_SCALE, qh[kk][0], ql[kk][0]);
            splitpack(a1.x * QK_SCALE, a1.y * QK_SCALE, qh[kk][1], ql[kk][1]);
            splitpack(a2.x * QK_SCALE, a2.y * QK_SCALE, qh[kk][2], ql[kk][2]);
            splitpack(a3.x * QK_SCALE, a3.y * QK_SCALE, qh[kk][3], ql[kk][3]);
        }
    }

    float oacc[16][4];
#pragma unroll
    for (int nt = 0; nt < 16; nt++)
#pragma unroll
        for (int r = 0; r < 4; r++) oacc[nt][r] = 0.f;
    float m0 = -INFINITY, m1 = -INFINITY;   // base-2 running max
    float l0 = 0.f, l1 = 0.f;               // lane-partial row sums

    // loader mappings (256 threads)
    const int vrp  = t & 15;          // V row-pair 0..15
    const int vcg  = (t >> 4) * 2;    // V col-group base (0,2,..,30)
    float4 pk[4], pv[4];

#define LDKV(kb_)                                                                     \
    {                                                                                 \
        _Pragma("unroll")                                                             \
        for (int i = 0; i < 4; i++) {                                                 \
            int idx = t + 256 * i;                                                    \
            int r   = idx >> 5;                                                       \
            int c4  = (idx & 31) * 4;                                                 \
            pk[i] = *(const float4*)(Kbase + (size_t)((kb_) + r) * DOUT + c4);        \
        }                                                                             \
        pv[0] = *(const float4*)(Vbase + (size_t)((kb_) + 2 * vrp) * DOUT + vcg * 4); \
        pv[1] = *(const float4*)(Vbase + (size_t)((kb_) + 2 * vrp + 1) * DOUT + vcg * 4); \
        pv[2] = *(const float4*)(Vbase + (size_t)((kb_) + 2 * vrp) * DOUT + (vcg + 1) * 4); \
        pv[3] = *(const float4*)(Vbase + (size_t)((kb_) + 2 * vrp + 1) * DOUT + (vcg + 1) * 4); \
    }

#define STKV(buf)                                                                     \
    {                                                                                 \
        _Pragma("unroll")                                                             \
        for (int i = 0; i < 4; i++) {                                                 \
            int idx = t + 256 * i;                                                    \
            int r   = idx >> 5;                                                       \
            int c4  = (idx & 31) * 4;                                                 \
            int p0  = c4 >> 1;                                                        \
            uint32_t* kh = Kh + (buf) * 32 * KS + r * KS;                             \
            uint32_t* kl = Kl + (buf) * 32 * KS + r * KS;                             \
            int j0 = ppos(p0), j1 = ppos(p0 + 1);                                     \
            uint32_t ph, pl;                                                          \
            splitpack(pk[i].x, pk[i].y, ph, pl); kh[j0] = ph; kl[j0] = pl;            \
            splitpack(pk[i].z, pk[i].w, ph, pl); kh[j1] = ph; kl[j1] = pl;            \
        }                                                                             \
        {                                                                             \
            uint32_t* vp = Vt + (buf) * 128 * VS;                                     \
            int jv = ppos(vrp);                                                       \
            vp[(vcg * 4 + 0) * VS + jv] = h2pack(pv[0].x, pv[1].x);                   \
            vp[(vcg * 4 + 1) * VS + jv] = h2pack(pv[0].y, pv[1].y);                   \
            vp[(vcg * 4 + 2) * VS + jv] = h2pack(pv[0].z, pv[1].z);                   \
            vp[(vcg * 4 + 3) * VS + jv] = h2pack(pv[0].w, pv[1].w);                   \
            vp[((vcg + 1) * 4 + 0) * VS + jv] = h2pack(pv[2].x, pv[3].x);             \
            vp[((vcg + 1) * 4 + 1) * VS + jv] = h2pack(pv[2].y, pv[3].y);             \
            vp[((vcg + 1) * 4 + 2) * VS + jv] = h2pack(pv[2].z, pv[3].z);             \
            vp[((vcg + 1) * 4 + 3) * VS + jv] = h2pack(pv[2].w, pv[3].w);             \
        }                                                                             \
    }

    const int nkt = qb / FBN + 4;

    LDKV(0);
    STKV(0);
    __syncthreads();

    for (int kt = 0; kt < nkt; kt++) {
        const int kb  = kt * FBN;
        const int cur = kt & 1;
        const bool more = (kt + 1 < nkt);
        if (more) LDKV(kb + FBN);

        if (kb <= wmax) {
            const uint32_t* khb = Kh + cur * 32 * KS;
            const uint32_t* klb = Kl + cur * 32 * KS;

            // ---- S = Q K^T: 3 independent chains per nt ----
            float shh[4][4], sxa[4][4], sxb[4][4];
#pragma unroll
            for (int nt = 0; nt < 4; nt++)
#pragma unroll
                for (int r = 0; r < 4; r++) {
                    shh[nt][r] = 0.f; sxa[nt][r] = 0.f; sxb[nt][r] = 0.f;
                }

#pragma unroll
            for (int kk = 0; kk < 8; kk++) {
                uint32_t bhv[4][2], blv[4][2];
#pragma unroll
                for (int nt = 0; nt < 4; nt++) {
                    int row = (nt * 8 + g) * KS + kk * 8 + 2 * tg;
                    uint2 bh2 = *(const uint2*)&khb[row];
                    uint2 bl2 = *(const uint2*)&klb[row];
                    bhv[nt][0] = bh2.x; bhv[nt][1] = bh2.y;
                    blv[nt][0] = bl2.x; blv[nt][1] = bl2.y;
                }
#pragma unroll
                for (int nt = 0; nt < 4; nt++) mma_f16(shh[nt], qh[kk], bhv[nt]);
#pragma unroll
                for (int nt = 0; nt < 4; nt++) mma_f16(sxa[nt], ql[kk], bhv[nt]);
#pragma unroll
                for (int nt = 0; nt < 4; nt++) mma_f16(sxb[nt], qh[kk], blv[nt]);
            }

            // ---- combine + causal mask (base-2 logits) ----
            float s[4][4];
#pragma unroll
            for (int nt = 0; nt < 4; nt++) {
#pragma unroll
                for (int r = 0; r < 4; r++)
                    s[nt][r] = shh[nt][r] + (sxa[nt][r] + sxb[nt][r]);
                if (kb + FBN - 1 > qb + warp * 16) {
                    int cb = kb + nt * 8 + 2 * tg;
                    if (cb     > gr0)     s[nt][0] = -INFINITY;
                    if (cb + 1 > gr0)     s[nt][1] = -INFINITY;
                    if (cb     > gr0 + 8) s[nt][2] = -INFINITY;
                    if (cb + 1 > gr0 + 8) s[nt][3] = -INFINITY;
                }
            }

            // ---- online softmax (base-2; exp2f = bare MUFU) ----
            float mx0 = -INFINITY, mx1 = -INFINITY;
#pragma unroll
            for (int nt = 0; nt < 4; nt++) {
                mx0 = fmaxf(mx0, fmaxf(s[nt][0], s[nt][1]));
                mx1 = fmaxf(mx1, fmaxf(s[nt][2], s[nt][3]));
            }
            mx0 = fmaxf(mx0, __shfl_xor_sync(0xffffffffu, mx0, 1));
            mx0 = fmaxf(mx0, __shfl_xor_sync(0xffffffffu, mx0, 2));
            mx1 = fmaxf(mx1, __shfl_xor_sync(0xffffffffu, mx1, 1));
            mx1 = fmaxf(mx1, __shfl_xor_sync(0xffffffffu, mx1, 2));

            float nm0 = fmaxf(m0, mx0), nm1 = fmaxf(m1, mx1);
            float f0 = exp2f(m0 - nm0), f1 = exp2f(m1 - nm1);
            m0 = nm0; m1 = nm1;

            uint32_t pa[2][4];   // PV A-fragments (== S C-fragment relayout)
            float s0 = 0.f, s1 = 0.f;
#pragma unroll
            for (int nt = 0; nt < 4; nt++) {
                float p0 = exp2f(s[nt][0] - nm0);
                float p1 = exp2f(s[nt][1] - nm0);
                float p2 = exp2f(s[nt][2] - nm1);
                float p3 = exp2f(s[nt][3] - nm1);
                s0 += p0 + p1;
                s1 += p2 + p3;
                pa[nt >> 1][(nt & 1) * 2 + 0] = h2pack(p0, p1);
                pa[nt >> 1][(nt & 1) * 2 + 1] = h2pack(p2, p3);
            }
            l0 = l0 * f0 + s0;
            l1 = l1 * f1 + s1;

            // ---- store next K/V tile while softmax results settle ----
            if (more) STKV(cur ^ 1);

            // ---- conditional O rescale ----
            if (!__all_sync(0xffffffffu, (f0 == 1.f) && (f1 == 1.f))) {
#pragma unroll
                for (int nt = 0; nt < 16; nt++) {
                    oacc[nt][0] *= f0; oacc[nt][1] *= f0;
                    oacc[nt][2] *= f1; oacc[nt][3] *= f1;
                }
            }

            // ---- O += P V (fp16), 16 independent n-chains ----
            const uint32_t* vpb = Vt + cur * 128 * VS;
#pragma unroll
            for (int kk = 0; kk < 2; kk++) {
#pragma unroll
                for (int nt = 0; nt < 16; nt++) {
                    uint2 bv = *(const uint2*)&vpb[(nt * 8 + g) * VS + kk * 8 + 2 * tg];
                    uint32_t bb[2] = {bv.x, bv.y};
                    mma_f16(oacc[nt], pa[kk], bb);
                }
            }
        } else {
            if (more) STKV(cur ^ 1);
        }

        __syncthreads();
    }

    // ---- epilogue: reduce l partials, normalize, store ----
    l0 += __shfl_xor_sync(0xffffffffu, l0, 1);
    l0 += __shfl_xor_sync(0xffffffffu, l0, 2);
    l1 += __shfl_xor_sync(0xffffffffu, l1, 1);
    l1 += __shfl_xor_sync(0xffffffffu, l1, 2);
    float inv0 = 1.f / l0, inv1 = 1.f / l1;
    float* o0 = Ctx + ((size_t)b * S_ + gr0) * DOUT + (size_t)h * HD;
    float* o1 = o0 + (size_t)8 * DOUT;
#pragma unroll
    for (int nt = 0; nt < 16; nt++) {
        int c = nt * 8 + 2 * tg;
        *(float2*)(o0 + c) = make_float2(oacc[nt][0] * inv0, oacc[nt][1] * inv0);
        *(float2*)(o1 + c) = make_float2(oacc[nt][2] * inv1, oacc[nt][3] * inv1);
    }
#undef LDKV
#undef STKV
}

// ====================================================================
// launch
// ====================================================================
extern "C" void kernel_launch(void* const* d_in, const int* in_sizes, int n_in,
                              void* d_out, int out_size)
{
    const float* x    = (const float*)d_in[0];
    const float* Wq   = (const float*)d_in[1];
    const float* Wdkv = (const float*)d_in[2];
    const float* Wuk  = (const float*)d_in[3];
    const float* Wuv  = (const float*)d_in[4];
    const float* Wout = (const float*)d_in[5];
    const float* bout = (const float*)d_in[6];
    float* out = (float*)d_out;

    float *q, *lat, *k, *v, *ctx;
    cudaGetSymbolAddress((void**)&q,   g_q);
    cudaGetSymbolAddress((void**)&lat, g_lat);
    cudaGetSymbolAddress((void**)&k,   g_k);
    cudaGetSymbolAddress((void**)&v,   g_v);
    cudaGetSymbolAddress((void**)&ctx, g_ctx);

    cudaFuncSetAttribute(flash_attn_reg,
                         cudaFuncAttributeMaxDynamicSharedMemorySize,
                         FA_SMEM_BYTES);

    tf32_gemm<<<dim3(DOUT / 128, ROWS / 128), 256>>>(x, Wq, q, nullptr, ROWS, DOUT, DIN);
    tf32_gemm<<<dim3(LAT / 128, ROWS / 128), 256>>>(x, Wdkv, lat, nullptr, ROWS, LAT, DIN);
    tf32_gemm<<<dim3(DOUT / 128, ROWS / 128), 256>>>(lat, Wuk, k, nullptr, ROWS, DOUT, LAT);
    tf32_gemm<<<dim3(DOUT / 128, ROWS / 128), 256>>>(lat, Wuv, v, nullptr, ROWS, DOUT, LAT);
    // marker: makes flash_attn the 6th launch for ncu (-s 5); ctx[0..255]
    // is fully overwritten by flash_attn below.
    mark_k<<<1, 256>>>(ctx);
    flash_attn_reg<<<dim3(S_ / FBM, B_ * NH), 256, FA_SMEM_BYTES>>>(q, k, v, ctx);
    tf32_gemm<<<dim3(DOUT / 128, ROWS / 128), 256>>>(ctx, Wout, out, bout, ROWS, DOUT, DOUT);
}

// round 10
// speedup vs baseline: 1.1542x; 1.0597x over previous
#include <cuda_runtime.h>
#include <cuda_fp16.h>
#include <math.h>
#include <stdint.h>

// ---------------- problem constants ----------------
#define B_    2
#define S_    2048
#define DIN   2048
#define DOUT  2048
#define NH    16
#define HD    128
#define LAT   256
#define ROWS  (B_ * S_)            // 4096
#define QK_SCALE  (0.08838834764831845f * 1.4426950408889634f)  // 1/sqrt(hd) * log2(e)

// ---------------- scratch ----------------
__device__ float    g_lat[ROWS * LAT];
__device__ float    g_ctx[ROWS * DOUT];
// attention-ready fp16 pair buffers, per (b,h) head:
__device__ uint32_t g_qh16[32 * 2048 * 64];   // Q hi pairs, natural pair order
__device__ uint32_t g_ql16[32 * 2048 * 64];   // Q lo pairs
__device__ uint32_t g_kh16[32 * 2048 * 64];   // K hi pairs, ppos order per row
__device__ uint32_t g_kl16[32 * 2048 * 64];   // K lo pairs
__device__ uint32_t g_vt16[32 * 128 * 1024];  // V transposed row-pair packs, ppos order

__device__ __forceinline__ uint32_t f2tf32(float x) {
    uint32_t r;
    asm("cvt.rna.tf32.f32 %0, %1;" : "=r"(r) : "f"(x));
    return r;
}

__device__ __forceinline__ void mma_tf32(float* d, const uint32_t* a, const uint32_t* b) {
    asm volatile(
        "mma.sync.aligned.m16n8k8.row.col.f32.tf32.tf32.f32 "
        "{%0,%1,%2,%3}, {%4,%5,%6,%7}, {%8,%9}, {%0,%1,%2,%3};"
        : "+f"(d[0]), "+f"(d[1]), "+f"(d[2]), "+f"(d[3])
        : "r"(a[0]), "r"(a[1]), "r"(a[2]), "r"(a[3]), "r"(b[0]), "r"(b[1]));
}

__device__ __forceinline__ void mma_f16(float* d, const uint32_t* a, const uint32_t* b) {
    asm volatile(
        "mma.sync.aligned.m16n8k16.row.col.f32.f16.f16.f32 "
        "{%0,%1,%2,%3}, {%4,%5,%6,%7}, {%8,%9}, {%0,%1,%2,%3};"
        : "+f"(d[0]), "+f"(d[1]), "+f"(d[2]), "+f"(d[3])
        : "r"(a[0]), "r"(a[1]), "r"(a[2]), "r"(a[3]), "r"(b[0]), "r"(b[1]));
}

// packed-pair slot: pair p -> u32 index so LDS.64 at (kk*8 + 2*tg) yields
// (pair tg, pair tg+4) = mma b0/b1.
__device__ __host__ __forceinline__ int ppos(int p) {
    int pp = p & 7;
    int slot = (pp < 4) ? (2 * pp) : (2 * (pp - 4) + 1);
    return ((p >> 3) << 3) + slot;
}

// single-instruction pack: {lo, hi} -> f16x2 (lo in bits [15:0])
__device__ __forceinline__ uint32_t h2pack(float lo, float hi) {
    uint32_t r;
    asm("cvt.rn.f16x2.f32 %0, %1, %2;" : "=r"(r) : "f"(hi), "f"(lo));
    return r;
}

// split (x,y) into fp16 hi-pair and fp16 lo-pair (error compensation)
__device__ __forceinline__ void splitpack(float x, float y, uint32_t& ph, uint32_t& pl) {
    ph = h2pack(x, y);
    float hx = __half2float(__ushort_as_half((unsigned short)(ph & 0xffffu)));
    float hy = __half2float(__ushort_as_half((unsigned short)(ph >> 16)));
    pl = h2pack(x - hx, y - hy);
}

// ====================================================================
// TF32 tensor-core GEMM with format-emitting epilogues.
// mode 0: fp32 C (+bias)
// mode 1: Q  -> oh/ol fp16 hi/lo pairs, scaled by QK_SCALE, natural order
// mode 2: K  -> oh/ol fp16 hi/lo pairs, ppos order per seq row
// mode 3: V  -> oh transposed row-pair packs, ppos order
// ====================================================================
#define AS_STRIDE 36
#define BS_STRIDE 136

__global__ __launch_bounds__(256) void tf32_gemm(
    const float* __restrict__ A, const float* __restrict__ Bm,
    float* __restrict__ C, const float* __restrict__ bias,
    int M, int N, int K, int mode, uint32_t* __restrict__ oh,
    uint32_t* __restrict__ ol)
{
    __shared__ uint32_t As[128 * AS_STRIDE];
    __shared__ uint32_t Bs[32 * BS_STRIDE];

    const int t    = threadIdx.x;
    const int lane = t & 31;
    const int warp = t >> 5;
    const int bm   = blockIdx.y * 128;
    const int bn   = blockIdx.x * 128;

    const int wm = (warp >> 1) * 32;
    const int wn = (warp & 1) * 64;
    const int g  = lane >> 2;
    const int tg = lane & 3;

    const int arow = t >> 3;
    const int acol = (t & 7) * 4;
    const int brow = t >> 5;
    const int bcol = (t & 31) * 4;

    const float* Ag = A  + (size_t)(bm + arow) * K + acol;
    const float* Bg = Bm + (size_t)brow * N + bn + bcol;

    float acc[2][8][4];
#pragma unroll
    for (int mt = 0; mt < 2; mt++)
#pragma unroll
        for (int nt = 0; nt < 8; nt++)
#pragma unroll
            for (int r = 0; r < 4; r++) acc[mt][nt][r] = 0.f;

    float4 pa[4], pb[4];

#define LDAB(k0)                                                            \
    {                                                                       \
        _Pragma("unroll")                                                   \
        for (int i = 0; i < 4; i++)                                         \
            pa[i] = *(const float4*)(Ag + (size_t)(i * 32) * K + (k0));     \
        _Pragma("unroll")                                                   \
        for (int i = 0; i < 4; i++)                                         \
            pb[i] = *(const float4*)(Bg + (size_t)((k0) + i * 8) * N);      \
    }

#define STAB()                                                              \
    {                                                                       \
        _Pragma("unroll")                                                   \
        for (int i = 0; i < 4; i++) {                                       \
            uint32_t* p = &As[(arow + 32 * i) * AS_STRIDE + acol];          \
            uint4 v;                                                        \
            v.x = f2tf32(pa[i].x); v.y = f2tf32(pa[i].y);                   \
            v.z = f2tf32(pa[i].z); v.w = f2tf32(pa[i].w);                   \
            *(uint4*)p = v;                                                 \
        }                                                                   \
        _Pragma("unroll")                                                   \
        for (int i = 0; i < 4; i++) {                                       \
            uint32_t* p = &Bs[(brow + 8 * i) * BS_STRIDE + bcol];           \
            uint4 v;                                                        \
            v.x = f2tf32(pb[i].x); v.y = f2tf32(pb[i].y);                   \
            v.z = f2tf32(pb[i].z); v.w = f2tf32(pb[i].w);                   \
            *(uint4*)p = v;                                                 \
        }                                                                   \
    }

    const int nkt = K >> 5;

    LDAB(0);
    STAB();
    __syncthreads();

    for (int kt = 0; kt < nkt; kt++) {
        if (kt + 1 < nkt) LDAB((kt + 1) * 32);

#pragma unroll
        for (int k8 = 0; k8 < 32; k8 += 8) {
            uint32_t af[2][4];
            uint32_t bf[8][2];
#pragma unroll
            for (int mt = 0; mt < 2; mt++) {
                int mb = wm + mt * 16;
                af[mt][0] = As[(mb + g) * AS_STRIDE + k8 + tg];
                af[mt][1] = As[(mb + g + 8) * AS_STRIDE + k8 + tg];
                af[mt][2] = As[(mb + g) * AS_STRIDE + k8 + tg + 4];
                af[mt][3] = As[(mb + g + 8) * AS_STRIDE + k8 + tg + 4];
            }
#pragma unroll
            for (int nt = 0; nt < 8; nt++) {
                int nb = wn + nt * 8 + g;
                bf[nt][0] = Bs[(k8 + tg) * BS_STRIDE + nb];
                bf[nt][1] = Bs[(k8 + tg + 4) * BS_STRIDE + nb];
            }
#pragma unroll
            for (int mt = 0; mt < 2; mt++)
#pragma unroll
                for (int nt = 0; nt < 8; nt++)
                    mma_tf32(acc[mt][nt], af[mt], bf[nt]);
        }
        __syncthreads();
        if (kt + 1 < nkt) {
            STAB();
            __syncthreads();
        }
    }

    // ---------------- epilogues ----------------
    if (mode == 0) {
#pragma unroll
        for (int mt = 0; mt < 2; mt++) {
            int row0 = bm + wm + mt * 16 + g;
#pragma unroll
            for (int nt = 0; nt < 8; nt++) {
                int col = bn + wn + nt * 8 + tg * 2;
                float b0 = 0.f, b1 = 0.f;
                if (bias) { b0 = bias[col]; b1 = bias[col + 1]; }
                float2 v0, v1;
                v0.x = acc[mt][nt][0] + b0;
                v0.y = acc[mt][nt][1] + b1;
                v1.x = acc[mt][nt][2] + b0;
                v1.y = acc[mt][nt][3] + b1;
                *(float2*)(C + (size_t)row0 * N + col)       = v0;
                *(float2*)(C + (size_t)(row0 + 8) * N + col) = v1;
            }
        }
    } else if (mode <= 2) {
        const float sc = (mode == 1) ? QK_SCALE : 1.f;
#pragma unroll
        for (int mt = 0; mt < 2; mt++) {
            int row0 = bm + wm + mt * 16 + g;
            int bb = row0 >> 11, seq = row0 & 2047;
#pragma unroll
            for (int nt = 0; nt < 8; nt++) {
                int col  = bn + wn + nt * 8 + tg * 2;
                int hh   = col >> 7;
                int p    = (col & 127) >> 1;
                int slot = (mode == 2) ? ppos(p) : p;
                size_t base = ((size_t)(bb * NH + hh) * 2048 + seq) * 64 + slot;
                uint32_t ph, pl;
                splitpack(acc[mt][nt][0] * sc, acc[mt][nt][1] * sc, ph, pl);
                oh[base] = ph; ol[base] = pl;
                splitpack(acc[mt][nt][2] * sc, acc[mt][nt][3] * sc, ph, pl);
                oh[base + 8 * 64] = ph; ol[base + 8 * 64] = pl;
            }
        }
    } else {  // mode 3: V transposed row-pair packs
#pragma unroll
        for (int mt = 0; mt < 2; mt++) {
            int row0 = bm + wm + mt * 16 + g;
            int bb = row0 >> 11, seq0 = row0 & 2047;
            int ppA = seq0 >> 1;
            int ppB = (seq0 + 8) >> 1;
            int slotA = (ppA >> 4) * 16 + ppos(ppA & 15);
            int slotB = (ppB >> 4) * 16 + ppos(ppB & 15);
#pragma unroll
            for (int nt = 0; nt < 8; nt++) {
                float o0 = acc[mt][nt][0], o1 = acc[mt][nt][1];
                float o2 = acc[mt][nt][2], o3 = acc[mt][nt][3];
                float q0 = __shfl_xor_sync(0xffffffffu, o0, 4);
                float q1 = __shfl_xor_sync(0xffffffffu, o1, 4);
                float q2 = __shfl_xor_sync(0xffffffffu, o2, 4);
                float q3 = __shfl_xor_sync(0xffffffffu, o3, 4);
                if (!(g & 1)) {
                    int col  = bn + wn + nt * 8 + tg * 2;
                    int hh   = col >> 7;
                    int wcol = col & 127;
                    uint32_t* vb = oh + ((size_t)(bb * NH + hh) * 128 + wcol) * 1024;
                    vb[slotA]        = h2pack(o0, q0);
                    vb[1024 + slotA] = h2pack(o1, q1);
                    vb[slotB]        = h2pack(o2, q2);
                    vb[1024 + slotB] = h2pack(o3, q3);
                }
            }
        }
    }
#undef LDAB
#undef STAB
}

// profiler marker
__global__ void mark_k(float* p) { p[threadIdx.x] = 0.f; }

// ====================================================================
// fp16 register-resident causal flash attention, cp.async edition.
// 256 threads / 8 warps; Q tile 128 rows; warp w owns rows 16w..16w+15.
// All operands arrive PRE-CONVERTED fp16 from GEMM epilogues; K/V tiles
// stream global->smem via cp.async (no registers, no cvt, no STS).
// QK^T fp16x3 (3 independent chains); base-2 register softmax; PV fp16.
// ====================================================================
#define FBM 128
#define FBN 32
#define KS 72     // u32 stride: 64 payload + 8 pad
#define VS 20     // u32 stride: 16 payload + 4 pad
#define FA_U32 (4*32*KS + 2*128*VS)
#define FA_SMEM_BYTES (FA_U32 * 4)

#define CPA16(saddr, gptr) \
    asm volatile("cp.async.cg.shared.global [%0], [%1], 16;" :: "r"(saddr), "l"(gptr))

__global__ __launch_bounds__(256) void flash_attn_cp(
    const uint32_t* __restrict__ Qh_g, const uint32_t* __restrict__ Ql_g,
    const uint32_t* __restrict__ Kh_g, const uint32_t* __restrict__ Kl_g,
    const uint32_t* __restrict__ Vt_g, float* __restrict__ Ctx)
{
    extern __shared__ uint32_t smu[];
    uint32_t* Khs = smu;                    // [2][32][KS]
    uint32_t* Kls = smu + 2 * 32 * KS;      // [2][32][KS]
    uint32_t* Vts = smu + 4 * 32 * KS;      // [2][128][VS]
    const uint32_t sbase = (uint32_t)__cvta_generic_to_shared(smu);
    const uint32_t sKh = sbase;
    const uint32_t sKl = sbase + 2 * 32 * KS * 4;
    const uint32_t sVt = sbase + 4 * 32 * KS * 4;

    const int t    = threadIdx.x;
    const int lane = t & 31;
    const int warp = t >> 5;
    const int g    = lane >> 2;
    const int tg   = lane & 3;

    // longest blocks first
    const int qt = gridDim.x - 1 - blockIdx.x;
    const int qb = qt * FBM;
    const int bh = blockIdx.y;
    const int b  = bh >> 4;
    const int h  = bh & 15;

    const uint32_t* Khg = Kh_g + (size_t)bh * 2048 * 64;
    const uint32_t* Klg = Kl_g + (size_t)bh * 2048 * 64;
    const uint32_t* Vgg = Vt_g + (size_t)bh * 128 * 1024;

    const int gr0  = qb + warp * 16 + g;     // lane's fragment rows: gr0, gr0+8
    const int wmax = qb + warp * 16 + 15;

    // ---- Q fragments: direct LDG of pre-converted pairs ----
    uint32_t qh[8][4], ql[8][4];
    {
        const uint32_t* qhg = Qh_g + ((size_t)bh * 2048 + gr0) * 64;
        const uint32_t* qlg = Ql_g + ((size_t)bh * 2048 + gr0) * 64;
#pragma unroll
        for (int kk = 0; kk < 8; kk++) {
            qh[kk][0] = qhg[8 * kk + tg];
            qh[kk][1] = qhg[8 * 64 + 8 * kk + tg];
            qh[kk][2] = qhg[8 * kk + tg + 4];
            qh[kk][3] = qhg[8 * 64 + 8 * kk + tg + 4];
            ql[kk][0] = qlg[8 * kk + tg];
            ql[kk][1] = qlg[8 * 64 + 8 * kk + tg];
            ql[kk][2] = qlg[8 * kk + tg + 4];
            ql[kk][3] = qlg[8 * 64 + 8 * kk + tg + 4];
        }
    }

    float oacc[16][4];
#pragma unroll
    for (int nt = 0; nt < 16; nt++)
#pragma unroll
        for (int r = 0; r < 4; r++) oacc[nt][r] = 0.f;
    float m0 = -INFINITY, m1 = -INFINITY;
    float l0 = 0.f, l1 = 0.f;

    // cp.async chunk assignments (6 x 16B per thread per tile)
    const int kr = t >> 4, kc = t & 15;      // K: rows kr, kr+16; chunk kc
    const int vl = t >> 2, vc = t & 3;       // V: cols vl, vl+64; chunk vc

#define ISSUE_KV(kb_, buf)                                                        \
    {                                                                             \
        const uint32_t* s1 = Khg + (size_t)((kb_) + kr) * 64 + kc * 4;            \
        const uint32_t* s2 = s1 + 16 * 64;                                        \
        uint32_t d1 = sKh + (buf) * (32 * KS * 4) + kr * (KS * 4) + kc * 16;      \
        CPA16(d1, s1);                                                            \
        CPA16(d1 + 16 * (KS * 4), s2);                                            \
        const uint32_t* s3 = Klg + (size_t)((kb_) + kr) * 64 + kc * 4;            \
        const uint32_t* s4 = s3 + 16 * 64;                                        \
        uint32_t d3 = sKl + (buf) * (32 * KS * 4) + kr * (KS * 4) + kc * 16;      \
        CPA16(d3, s3);                                                            \
        CPA16(d3 + 16 * (KS * 4), s4);                                            \
        const uint32_t* s5 = Vgg + (size_t)vl * 1024 + ((kb_) >> 1) + vc * 4;     \
        const uint32_t* s6 = s5 + (size_t)64 * 1024;                              \
        uint32_t d5 = sVt + (buf) * (128 * VS * 4) + vl * (VS * 4) + vc * 16;     \
        CPA16(d5, s5);                                                            \
        CPA16(d5 + 64 * (VS * 4), s6);                                            \
        asm volatile("cp.async.commit_group;");                                   \
    }

    const int nkt = qb / FBN + 4;

    ISSUE_KV(0, 0);
    asm volatile("cp.async.wait_group 0;");
    __syncthreads();

    for (int kt = 0; kt < nkt; kt++) {
        const int kb  = kt * FBN;
        const int cur = kt & 1;
        const bool more = (kt + 1 < nkt);
        if (more) ISSUE_KV(kb + FBN, cur ^ 1);

        if (kb <= wmax) {
            const uint32_t* khb = Khs + cur * 32 * KS;
            const uint32_t* klb = Kls + cur * 32 * KS;

            // ---- S = Q K^T: 3 independent chains ----
            float shh[4][4], sxa[4][4], sxb[4][4];
#pragma unroll
            for (int nt = 0; nt < 4; nt++)
#pragma unroll
                for (int r = 0; r < 4; r++) {
                    shh[nt][r] = 0.f; sxa[nt][r] = 0.f; sxb[nt][r] = 0.f;
                }

#pragma unroll
            for (int kk = 0; kk < 8; kk++) {
                uint32_t bhv[4][2], blv[4][2];
#pragma unroll
                for (int nt = 0; nt < 4; nt++) {
                    int row = (nt * 8 + g) * KS + kk * 8 + 2 * tg;
                    uint2 bh2 = *(const uint2*)&khb[row];
                    uint2 bl2 = *(const uint2*)&klb[row];
                    bhv[nt][0] = bh2.x; bhv[nt][1] = bh2.y;
                    blv[nt][0] = bl2.x; blv[nt][1] = bl2.y;
                }
#pragma unroll
                for (int nt = 0; nt < 4; nt++) mma_f16(shh[nt], qh[kk], bhv[nt]);
#pragma unroll
                for (int nt = 0; nt < 4; nt++) mma_f16(sxa[nt], ql[kk], bhv[nt]);
#pragma unroll
                for (int nt = 0; nt < 4; nt++) mma_f16(sxb[nt], qh[kk], blv[nt]);
            }

            // ---- combine + causal mask ----
            float s[4][4];
#pragma unroll
            for (int nt = 0; nt < 4; nt++) {
#pragma unroll
                for (int r = 0; r < 4; r++)
                    s[nt][r] = shh[nt][r] + (sxa[nt][r] + sxb[nt][r]);
                if (kb + FBN - 1 > qb + warp * 16) {
                    int cb = kb + nt * 8 + 2 * tg;
                    if (cb     > gr0)     s[nt][0] = -INFINITY;
                    if (cb + 1 > gr0)     s[nt][1] = -INFINITY;
                    if (cb     > gr0 + 8) s[nt][2] = -INFINITY;
                    if (cb + 1 > gr0 + 8) s[nt][3] = -INFINITY;
                }
            }

            // ---- online softmax (base-2) ----
            float mx0 = -INFINITY, mx1 = -INFINITY;
#pragma unroll
            for (int nt = 0; nt < 4; nt++) {
                mx0 = fmaxf(mx0, fmaxf(s[nt][0], s[nt][1]));
                mx1 = fmaxf(mx1, fmaxf(s[nt][2], s[nt][3]));
            }
            mx0 = fmaxf(mx0, __shfl_xor_sync(0xffffffffu, mx0, 1));
            mx0 = fmaxf(mx0, __shfl_xor_sync(0xffffffffu, mx0, 2));
            mx1 = fmaxf(mx1, __shfl_xor_sync(0xffffffffu, mx1, 1));
            mx1 = fmaxf(mx1, __shfl_xor_sync(0xffffffffu, mx1, 2));

            float nm0 = fmaxf(m0, mx0), nm1 = fmaxf(m1, mx1);
            float f0 = exp2f(m0 - nm0), f1 = exp2f(m1 - nm1);
            m0 = nm0; m1 = nm1;

            uint32_t pa[2][4];
            float s0 = 0.f, s1 = 0.f;
#pragma unroll
            for (int nt = 0; nt < 4; nt++) {
                float p0 = exp2f(s[nt][0] - nm0);
                float p1 = exp2f(s[nt][1] - nm0);
                float p2 = exp2f(s[nt][2] - nm1);
                float p3 = exp2f(s[nt][3] - nm1);
                s0 += p0 + p1;
                s1 += p2 + p3;
                pa[nt >> 1][(nt & 1) * 2 + 0] = h2pack(p0, p1);
                pa[nt >> 1][(nt & 1) * 2 + 1] = h2pack(p2, p3);
            }
            l0 = l0 * f0 + s0;
            l1 = l1 * f1 + s1;

            // ---- conditional O rescale ----
            if (!__all_sync(0xffffffffu, (f0 == 1.f) && (f1 == 1.f))) {
#pragma unroll
                for (int nt = 0; nt < 16; nt++) {
                    oacc[nt][0] *= f0; oacc[nt][1] *= f0;
                    oacc[nt][2] *= f1; oacc[nt][3] *= f1;
                }
            }

            // ---- O += P V (fp16), 16 independent n-chains ----
            const uint32_t* vpb = Vts + cur * 128 * VS;
#pragma unroll
            for (int kk = 0; kk < 2; kk++) {
#pragma unroll
                for (int nt = 0; nt < 16; nt++) {
                    uint2 bv = *(const uint2*)&vpb[(nt * 8 + g) * VS + kk * 8 + 2 * tg];
                    uint32_t bb[2] = {bv.x, bv.y};
                    mma_f16(oacc[nt], pa[kk], bb);
                }
            }
        }

        if (more) asm volatile("cp.async.wait_group 0;");
        __syncthreads();
    }

    // ---- epilogue: reduce l partials, normalize, store ----
    l0 += __shfl_xor_sync(0xffffffffu, l0, 1);
    l0 += __shfl_xor_sync(0xffffffffu, l0, 2);
    l1 += __shfl_xor_sync(0xffffffffu, l1, 1);
    l1 += __shfl_xor_sync(0xffffffffu, l1, 2);
    float inv0 = 1.f / l0, inv1 = 1.f / l1;
    float* o0 = Ctx + ((size_t)b * S_ + gr0) * DOUT + (size_t)h * HD;
    float* o1 = o0 + (size_t)8 * DOUT;
#pragma unroll
    for (int nt = 0; nt < 16; nt++) {
        int c = nt * 8 + 2 * tg;
        *(float2*)(o0 + c) = make_float2(oacc[nt][0] * inv0, oacc[nt][1] * inv0);
        *(float2*)(o1 + c) = make_float2(oacc[nt][2] * inv1, oacc[nt][3] * inv1);
    }
#undef ISSUE_KV
}

// ====================================================================
// launch
// ====================================================================
extern "C" void kernel_launch(void* const* d_in, const int* in_sizes, int n_in,
                              void* d_out, int out_size)
{
    const float* x    = (const float*)d_in[0];
    const float* Wq   = (const float*)d_in[1];
    const float* Wdkv = (const float*)d_in[2];
    const float* Wuk  = (const float*)d_in[3];
    const float* Wuv  = (const float*)d_in[4];
    const float* Wout = (const float*)d_in[5];
    const float* bout = (const float*)d_in[6];
    float* out = (float*)d_out;

    float *lat, *ctx;
    uint32_t *qh, *ql, *kh, *kl, *vt;
    cudaGetSymbolAddress((void**)&lat, g_lat);
    cudaGetSymbolAddress((void**)&ctx, g_ctx);
    cudaGetSymbolAddress((void**)&qh,  g_qh16);
    cudaGetSymbolAddress((void**)&ql,  g_ql16);
    cudaGetSymbolAddress((void**)&kh,  g_kh16);
    cudaGetSymbolAddress((void**)&kl,  g_kl16);
    cudaGetSymbolAddress((void**)&vt,  g_vt16);

    cudaFuncSetAttribute(flash_attn_cp,
                         cudaFuncAttributeMaxDynamicSharedMemorySize,
                         FA_SMEM_BYTES);

    // q (mode 1) -> fp16 hi/lo, scaled
    tf32_gemm<<<dim3(DOUT / 128, ROWS / 128), 256>>>(
        x, Wq, nullptr, nullptr, ROWS, DOUT, DIN, 1, qh, ql);
    // latent (mode 0)
    tf32_gemm<<<dim3(LAT / 128, ROWS / 128), 256>>>(
        x, Wdkv, lat, nullptr, ROWS, LAT, DIN, 0, nullptr, nullptr);
    // k (mode 2) -> fp16 hi/lo, ppos order
    tf32_gemm<<<dim3(DOUT / 128, ROWS / 128), 256>>>(
        lat, Wuk, nullptr, nullptr, ROWS, DOUT, LAT, 2, kh, kl);
    // v (mode 3) -> fp16 transposed row-pair packs
    tf32_gemm<<<dim3(DOUT / 128, ROWS / 128), 256>>>(
        lat, Wuv, nullptr, nullptr, ROWS, DOUT, LAT, 3, vt, nullptr);
    // profiling marker (ctx fully overwritten below)
    mark_k<<<1, 256>>>(ctx);
    // attention
    flash_attn_cp<<<dim3(S_ / FBM, B_ * NH), 256, FA_SMEM_BYTES>>>(
        qh, ql, kh, kl, vt, ctx);
    // out (mode 0, bias)
    tf32_gemm<<<dim3(DOUT / 128, ROWS / 128), 256>>>(
        ctx, Wout, out, bout, ROWS, DOUT, DOUT, 0, nullptr, nullptr);
}

// round 12
// speedup vs baseline: 1.5014x; 1.3007x over previous
#include <cuda_runtime.h>
#include <cuda_fp16.h>
#include <math.h>
#include <stdint.h>

// ---------------- problem constants ----------------
#define B_    2
#define S_    2048
#define DIN   2048
#define DOUT  2048
#define NH    16
#define HD    128
#define LAT   256
#define ROWS  (B_ * S_)            // 4096
#define QK_SCALE  (0.08838834764831845f * 1.4426950408889634f)  // 1/sqrt(hd) * log2(e)

// ---------------- scratch ----------------
__device__ uint32_t g_xp[ROWS * 1024];        // x as fp16 pairs, slot order
__device__ uint32_t g_latp[ROWS * 128];       // latent pairs, slot order
__device__ uint32_t g_ctxp[ROWS * 1024];      // ctx pairs, slot order
__device__ uint32_t g_qh16[32 * 2048 * 64];   // Q hi pairs (natural order, scaled)
__device__ uint32_t g_ql16[32 * 2048 * 64];   // Q lo pairs
__device__ uint32_t g_kh16[32 * 2048 * 64];   // K hi pairs (slot order per row)
__device__ uint32_t g_kl16[32 * 2048 * 64];   // K lo pairs
__device__ uint32_t g_vt16[32 * 128 * 1024];  // V transposed row-pair packs
// weights as fp16 pairs, blocked [kt][ntile][n 128][slot 16]
__device__ uint32_t g_wqp[64 * 16 * 128 * 16];
__device__ uint32_t g_wdkvp[64 * 2 * 128 * 16];
__device__ uint32_t g_wukp[8 * 16 * 128 * 16];
__device__ uint32_t g_wuvp[8 * 16 * 128 * 16];
__device__ uint32_t g_woutp[64 * 16 * 128 * 16];

__device__ __forceinline__ void mma_f16(float* d, const uint32_t* a, const uint32_t* b) {
    asm volatile(
        "mma.sync.aligned.m16n8k16.row.col.f32.f16.f16.f32 "
        "{%0,%1,%2,%3}, {%4,%5,%6,%7}, {%8,%9}, {%0,%1,%2,%3};"
        : "+f"(d[0]), "+f"(d[1]), "+f"(d[2]), "+f"(d[3])
        : "r"(a[0]), "r"(a[1]), "r"(a[2]), "r"(a[3]), "r"(b[0]), "r"(b[1]));
}

// packed-pair slot: pair p -> u32 index so LDS.64 at (kk*8 + 2*tg) yields
// (pair tg, pair tg+4) = mma b0/b1 (or a0/a2).
__device__ __host__ __forceinline__ int ppos(int p) {
    int pp = p & 7;
    int slot = (pp < 4) ? (2 * pp) : (2 * (pp - 4) + 1);
    return ((p >> 3) << 3) + slot;
}

// single-instruction pack: {lo, hi} -> f16x2 (lo in bits [15:0])
__device__ __forceinline__ uint32_t h2pack(float lo, float hi) {
    uint32_t r;
    asm("cvt.rn.f16x2.f32 %0, %1, %2;" : "=r"(r) : "f"(hi), "f"(lo));
    return r;
}

// split (x,y) into fp16 hi-pair and fp16 lo-pair (error compensation)
__device__ __forceinline__ void splitpack(float x, float y, uint32_t& ph, uint32_t& pl) {
    ph = h2pack(x, y);
    float hx = __half2float(__ushort_as_half((unsigned short)(ph & 0xffffu)));
    float hy = __half2float(__ushort_as_half((unsigned short)(ph >> 16)));
    pl = h2pack(x - hx, y - hy);
}

#define CPA16(saddr, gptr) \
    asm volatile("cp.async.cg.shared.global [%0], [%1], 16;" :: "r"(saddr), "l"(gptr))

// ====================================================================
// one-time converters
// ====================================================================
// x [rows][2048] fp32 -> xp [rows][1024] fp16 pairs in slot order
__global__ void convert_x(const float* __restrict__ x, uint32_t* __restrict__ xp) {
    int row = blockIdx.x, t = threadIdx.x;
    const float* src = x + (size_t)row * 2048;
    uint32_t* dst = xp + (size_t)row * 1024;
#pragma unroll
    for (int j = 0; j < 2; j++) {
        int c = (t + 256 * j) * 4;
        float4 v = *(const float4*)(src + c);
        int p = c >> 1;
        dst[ppos(p)]     = h2pack(v.x, v.y);
        dst[ppos(p + 1)] = h2pack(v.z, v.w);
    }
}

// W [K][N] fp32 -> Bp [kt][ntile][n 128][slot 16] fp16 k-pairs
// stage stride 132 floats: rows stay 16B-aligned for float4 (129 was the
// R11 misaligned-address crash).
#define WST 132
__global__ void convert_w(const float* __restrict__ W, uint32_t* __restrict__ Bp, int N) {
    __shared__ __align__(16) float stage[32 * WST];
    int kt = blockIdx.y, ntile = blockIdx.x, t = threadIdx.x;
    int NT = N >> 7;
    int r = t >> 5, c = (t & 31) * 4;
    const float* src = W + (size_t)(kt * 32) * N + ntile * 128;
#pragma unroll
    for (int i = 0; i < 4; i++)
        *(float4*)&stage[(r + 8 * i) * WST + c] =
            *(const float4*)(src + (size_t)(r + 8 * i) * N + c);
    __syncthreads();
    uint32_t* dst = Bp + ((size_t)(kt * NT + ntile) * 128) * 16;
#pragma unroll
    for (int j = 0; j < 8; j++) {
        int id = t + 256 * j;
        int n = id >> 4, s = id & 15;
        int grp = s >> 3, sw = s & 7;
        int pp = (sw & 1) ? ((sw >> 1) + 4) : (sw >> 1);
        int p = grp * 8 + pp;
        dst[n * 16 + s] = h2pack(stage[(2 * p) * WST + n], stage[(2 * p + 1) * WST + n]);
    }
}

// ====================================================================
// fp16 tensor-core GEMM: C[M,N] = A@B, fp32 accumulate.
// A: fp16 pairs [m][K/2 slots]; B: fp16 pairs blocked [kt][nt][128][16].
// 128x128 tile, BK=32, 256 thr, cp.async double buffer.
// modes: 0 fp32+bias | 1 Q hi/lo scaled (natural) | 2 K hi/lo (slot)
//        3 V transposed packs | 4 A-format pairs (slot)
// ====================================================================
#define GS 24   // smem u32 stride per row (16 payload + 8 pad)

__global__ __launch_bounds__(256) void f16_gemm(
    const uint32_t* __restrict__ Ap, int assw,
    const uint32_t* __restrict__ Bp,
    float* __restrict__ C, const float* __restrict__ bias,
    int M, int N, int K, int mode,
    uint32_t* __restrict__ oh, uint32_t* __restrict__ ol)
{
    extern __shared__ uint32_t gsm[];
    uint32_t* As = gsm;                 // [2][128*GS]
    uint32_t* Bs = gsm + 2 * 128 * GS;  // [2][128*GS]
    const uint32_t sA = (uint32_t)__cvta_generic_to_shared(As);
    const uint32_t sB = (uint32_t)__cvta_generic_to_shared(Bs);

    const int t    = threadIdx.x;
    const int lane = t & 31;
    const int warp = t >> 5;
    const int bm   = blockIdx.y * 128;
    const int NT   = N >> 7;
    const int wm   = (warp >> 1) * 32;
    const int wn   = (warp & 1) * 64;
    const int g    = lane >> 2;
    const int tg   = lane & 3;

    // loader: thread owns one row-chunk pair (32B) per operand
    const int lrow = t >> 1;
    const int lseg = (t & 1) * 2;

#define GISSUE(kt_, buf_)                                                          \
    {                                                                              \
        const uint32_t* as_ = Ap + (size_t)(bm + lrow) * assw + (kt_) * 16 + lseg * 4; \
        uint32_t ad_ = sA + ((buf_) * 128 * GS + lrow * GS + lseg * 4) * 4;        \
        CPA16(ad_, as_); CPA16(ad_ + 16, as_ + 4);                                 \
        const uint32_t* bs_ = Bp + ((size_t)((kt_) * NT + blockIdx.x) * 128 + lrow) * 16 + lseg * 4; \
        uint32_t bd_ = sB + ((buf_) * 128 * GS + lrow * GS + lseg * 4) * 4;        \
        CPA16(bd_, bs_); CPA16(bd_ + 16, bs_ + 4);                                 \
        asm volatile("cp.async.commit_group;");                                    \
    }

    float acc[2][8][4];
#pragma unroll
    for (int mt = 0; mt < 2; mt++)
#pragma unroll
        for (int nt = 0; nt < 8; nt++)
#pragma unroll
            for (int r = 0; r < 4; r++) acc[mt][nt][r] = 0.f;

    const int nkt = K >> 5;
    GISSUE(0, 0);

    for (int kt = 0; kt < nkt; kt++) {
        const int buf = kt & 1;
        if (kt + 1 < nkt) {
            GISSUE(kt + 1, buf ^ 1);
            asm volatile("cp.async.wait_group 1;");
        } else {
            asm volatile("cp.async.wait_group 0;");
        }
        __syncthreads();

        const uint32_t* A0 = As + buf * 128 * GS;
        const uint32_t* B0 = Bs + buf * 128 * GS;
#pragma unroll
        for (int kk = 0; kk < 2; kk++) {
            uint32_t af[2][4], bf[8][2];
#pragma unroll
            for (int mt = 0; mt < 2; mt++) {
                uint2 v0 = *(const uint2*)&A0[(wm + mt * 16 + g) * GS + kk * 8 + 2 * tg];
                uint2 v1 = *(const uint2*)&A0[(wm + mt * 16 + g + 8) * GS + kk * 8 + 2 * tg];
                af[mt][0] = v0.x; af[mt][1] = v1.x;
                af[mt][2] = v0.y; af[mt][3] = v1.y;
            }
#pragma unroll
            for (int nt = 0; nt < 8; nt++) {
                uint2 vb = *(const uint2*)&B0[(wn + nt * 8 + g) * GS + kk * 8 + 2 * tg];
                bf[nt][0] = vb.x; bf[nt][1] = vb.y;
            }
#pragma unroll
            for (int mt = 0; mt < 2; mt++)
#pragma unroll
                for (int nt = 0; nt < 8; nt++)
                    mma_f16(acc[mt][nt], af[mt], bf[nt]);
        }
        __syncthreads();
    }

    // ---------------- epilogues ----------------
    if (mode == 0) {
#pragma unroll
        for (int mt = 0; mt < 2; mt++) {
            int row0 = bm + wm + mt * 16 + g;
#pragma unroll
            for (int nt = 0; nt < 8; nt++) {
                int col = blockIdx.x * 128 + wn + nt * 8 + tg * 2;
                float b0 = 0.f, b1 = 0.f;
                if (bias) { b0 = bias[col]; b1 = bias[col + 1]; }
                float2 v0, v1;
                v0.x = acc[mt][nt][0] + b0;
                v0.y = acc[mt][nt][1] + b1;
                v1.x = acc[mt][nt][2] + b0;
                v1.y = acc[mt][nt][3] + b1;
                *(float2*)(C + (size_t)row0 * N + col)       = v0;
                *(float2*)(C + (size_t)(row0 + 8) * N + col) = v1;
            }
        }
    } else if (mode <= 2) {
        const float sc = (mode == 1) ? QK_SCALE : 1.f;
#pragma unroll
        for (int mt = 0; mt < 2; mt++) {
            int row0 = bm + wm + mt * 16 + g;
            int bb = row0 >> 11, seq = row0 & 2047;
#pragma unroll
            for (int nt = 0; nt < 8; nt++) {
                int col  = blockIdx.x * 128 + wn + nt * 8 + tg * 2;
                int hh   = col >> 7;
                int p    = (col & 127) >> 1;
                int slot = (mode == 2) ? ppos(p) : p;
                size_t base = ((size_t)(bb * NH + hh) * 2048 + seq) * 64 + slot;
                uint32_t ph, pl;
                splitpack(acc[mt][nt][0] * sc, acc[mt][nt][1] * sc, ph, pl);
                oh[base] = ph; ol[base] = pl;
                splitpack(acc[mt][nt][2] * sc, acc[mt][nt][3] * sc, ph, pl);
                oh[base + 8 * 64] = ph; ol[base + 8 * 64] = pl;
            }
        }
    } else if (mode == 3) {  // V transposed row-pair packs
#pragma unroll
        for (int mt = 0; mt < 2; mt++) {
            int row0 = bm + wm + mt * 16 + g;
            int bb = row0 >> 11, seq0 = row0 & 2047;
            int ppA = seq0 >> 1;
            int ppB = (seq0 + 8) >> 1;
            int slotA = (ppA >> 4) * 16 + ppos(ppA & 15);
            int slotB = (ppB >> 4) * 16 + ppos(ppB & 15);
#pragma unroll
            for (int nt = 0; nt < 8; nt++) {
                float o0 = acc[mt][nt][0], o1 = acc[mt][nt][1];
                float o2 = acc[mt][nt][2], o3 = acc[mt][nt][3];
                float q0 = __shfl_xor_sync(0xffffffffu, o0, 4);
                float q1 = __shfl_xor_sync(0xffffffffu, o1, 4);
                float q2 = __shfl_xor_sync(0xffffffffu, o2, 4);
                float q3 = __shfl_xor_sync(0xffffffffu, o3, 4);
                if (!(g & 1)) {
                    int col  = blockIdx.x * 128 + wn + nt * 8 + tg * 2;
                    int hh   = col >> 7;
                    int wcol = col & 127;
                    uint32_t* vb = oh + ((size_t)(bb * NH + hh) * 128 + wcol) * 1024;
                    vb[slotA]        = h2pack(o0, q0);
                    vb[1024 + slotA] = h2pack(o1, q1);
                    vb[slotB]        = h2pack(o2, q2);
                    vb[1024 + slotB] = h2pack(o3, q3);
                }
            }
        }
    } else {  // mode 4: A-format pairs (slot order), row width N/2
        const int sw = N >> 1;
#pragma unroll
        for (int mt = 0; mt < 2; mt++) {
            int row0 = bm + wm + mt * 16 + g;
#pragma unroll
            for (int nt = 0; nt < 8; nt++) {
                int col = blockIdx.x * 128 + wn + nt * 8 + tg * 2;
                int slot = ppos(col >> 1);
                oh[(size_t)row0 * sw + slot]       = h2pack(acc[mt][nt][0], acc[mt][nt][1]);
                oh[(size_t)(row0 + 8) * sw + slot] = h2pack(acc[mt][nt][2], acc[mt][nt][3]);
            }
        }
    }
#undef GISSUE
}

// ====================================================================
// fp16 register-resident causal flash attention (R10 structure).
// Epilogue writes ctx as fp16 pairs in A-format (slot order).
// ====================================================================
#define FBM 128
#define FBN 32
#define KS 72
#define VS 20
#define FA_U32 (4*32*KS + 2*128*VS)
#define FA_SMEM_BYTES (FA_U32 * 4)

__global__ __launch_bounds__(256) void flash_attn_cp(
    const uint32_t* __restrict__ Qh_g, const uint32_t* __restrict__ Ql_g,
    const uint32_t* __restrict__ Kh_g, const uint32_t* __restrict__ Kl_g,
    const uint32_t* __restrict__ Vt_g, uint32_t* __restrict__ Ctxp)
{
    extern __shared__ uint32_t smu[];
    uint32_t* Khs = smu;
    uint32_t* Kls = smu + 2 * 32 * KS;
    uint32_t* Vts = smu + 4 * 32 * KS;
    const uint32_t sbase = (uint32_t)__cvta_generic_to_shared(smu);
    const uint32_t sKh = sbase;
    const uint32_t sKl = sbase + 2 * 32 * KS * 4;
    const uint32_t sVt = sbase + 4 * 32 * KS * 4;

    const int t    = threadIdx.x;
    const int lane = t & 31;
    const int warp = t >> 5;
    const int g    = lane >> 2;
    const int tg   = lane & 3;

    const int qt = gridDim.x - 1 - blockIdx.x;
    const int qb = qt * FBM;
    const int bh = blockIdx.y;
    const int b  = bh >> 4;
    const int h  = bh & 15;

    const uint32_t* Khg = Kh_g + (size_t)bh * 2048 * 64;
    const uint32_t* Klg = Kl_g + (size_t)bh * 2048 * 64;
    const uint32_t* Vgg = Vt_g + (size_t)bh * 128 * 1024;

    const int gr0  = qb + warp * 16 + g;
    const int wmax = qb + warp * 16 + 15;

    uint32_t qh[8][4], ql[8][4];
    {
        const uint32_t* qhg = Qh_g + ((size_t)bh * 2048 + gr0) * 64;
        const uint32_t* qlg = Ql_g + ((size_t)bh * 2048 + gr0) * 64;
#pragma unroll
        for (int kk = 0; kk < 8; kk++) {
            qh[kk][0] = qhg[8 * kk + tg];
            qh[kk][1] = qhg[8 * 64 + 8 * kk + tg];
            qh[kk][2] = qhg[8 * kk + tg + 4];
            qh[kk][3] = qhg[8 * 64 + 8 * kk + tg + 4];
            ql[kk][0] = qlg[8 * kk + tg];
            ql[kk][1] = qlg[8 * 64 + 8 * kk + tg];
            ql[kk][2] = qlg[8 * kk + tg + 4];
            ql[kk][3] = qlg[8 * 64 + 8 * kk + tg + 4];
        }
    }

    float oacc[16][4];
#pragma unroll
    for (int nt = 0; nt < 16; nt++)
#pragma unroll
        for (int r = 0; r < 4; r++) oacc[nt][r] = 0.f;
    float m0 = -INFINITY, m1 = -INFINITY;
    float l0 = 0.f, l1 = 0.f;

    const int kr = t >> 4, kc = t & 15;
    const int vl = t >> 2, vc = t & 3;

#define ISSUE_KV(kb_, buf)                                                        \
    {                                                                             \
        const uint32_t* s1 = Khg + (size_t)((kb_) + kr) * 64 + kc * 4;            \
        const uint32_t* s2 = s1 + 16 * 64;                                        \
        uint32_t d1 = sKh + (buf) * (32 * KS * 4) + kr * (KS * 4) + kc * 16;      \
        CPA16(d1, s1);                                                            \
        CPA16(d1 + 16 * (KS * 4), s2);                                            \
        const uint32_t* s3 = Klg + (size_t)((kb_) + kr) * 64 + kc * 4;            \
        const uint32_t* s4 = s3 + 16 * 64;                                        \
        uint32_t d3 = sKl + (buf) * (32 * KS * 4) + kr * (KS * 4) + kc * 16;      \
        CPA16(d3, s3);                                                            \
        CPA16(d3 + 16 * (KS * 4), s4);                                            \
        const uint32_t* s5 = Vgg + (size_t)vl * 1024 + ((kb_) >> 1) + vc * 4;     \
        const uint32_t* s6 = s5 + (size_t)64 * 1024;                              \
        uint32_t d5 = sVt + (buf) * (128 * VS * 4) + vl * (VS * 4) + vc * 16;     \
        CPA16(d5, s5);                                                            \
        CPA16(d5 + 64 * (VS * 4), s6);                                            \
        asm volatile("cp.async.commit_group;");                                   \
    }

    const int nkt = qb / FBN + 4;

    ISSUE_KV(0, 0);
    asm volatile("cp.async.wait_group 0;");
    __syncthreads();

    for (int kt = 0; kt < nkt; kt++) {
        const int kb  = kt * FBN;
        const int cur = kt & 1;
        const bool more = (kt + 1 < nkt);
        if (more) ISSUE_KV(kb + FBN, cur ^ 1);

        if (kb <= wmax) {
            const uint32_t* khb = Khs + cur * 32 * KS;
            const uint32_t* klb = Kls + cur * 32 * KS;

            float shh[4][4], sxa[4][4], sxb[4][4];
#pragma unroll
            for (int nt = 0; nt < 4; nt++)
#pragma unroll
                for (int r = 0; r < 4; r++) {
                    shh[nt][r] = 0.f; sxa[nt][r] = 0.f; sxb[nt][r] = 0.f;
                }

#pragma unroll
            for (int kk = 0; kk < 8; kk++) {
                uint32_t bhv[4][2], blv[4][2];
#pragma unroll
                for (int nt = 0; nt < 4; nt++) {
                    int row = (nt * 8 + g) * KS + kk * 8 + 2 * tg;
                    uint2 bh2 = *(const uint2*)&khb[row];
                    uint2 bl2 = *(const uint2*)&klb[row];
                    bhv[nt][0] = bh2.x; bhv[nt][1] = bh2.y;
                    blv[nt][0] = bl2.x; blv[nt][1] = bl2.y;
                }
#pragma unroll
                for (int nt = 0; nt < 4; nt++) mma_f16(shh[nt], qh[kk], bhv[nt]);
#pragma unroll
                for (int nt = 0; nt < 4; nt++) mma_f16(sxa[nt], ql[kk], bhv[nt]);
#pragma unroll
                for (int nt = 0; nt < 4; nt++) mma_f16(sxb[nt], qh[kk], blv[nt]);
            }

            float s[4][4];
#pragma unroll
            for (int nt = 0; nt < 4; nt++) {
#pragma unroll
                for (int r = 0; r < 4; r++)
                    s[nt][r] = shh[nt][r] + (sxa[nt][r] + sxb[nt][r]);
                if (kb + FBN - 1 > qb + warp * 16) {
                    int cb = kb + nt * 8 + 2 * tg;
                    if (cb     > gr0)     s[nt][0] = -INFINITY;
                    if (cb + 1 > gr0)     s[nt][1] = -INFINITY;
                    if (cb     > gr0 + 8) s[nt][2] = -INFINITY;
                    if (cb + 1 > gr0 + 8) s[nt][3] = -INFINITY;
                }
            }

            float mx0 = -INFINITY, mx1 = -INFINITY;
#pragma unroll
            for (int nt = 0; nt < 4; nt++) {
                mx0 = fmaxf(mx0, fmaxf(s[nt][0], s[nt][1]));
                mx1 = fmaxf(mx1, fmaxf(s[nt][2], s[nt][3]));
            }
            mx0 = fmaxf(mx0, __shfl_xor_sync(0xffffffffu, mx0, 1));
            mx0 = fmaxf(mx0, __shfl_xor_sync(0xffffffffu, mx0, 2));
            mx1 = fmaxf(mx1, __shfl_xor_sync(0xffffffffu, mx1, 1));
            mx1 = fmaxf(mx1, __shfl_xor_sync(0xffffffffu, mx1, 2));

            float nm0 = fmaxf(m0, mx0), nm1 = fmaxf(m1, mx1);
            float f0 = exp2f(m0 - nm0), f1 = exp2f(m1 - nm1);
            m0 = nm0; m1 = nm1;

            uint32_t pa[2][4];
            float s0 = 0.f, s1 = 0.f;
#pragma unroll
            for (int nt = 0; nt < 4; nt++) {
                float p0 = exp2f(s[nt][0] - nm0);
                float p1 = exp2f(s[nt][1] - nm0);
                float p2 = exp2f(s[nt][2] - nm1);
                float p3 = exp2f(s[nt][3] - nm1);
                s0 += p0 + p1;
                s1 += p2 + p3;
                pa[nt >> 1][(nt & 1) * 2 + 0] = h2pack(p0, p1);
                pa[nt >> 1][(nt & 1) * 2 + 1] = h2pack(p2, p3);
            }
            l0 = l0 * f0 + s0;
            l1 = l1 * f1 + s1;

            if (!__all_sync(0xffffffffu, (f0 == 1.f) && (f1 == 1.f))) {
#pragma unroll
                for (int nt = 0; nt < 16; nt++) {
                    oacc[nt][0] *= f0; oacc[nt][1] *= f0;
                    oacc[nt][2] *= f1; oacc[nt][3] *= f1;
                }
            }

            const uint32_t* vpb = Vts + cur * 128 * VS;
#pragma unroll
            for (int kk = 0; kk < 2; kk++) {
#pragma unroll
                for (int nt = 0; nt < 16; nt++) {
                    uint2 bv = *(const uint2*)&vpb[(nt * 8 + g) * VS + kk * 8 + 2 * tg];
                    uint32_t bb[2] = {bv.x, bv.y};
                    mma_f16(oacc[nt], pa[kk], bb);
                }
            }
        }

        if (more) asm volatile("cp.async.wait_group 0;");
        __syncthreads();
    }

    // ---- epilogue: write ctx as fp16 pairs in A-format ----
    l0 += __shfl_xor_sync(0xffffffffu, l0, 1);
    l0 += __shfl_xor_sync(0xffffffffu, l0, 2);
    l1 += __shfl_xor_sync(0xffffffffu, l1, 1);
    l1 += __shfl_xor_sync(0xffffffffu, l1, 2);
    float inv0 = 1.f / l0, inv1 = 1.f / l1;
    uint32_t* c0 = Ctxp + ((size_t)b * S_ + gr0) * 1024;
    uint32_t* c1 = Ctxp + ((size_t)b * S_ + gr0 + 8) * 1024;
#pragma unroll
    for (int nt = 0; nt < 16; nt++) {
        int colg = h * HD + nt * 8 + 2 * tg;
        int slot = ppos(colg >> 1);
        c0[slot] = h2pack(oacc[nt][0] * inv0, oacc[nt][1] * inv0);
        c1[slot] = h2pack(oacc[nt][2] * inv1, oacc[nt][3] * inv1);
    }
#undef ISSUE_KV
}

// ====================================================================
// launch
// ====================================================================
#define GEMM_SMEM (4 * 128 * GS * 4)

extern "C" void kernel_launch(void* const* d_in, const int* in_sizes, int n_in,
                              void* d_out, int out_size)
{
    const float* x    = (const float*)d_in[0];
    const float* Wq   = (const float*)d_in[1];
    const float* Wdkv = (const float*)d_in[2];
    const float* Wuk  = (const float*)d_in[3];
    const float* Wuv  = (const float*)d_in[4];
    const float* Wout = (const float*)d_in[5];
    const float* bout = (const float*)d_in[6];
    float* out = (float*)d_out;

    uint32_t *xp, *latp, *ctxp, *qh, *ql, *kh, *kl, *vt;
    uint32_t *wqp, *wdkvp, *wukp, *wuvp, *woutp;
    cudaGetSymbolAddress((void**)&xp,    g_xp);
    cudaGetSymbolAddress((void**)&latp,  g_latp);
    cudaGetSymbolAddress((void**)&ctxp,  g_ctxp);
    cudaGetSymbolAddress((void**)&qh,    g_qh16);
    cudaGetSymbolAddress((void**)&ql,    g_ql16);
    cudaGetSymbolAddress((void**)&kh,    g_kh16);
    cudaGetSymbolAddress((void**)&kl,    g_kl16);
    cudaGetSymbolAddress((void**)&vt,    g_vt16);
    cudaGetSymbolAddress((void**)&wqp,   g_wqp);
    cudaGetSymbolAddress((void**)&wdkvp, g_wdkvp);
    cudaGetSymbolAddress((void**)&wukp,  g_wukp);
    cudaGetSymbolAddress((void**)&wuvp,  g_wuvp);
    cudaGetSymbolAddress((void**)&woutp, g_woutp);

    cudaFuncSetAttribute(flash_attn_cp,
                         cudaFuncAttributeMaxDynamicSharedMemorySize, FA_SMEM_BYTES);
    cudaFuncSetAttribute(f16_gemm,
                         cudaFuncAttributeMaxDynamicSharedMemorySize, GEMM_SMEM);

    // one-time conversions (reads inputs each call for determinism)
    convert_x<<<ROWS, 256>>>(x, xp);
    convert_w<<<dim3(16, 64), 256>>>(Wq,   wqp,   DOUT);
    convert_w<<<dim3(2, 64),  256>>>(Wdkv, wdkvp, LAT);
    convert_w<<<dim3(16, 8),  256>>>(Wuk,  wukp,  DOUT);
    convert_w<<<dim3(16, 8),  256>>>(Wuv,  wuvp,  DOUT);
    convert_w<<<dim3(16, 64), 256>>>(Wout, woutp, DOUT);

    // q = x @ Wq -> Q hi/lo (scaled)
    f16_gemm<<<dim3(16, 32), 256, GEMM_SMEM>>>(
        xp, 1024, wqp, nullptr, nullptr, ROWS, DOUT, DIN, 1, qh, ql);
    // latent = x @ Wdkv -> A-format pairs
    f16_gemm<<<dim3(2, 32), 256, GEMM_SMEM>>>(
        xp, 1024, wdkvp, nullptr, nullptr, ROWS, LAT, DIN, 4, latp, nullptr);
    // k = lat @ Wuk -> K hi/lo
    f16_gemm<<<dim3(16, 32), 256, GEMM_SMEM>>>(
        latp, 128, wukp, nullptr, nullptr, ROWS, DOUT, LAT, 2, kh, kl);
    // v = lat @ Wuv -> V transposed packs
    f16_gemm<<<dim3(16, 32), 256, GEMM_SMEM>>>(
        latp, 128, wuvp, nullptr, nullptr, ROWS, DOUT, LAT, 3, vt, nullptr);
    // attention -> ctx pairs
    flash_attn_cp<<<dim3(S_ / FBM, B_ * NH), 256, FA_SMEM_BYTES>>>(
        qh, ql, kh, kl, vt, ctxp);
    // out = ctx @ Wout + bias (fp32)
    f16_gemm<<<dim3(16, 32), 256, GEMM_SMEM>>>(
        ctxp, 1024, woutp, out, bout, ROWS, DOUT, DOUT, 0, nullptr, nullptr);
}

// round 13
// speedup vs baseline: 1.6324x; 1.0873x over previous
#include <cuda_runtime.h>
#include <cuda_fp16.h>
#include <math.h>
#include <stdint.h>

// ---------------- problem constants ----------------
#define B_    2
#define S_    2048
#define DIN   2048
#define DOUT  2048
#define NH    16
#define HD    128
#define LAT   256
#define ROWS  (B_ * S_)            // 4096
#define QK_SCALE  (0.08838834764831845f * 1.4426950408889634f)  // 1/sqrt(hd) * log2(e)

// ---------------- scratch ----------------
__device__ uint32_t g_xp[ROWS * 1024];        // x as fp16 pairs, slot order
__device__ uint32_t g_latp[ROWS * 128];       // latent pairs, slot order
__device__ uint32_t g_ctxp[ROWS * 1024];      // ctx pairs, slot order
__device__ uint32_t g_qh16[32 * 2048 * 64];   // Q hi pairs (natural order, scaled)
__device__ uint32_t g_ql16[32 * 2048 * 64];   // Q lo pairs
__device__ uint32_t g_kh16[32 * 2048 * 64];   // K hi pairs (slot order per row)
__device__ uint32_t g_kl16[32 * 2048 * 64];   // K lo pairs
__device__ uint32_t g_vt16[32 * 128 * 1024];  // V transposed row-pair packs
// weights as fp16 pairs, blocked [kt][ntile][n 128][slot 16]
__device__ uint32_t g_wqp[64 * 16 * 128 * 16];
__device__ uint32_t g_wdkvp[64 * 2 * 128 * 16];
__device__ uint32_t g_wukp[8 * 16 * 128 * 16];
__device__ uint32_t g_wuvp[8 * 16 * 128 * 16];
__device__ uint32_t g_woutp[64 * 16 * 128 * 16];

__device__ __forceinline__ void mma_f16(float* d, const uint32_t* a, const uint32_t* b) {
    asm volatile(
        "mma.sync.aligned.m16n8k16.row.col.f32.f16.f16.f32 "
        "{%0,%1,%2,%3}, {%4,%5,%6,%7}, {%8,%9}, {%0,%1,%2,%3};"
        : "+f"(d[0]), "+f"(d[1]), "+f"(d[2]), "+f"(d[3])
        : "r"(a[0]), "r"(a[1]), "r"(a[2]), "r"(a[3]), "r"(b[0]), "r"(b[1]));
}

// packed-pair slot: pair p -> u32 index so LDS.64 at (kk*8 + 2*tg) yields
// (pair tg, pair tg+4) = mma b0/b1 (or a0/a2).
__device__ __host__ __forceinline__ int ppos(int p) {
    int pp = p & 7;
    int slot = (pp < 4) ? (2 * pp) : (2 * (pp - 4) + 1);
    return ((p >> 3) << 3) + slot;
}

// single-instruction pack: {lo, hi} -> f16x2 (lo in bits [15:0])
__device__ __forceinline__ uint32_t h2pack(float lo, float hi) {
    uint32_t r;
    asm("cvt.rn.f16x2.f32 %0, %1, %2;" : "=r"(r) : "f"(hi), "f"(lo));
    return r;
}

// split (x,y) into fp16 hi-pair and fp16 lo-pair (error compensation)
__device__ __forceinline__ void splitpack(float x, float y, uint32_t& ph, uint32_t& pl) {
    ph = h2pack(x, y);
    float hx = __half2float(__ushort_as_half((unsigned short)(ph & 0xffffu)));
    float hy = __half2float(__ushort_as_half((unsigned short)(ph >> 16)));
    pl = h2pack(x - hx, y - hy);
}

#define CPA16(saddr, gptr) \
    asm volatile("cp.async.cg.shared.global [%0], [%1], 16;" :: "r"(saddr), "l"(gptr))

// ====================================================================
// one-time converters
// ====================================================================
// x [rows][2048] fp32 -> xp [rows][1024] fp16 pairs in slot order
__global__ void convert_x(const float* __restrict__ x, uint32_t* __restrict__ xp) {
    int row = blockIdx.x, t = threadIdx.x;
    const float* src = x + (size_t)row * 2048;
    uint32_t* dst = xp + (size_t)row * 1024;
#pragma unroll
    for (int j = 0; j < 2; j++) {
        int c = (t + 256 * j) * 4;
        float4 v = *(const float4*)(src + c);
        int p = c >> 1;
        dst[ppos(p)]     = h2pack(v.x, v.y);
        dst[ppos(p + 1)] = h2pack(v.z, v.w);
    }
}

// W [K][N] fp32 -> Bp [kt][ntile][n 128][slot 16] fp16 k-pairs
#define WST 132
__global__ void convert_w(const float* __restrict__ W, uint32_t* __restrict__ Bp, int N) {
    __shared__ __align__(16) float stage[32 * WST];
    int kt = blockIdx.y, ntile = blockIdx.x, t = threadIdx.x;
    int NT = N >> 7;
    int r = t >> 5, c = (t & 31) * 4;
    const float* src = W + (size_t)(kt * 32) * N + ntile * 128;
#pragma unroll
    for (int i = 0; i < 4; i++)
        *(float4*)&stage[(r + 8 * i) * WST + c] =
            *(const float4*)(src + (size_t)(r + 8 * i) * N + c);
    __syncthreads();
    uint32_t* dst = Bp + ((size_t)(kt * NT + ntile) * 128) * 16;
#pragma unroll
    for (int j = 0; j < 8; j++) {
        int id = t + 256 * j;
        int n = id >> 4, s = id & 15;
        int grp = s >> 3, sw = s & 7;
        int pp = (sw & 1) ? ((sw >> 1) + 4) : (sw >> 1);
        int p = grp * 8 + pp;
        dst[n * 16 + s] = h2pack(stage[(2 * p) * WST + n], stage[(2 * p + 1) * WST + n]);
    }
}

// ====================================================================
// fp16 tensor-core GEMM: C[M,N] = A@B, fp32 accumulate.
// A: fp16 pairs [m][K/2 slots]; B: fp16 pairs blocked [kt][nt][128][16].
// 128x128 tile, BK=32, 256 thr, 3-stage cp.async pipeline,
// __launch_bounds__(256,2) -> 2 CTAs/SM (4 warps/SMSP).
// modes: 0 fp32+bias | 1 Q hi/lo scaled (natural) | 2 K hi/lo (slot)
//        3 V transposed packs | 4 A-format pairs (slot)
// ====================================================================
#define GS 24   // smem u32 stride per row (16 payload + 8 pad)
#define GSTG 3  // pipeline stages

__global__ __launch_bounds__(256, 2) void f16_gemm(
    const uint32_t* __restrict__ Ap, int assw,
    const uint32_t* __restrict__ Bp,
    float* __restrict__ C, const float* __restrict__ bias,
    int M, int N, int K, int mode,
    uint32_t* __restrict__ oh, uint32_t* __restrict__ ol)
{
    extern __shared__ uint32_t gsm[];
    uint32_t* As = gsm;                    // [3][128*GS]
    uint32_t* Bs = gsm + GSTG * 128 * GS;  // [3][128*GS]
    const uint32_t sA = (uint32_t)__cvta_generic_to_shared(As);
    const uint32_t sB = (uint32_t)__cvta_generic_to_shared(Bs);

    const int t    = threadIdx.x;
    const int lane = t & 31;
    const int warp = t >> 5;
    const int bm   = blockIdx.y * 128;
    const int NT   = N >> 7;
    const int wm   = (warp >> 1) * 32;
    const int wn   = (warp & 1) * 64;
    const int g    = lane >> 2;
    const int tg   = lane & 3;

    // loader: thread owns one row-chunk pair (32B) per operand
    const int lrow = t >> 1;
    const int lseg = (t & 1) * 2;

#define GISSUE(kt_, buf_)                                                          \
    {                                                                              \
        const uint32_t* as_ = Ap + (size_t)(bm + lrow) * assw + (kt_) * 16 + lseg * 4; \
        uint32_t ad_ = sA + ((buf_) * 128 * GS + lrow * GS + lseg * 4) * 4;        \
        CPA16(ad_, as_); CPA16(ad_ + 16, as_ + 4);                                 \
        const uint32_t* bs_ = Bp + ((size_t)((kt_) * NT + blockIdx.x) * 128 + lrow) * 16 + lseg * 4; \
        uint32_t bd_ = sB + ((buf_) * 128 * GS + lrow * GS + lseg * 4) * 4;        \
        CPA16(bd_, bs_); CPA16(bd_ + 16, bs_ + 4);                                 \
        asm volatile("cp.async.commit_group;");                                    \
    }

    float acc[2][8][4];
#pragma unroll
    for (int mt = 0; mt < 2; mt++)
#pragma unroll
        for (int nt = 0; nt < 8; nt++)
#pragma unroll
            for (int r = 0; r < 4; r++) acc[mt][nt][r] = 0.f;

    const int nkt = K >> 5;
    GISSUE(0, 0);
    if (nkt > 1) GISSUE(1, 1);

    int buf = 0;
    for (int kt = 0; kt < nkt; kt++) {
        if (kt + 2 < nkt) {
            int nb = (kt + 2) % GSTG;
            GISSUE(kt + 2, nb);
            asm volatile("cp.async.wait_group 2;");
        } else if (kt + 1 < nkt) {
            asm volatile("cp.async.wait_group 1;");
        } else {
            asm volatile("cp.async.wait_group 0;");
        }
        __syncthreads();

        const uint32_t* A0 = As + buf * 128 * GS;
        const uint32_t* B0 = Bs + buf * 128 * GS;
#pragma unroll
        for (int kk = 0; kk < 2; kk++) {
            uint32_t af[2][4], bf[8][2];
#pragma unroll
            for (int mt = 0; mt < 2; mt++) {
                uint2 v0 = *(const uint2*)&A0[(wm + mt * 16 + g) * GS + kk * 8 + 2 * tg];
                uint2 v1 = *(const uint2*)&A0[(wm + mt * 16 + g + 8) * GS + kk * 8 + 2 * tg];
                af[mt][0] = v0.x; af[mt][1] = v1.x;
                af[mt][2] = v0.y; af[mt][3] = v1.y;
            }
#pragma unroll
            for (int nt = 0; nt < 8; nt++) {
                uint2 vb = *(const uint2*)&B0[(wn + nt * 8 + g) * GS + kk * 8 + 2 * tg];
                bf[nt][0] = vb.x; bf[nt][1] = vb.y;
            }
#pragma unroll
            for (int mt = 0; mt < 2; mt++)
#pragma unroll
                for (int nt = 0; nt < 8; nt++)
                    mma_f16(acc[mt][nt], af[mt], bf[nt]);
        }
        __syncthreads();
        buf = (buf + 1 == GSTG) ? 0 : buf + 1;
    }

    // ---------------- epilogues ----------------
    if (mode == 0) {
#pragma unroll
        for (int mt = 0; mt < 2; mt++) {
            int row0 = bm + wm + mt * 16 + g;
#pragma unroll
            for (int nt = 0; nt < 8; nt++) {
                int col = blockIdx.x * 128 + wn + nt * 8 + tg * 2;
                float b0 = 0.f, b1 = 0.f;
                if (bias) { b0 = bias[col]; b1 = bias[col + 1]; }
                float2 v0, v1;
                v0.x = acc[mt][nt][0] + b0;
                v0.y = acc[mt][nt][1] + b1;
                v1.x = acc[mt][nt][2] + b0;
                v1.y = acc[mt][nt][3] + b1;
                *(float2*)(C + (size_t)row0 * N + col)       = v0;
                *(float2*)(C + (size_t)(row0 + 8) * N + col) = v1;
            }
        }
    } else if (mode <= 2) {
        const float sc = (mode == 1) ? QK_SCALE : 1.f;
#pragma unroll
        for (int mt = 0; mt < 2; mt++) {
            int row0 = bm + wm + mt * 16 + g;
            int bb = row0 >> 11, seq = row0 & 2047;
#pragma unroll
            for (int nt = 0; nt < 8; nt++) {
                int col  = blockIdx.x * 128 + wn + nt * 8 + tg * 2;
                int hh   = col >> 7;
                int p    = (col & 127) >> 1;
                int slot = (mode == 2) ? ppos(p) : p;
                size_t base = ((size_t)(bb * NH + hh) * 2048 + seq) * 64 + slot;
                uint32_t ph, pl;
                splitpack(acc[mt][nt][0] * sc, acc[mt][nt][1] * sc, ph, pl);
                oh[base] = ph; ol[base] = pl;
                splitpack(acc[mt][nt][2] * sc, acc[mt][nt][3] * sc, ph, pl);
                oh[base + 8 * 64] = ph; ol[base + 8 * 64] = pl;
            }
        }
    } else if (mode == 3) {  // V transposed row-pair packs
#pragma unroll
        for (int mt = 0; mt < 2; mt++) {
            int row0 = bm + wm + mt * 16 + g;
            int bb = row0 >> 11, seq0 = row0 & 2047;
            int ppA = seq0 >> 1;
            int ppB = (seq0 + 8) >> 1;
            int slotA = (ppA >> 4) * 16 + ppos(ppA & 15);
            int slotB = (ppB >> 4) * 16 + ppos(ppB & 15);
#pragma unroll
            for (int nt = 0; nt < 8; nt++) {
                float o0 = acc[mt][nt][0], o1 = acc[mt][nt][1];
                float o2 = acc[mt][nt][2], o3 = acc[mt][nt][3];
                float q0 = __shfl_xor_sync(0xffffffffu, o0, 4);
                float q1 = __shfl_xor_sync(0xffffffffu, o1, 4);
                float q2 = __shfl_xor_sync(0xffffffffu, o2, 4);
                float q3 = __shfl_xor_sync(0xffffffffu, o3, 4);
                if (!(g & 1)) {
                    int col  = blockIdx.x * 128 + wn + nt * 8 + tg * 2;
                    int hh   = col >> 7;
                    int wcol = col & 127;
                    uint32_t* vb = oh + ((size_t)(bb * NH + hh) * 128 + wcol) * 1024;
                    vb[slotA]        = h2pack(o0, q0);
                    vb[1024 + slotA] = h2pack(o1, q1);
                    vb[slotB]        = h2pack(o2, q2);
                    vb[1024 + slotB] = h2pack(o3, q3);
                }
            }
        }
    } else {  // mode 4: A-format pairs (slot order), row width N/2
        const int sw = N >> 1;
#pragma unroll
        for (int mt = 0; mt < 2; mt++) {
            int row0 = bm + wm + mt * 16 + g;
#pragma unroll
            for (int nt = 0; nt < 8; nt++) {
                int col = blockIdx.x * 128 + wn + nt * 8 + tg * 2;
                int slot = ppos(col >> 1);
                oh[(size_t)row0 * sw + slot]       = h2pack(acc[mt][nt][0], acc[mt][nt][1]);
                oh[(size_t)(row0 + 8) * sw + slot] = h2pack(acc[mt][nt][2], acc[mt][nt][3]);
            }
        }
    }
#undef GISSUE
}

// ====================================================================
// fp16 register-resident causal flash attention (unchanged from R12).
// ====================================================================
#define FBM 128
#define FBN 32
#define KS 72
#define VS 20
#define FA_U32 (4*32*KS + 2*128*VS)
#define FA_SMEM_BYTES (FA_U32 * 4)

__global__ __launch_bounds__(256) void flash_attn_cp(
    const uint32_t* __restrict__ Qh_g, const uint32_t* __restrict__ Ql_g,
    const uint32_t* __restrict__ Kh_g, const uint32_t* __restrict__ Kl_g,
    const uint32_t* __restrict__ Vt_g, uint32_t* __restrict__ Ctxp)
{
    extern __shared__ uint32_t smu[];
    uint32_t* Khs = smu;
    uint32_t* Kls = smu + 2 * 32 * KS;
    uint32_t* Vts = smu + 4 * 32 * KS;
    const uint32_t sbase = (uint32_t)__cvta_generic_to_shared(smu);
    const uint32_t sKh = sbase;
    const uint32_t sKl = sbase + 2 * 32 * KS * 4;
    const uint32_t sVt = sbase + 4 * 32 * KS * 4;

    const int t    = threadIdx.x;
    const int lane = t & 31;
    const int warp = t >> 5;
    const int g    = lane >> 2;
    const int tg   = lane & 3;

    const int qt = gridDim.x - 1 - blockIdx.x;
    const int qb = qt * FBM;
    const int bh = blockIdx.y;
    const int b  = bh >> 4;
    const int h  = bh & 15;

    const uint32_t* Khg = Kh_g + (size_t)bh * 2048 * 64;
    const uint32_t* Klg = Kl_g + (size_t)bh * 2048 * 64;
    const uint32_t* Vgg = Vt_g + (size_t)bh * 128 * 1024;

    const int gr0  = qb + warp * 16 + g;
    const int wmax = qb + warp * 16 + 15;

    uint32_t qh[8][4], ql[8][4];
    {
        const uint32_t* qhg = Qh_g + ((size_t)bh * 2048 + gr0) * 64;
        const uint32_t* qlg = Ql_g + ((size_t)bh * 2048 + gr0) * 64;
#pragma unroll
        for (int kk = 0; kk < 8; kk++) {
            qh[kk][0] = qhg[8 * kk + tg];
            qh[kk][1] = qhg[8 * 64 + 8 * kk + tg];
            qh[kk][2] = qhg[8 * kk + tg + 4];
            qh[kk][3] = qhg[8 * 64 + 8 * kk + tg + 4];
            ql[kk][0] = qlg[8 * kk + tg];
            ql[kk][1] = qlg[8 * 64 + 8 * kk + tg];
            ql[kk][2] = qlg[8 * kk + tg + 4];
            ql[kk][3] = qlg[8 * 64 + 8 * kk + tg + 4];
        }
    }

    float oacc[16][4];
#pragma unroll
    for (int nt = 0; nt < 16; nt++)
#pragma unroll
        for (int r = 0; r < 4; r++) oacc[nt][r] = 0.f;
    float m0 = -INFINITY, m1 = -INFINITY;
    float l0 = 0.f, l1 = 0.f;

    const int kr = t >> 4, kc = t & 15;
    const int vl = t >> 2, vc = t & 3;

#define ISSUE_KV(kb_, buf)                                                        \
    {                                                                             \
        const uint32_t* s1 = Khg + (size_t)((kb_) + kr) * 64 + kc * 4;            \
        const uint32_t* s2 = s1 + 16 * 64;                                        \
        uint32_t d1 = sKh + (buf) * (32 * KS * 4) + kr * (KS * 4) + kc * 16;      \
        CPA16(d1, s1);                                                            \
        CPA16(d1 + 16 * (KS * 4), s2);                                            \
        const uint32_t* s3 = Klg + (size_t)((kb_) + kr) * 64 + kc * 4;            \
        const uint32_t* s4 = s3 + 16 * 64;                                        \
        uint32_t d3 = sKl + (buf) * (32 * KS * 4) + kr * (KS * 4) + kc * 16;      \
        CPA16(d3, s3);                                                            \
        CPA16(d3 + 16 * (KS * 4), s4);                                            \
        const uint32_t* s5 = Vgg + (size_t)vl * 1024 + ((kb_) >> 1) + vc * 4;     \
        const uint32_t* s6 = s5 + (size_t)64 * 1024;                              \
        uint32_t d5 = sVt + (buf) * (128 * VS * 4) + vl * (VS * 4) + vc * 16;     \
        CPA16(d5, s5);                                                            \
        CPA16(d5 + 64 * (VS * 4), s6);                                            \
        asm volatile("cp.async.commit_group;");                                   \
    }

    const int nkt = qb / FBN + 4;

    ISSUE_KV(0, 0);
    asm volatile("cp.async.wait_group 0;");
    __syncthreads();

    for (int kt = 0; kt < nkt; kt++) {
        const int kb  = kt * FBN;
        const int cur = kt & 1;
        const bool more = (kt + 1 < nkt);
        if (more) ISSUE_KV(kb + FBN, cur ^ 1);

        if (kb <= wmax) {
            const uint32_t* khb = Khs + cur * 32 * KS;
            const uint32_t* klb = Kls + cur * 32 * KS;

            float shh[4][4], sxa[4][4], sxb[4][4];
#pragma unroll
            for (int nt = 0; nt < 4; nt++)
#pragma unroll
                for (int r = 0; r < 4; r++) {
                    shh[nt][r] = 0.f; sxa[nt][r] = 0.f; sxb[nt][r] = 0.f;
                }

#pragma unroll
            for (int kk = 0; kk < 8; kk++) {
                uint32_t bhv[4][2], blv[4][2];
#pragma unroll
                for (int nt = 0; nt < 4; nt++) {
                    int row = (nt * 8 + g) * KS + kk * 8 + 2 * tg;
                    uint2 bh2 = *(const uint2*)&khb[row];
                    uint2 bl2 = *(const uint2*)&klb[row];
                    bhv[nt][0] = bh2.x; bhv[nt][1] = bh2.y;
                    blv[nt][0] = bl2.x; blv[nt][1] = bl2.y;
                }
#pragma unroll
                for (int nt = 0; nt < 4; nt++) mma_f16(shh[nt], qh[kk], bhv[nt]);
#pragma unroll
                for (int nt = 0; nt < 4; nt++) mma_f16(sxa[nt], ql[kk], bhv[nt]);
#pragma unroll
                for (int nt = 0; nt < 4; nt++) mma_f16(sxb[nt], qh[kk], blv[nt]);
            }

            float s[4][4];
#pragma unroll
            for (int nt = 0; nt < 4; nt++) {
#pragma unroll
                for (int r = 0; r < 4; r++)
                    s[nt][r] = shh[nt][r] + (sxa[nt][r] + sxb[nt][r]);
                if (kb + FBN - 1 > qb + warp * 16) {
                    int cb = kb + nt * 8 + 2 * tg;
                    if (cb     > gr0)     s[nt][0] = -INFINITY;
                    if (cb + 1 > gr0)     s[nt][1] = -INFINITY;
                    if (cb     > gr0 + 8) s[nt][2] = -INFINITY;
                    if (cb + 1 > gr0 + 8) s[nt][3] = -INFINITY;
                }
            }

            float mx0 = -INFINITY, mx1 = -INFINITY;
#pragma unroll
            for (int nt = 0; nt < 4; nt++) {
                mx0 = fmaxf(mx0, fmaxf(s[nt][0], s[nt][1]));
                mx1 = fmaxf(mx1, fmaxf(s[nt][2], s[nt][3]));
            }
            mx0 = fmaxf(mx0, __shfl_xor_sync(0xffffffffu, mx0, 1));
            mx0 = fmaxf(mx0, __shfl_xor_sync(0xffffffffu, mx0, 2));
            mx1 = fmaxf(mx1, __shfl_xor_sync(0xffffffffu, mx1, 1));
            mx1 = fmaxf(mx1, __shfl_xor_sync(0xffffffffu, mx1, 2));

            float nm0 = fmaxf(m0, mx0), nm1 = fmaxf(m1, mx1);
            float f0 = exp2f(m0 - nm0), f1 = exp2f(m1 - nm1);
            m0 = nm0; m1 = nm1;

            uint32_t pa[2][4];
            float s0 = 0.f, s1 = 0.f;
#pragma unroll
            for (int nt = 0; nt < 4; nt++) {
                float p0 = exp2f(s[nt][0] - nm0);
                float p1 = exp2f(s[nt][1] - nm0);
                float p2 = exp2f(s[nt][2] - nm1);
                float p3 = exp2f(s[nt][3] - nm1);
                s0 += p0 + p1;
                s1 += p2 + p3;
                pa[nt >> 1][(nt & 1) * 2 + 0] = h2pack(p0, p1);
                pa[nt >> 1][(nt & 1) * 2 + 1] = h2pack(p2, p3);
            }
            l0 = l0 * f0 + s0;
            l1 = l1 * f1 + s1;

            if (!__all_sync(0xffffffffu, (f0 == 1.f) && (f1 == 1.f))) {
#pragma unroll
                for (int nt = 0; nt < 16; nt++) {
                    oacc[nt][0] *= f0; oacc[nt][1] *= f0;
                    oacc[nt][2] *= f1; oacc[nt][3] *= f1;
                }
            }

            const uint32_t* vpb = Vts + cur * 128 * VS;
#pragma unroll
            for (int kk = 0; kk < 2; kk++) {
#pragma unroll
                for (int nt = 0; nt < 16; nt++) {
                    uint2 bv = *(const uint2*)&vpb[(nt * 8 + g) * VS + kk * 8 + 2 * tg];
                    uint32_t bb[2] = {bv.x, bv.y};
                    mma_f16(oacc[nt], pa[kk], bb);
                }
            }
        }

        if (more) asm volatile("cp.async.wait_group 0;");
        __syncthreads();
    }

    // ---- epilogue: write ctx as fp16 pairs in A-format ----
    l0 += __shfl_xor_sync(0xffffffffu, l0, 1);
    l0 += __shfl_xor_sync(0xffffffffu, l0, 2);
    l1 += __shfl_xor_sync(0xffffffffu, l1, 1);
    l1 += __shfl_xor_sync(0xffffffffu, l1, 2);
    float inv0 = 1.f / l0, inv1 = 1.f / l1;
    uint32_t* c0 = Ctxp + ((size_t)b * S_ + gr0) * 1024;
    uint32_t* c1 = Ctxp + ((size_t)b * S_ + gr0 + 8) * 1024;
#pragma unroll
    for (int nt = 0; nt < 16; nt++) {
        int colg = h * HD + nt * 8 + 2 * tg;
        int slot = ppos(colg >> 1);
        c0[slot] = h2pack(oacc[nt][0] * inv0, oacc[nt][1] * inv0);
        c1[slot] = h2pack(oacc[nt][2] * inv1, oacc[nt][3] * inv1);
    }
#undef ISSUE_KV
}

// ====================================================================
// launch
// ====================================================================
#define GEMM_SMEM (2 * GSTG * 128 * GS * 4)

extern "C" void kernel_launch(void* const* d_in, const int* in_sizes, int n_in,
                              void* d_out, int out_size)
{
    const float* x    = (const float*)d_in[0];
    const float* Wq   = (const float*)d_in[1];
    const float* Wdkv = (const float*)d_in[2];
    const float* Wuk  = (const float*)d_in[3];
    const float* Wuv  = (const float*)d_in[4];
    const float* Wout = (const float*)d_in[5];
    const float* bout = (const float*)d_in[6];
    float* out = (float*)d_out;

    uint32_t *xp, *latp, *ctxp, *qh, *ql, *kh, *kl, *vt;
    uint32_t *wqp, *wdkvp, *wukp, *wuvp, *woutp;
    cudaGetSymbolAddress((void**)&xp,    g_xp);
    cudaGetSymbolAddress((void**)&latp,  g_latp);
    cudaGetSymbolAddress((void**)&ctxp,  g_ctxp);
    cudaGetSymbolAddress((void**)&qh,    g_qh16);
    cudaGetSymbolAddress((void**)&ql,    g_ql16);
    cudaGetSymbolAddress((void**)&kh,    g_kh16);
    cudaGetSymbolAddress((void**)&kl,    g_kl16);
    cudaGetSymbolAddress((void**)&vt,    g_vt16);
    cudaGetSymbolAddress((void**)&wqp,   g_wqp);
    cudaGetSymbolAddress((void**)&wdkvp, g_wdkvp);
    cudaGetSymbolAddress((void**)&wukp,  g_wukp);
    cudaGetSymbolAddress((void**)&wuvp,  g_wuvp);
    cudaGetSymbolAddress((void**)&woutp, g_woutp);

    cudaFuncSetAttribute(flash_attn_cp,
                         cudaFuncAttributeMaxDynamicSharedMemorySize, FA_SMEM_BYTES);
    cudaFuncSetAttribute(f16_gemm,
                         cudaFuncAttributeMaxDynamicSharedMemorySize, GEMM_SMEM);

    // one-time conversions
    convert_x<<<ROWS, 256>>>(x, xp);
    convert_w<<<dim3(16, 64), 256>>>(Wq,   wqp,   DOUT);
    convert_w<<<dim3(2, 64),  256>>>(Wdkv, wdkvp, LAT);
    convert_w<<<dim3(16, 8),  256>>>(Wuk,  wukp,  DOUT);
    convert_w<<<dim3(16, 8),  256>>>(Wuv,  wuvp,  DOUT);
    convert_w<<<dim3(16, 64), 256>>>(Wout, woutp, DOUT);

    // q = x @ Wq -> Q hi/lo (scaled)
    f16_gemm<<<dim3(16, 32), 256, GEMM_SMEM>>>(
        xp, 1024, wqp, nullptr, nullptr, ROWS, DOUT, DIN, 1, qh, ql);
    // latent = x @ Wdkv -> A-format pairs
    f16_gemm<<<dim3(2, 32), 256, GEMM_SMEM>>>(
        xp, 1024, wdkvp, nullptr, nullptr, ROWS, LAT, DIN, 4, latp, nullptr);
    // k = lat @ Wuk -> K hi/lo
    f16_gemm<<<dim3(16, 32), 256, GEMM_SMEM>>>(
        latp, 128, wukp, nullptr, nullptr, ROWS, DOUT, LAT, 2, kh, kl);
    // v = lat @ Wuv -> V transposed packs
    f16_gemm<<<dim3(16, 32), 256, GEMM_SMEM>>>(
        latp, 128, wuvp, nullptr, nullptr, ROWS, DOUT, LAT, 3, vt, nullptr);
    // attention -> ctx pairs
    flash_attn_cp<<<dim3(S_ / FBM, B_ * NH), 256, FA_SMEM_BYTES>>>(
        qh, ql, kh, kl, vt, ctxp);
    // out = ctx @ Wout + bias (fp32)
    f16_gemm<<<dim3(16, 32), 256, GEMM_SMEM>>>(
        ctxp, 1024, woutp, out, bout, ROWS, DOUT, DOUT, 0, nullptr, nullptr);
}

// round 15
// speedup vs baseline: 1.7702x; 1.0845x over previous
#include <cuda_runtime.h>
#include <cuda_fp16.h>
#include <math.h>
#include <stdint.h>

// ---------------- problem constants ----------------
#define B_    2
#define S_    2048
#define DIN   2048
#define DOUT  2048
#define NH    16
#define HD    128
#define LAT   256
#define ROWS  (B_ * S_)            // 4096
#define QK_SCALE  (0.08838834764831845f * 1.4426950408889634f)  // 1/sqrt(hd) * log2(e)

// ---------------- scratch ----------------
__device__ uint32_t g_xp[ROWS * 1024];        // x as fp16 pairs, slot order
__device__ uint32_t g_latp[ROWS * 128];       // latent pairs, slot order
__device__ uint32_t g_ctxp[ROWS * 1024];      // ctx pairs, slot order
__device__ uint32_t g_qh16[32 * 2048 * 64];   // Q hi pairs (natural order, scaled)
__device__ uint32_t g_ql16[32 * 2048 * 64];   // Q lo pairs
__device__ uint32_t g_kh16[32 * 2048 * 64];   // K fp16 pairs (slot order per row)
__device__ uint32_t g_vt16[32 * 128 * 1024];  // V transposed row-pair packs
// weights as fp16 pairs, blocked [kt][ntile][n 128][slot 16]
__device__ uint32_t g_wqp[64 * 16 * 128 * 16];
__device__ uint32_t g_wdkvp[64 * 2 * 128 * 16];
__device__ uint32_t g_wukp[8 * 16 * 128 * 16];
__device__ uint32_t g_wuvp[8 * 16 * 128 * 16];
__device__ uint32_t g_woutp[64 * 16 * 128 * 16];

__device__ __forceinline__ void mma_f16(float* d, const uint32_t* a, const uint32_t* b) {
    asm volatile(
        "mma.sync.aligned.m16n8k16.row.col.f32.f16.f16.f32 "
        "{%0,%1,%2,%3}, {%4,%5,%6,%7}, {%8,%9}, {%0,%1,%2,%3};"
        : "+f"(d[0]), "+f"(d[1]), "+f"(d[2]), "+f"(d[3])
        : "r"(a[0]), "r"(a[1]), "r"(a[2]), "r"(a[3]), "r"(b[0]), "r"(b[1]));
}

// packed-pair slot: pair p -> u32 index so LDS.64 at (kk*8 + 2*tg) yields
// (pair tg, pair tg+4) = mma b0/b1 (or a0/a2).
__device__ __host__ __forceinline__ int ppos(int p) {
    int pp = p & 7;
    int slot = (pp < 4) ? (2 * pp) : (2 * (pp - 4) + 1);
    return ((p >> 3) << 3) + slot;
}

// single-instruction pack: {lo, hi} -> f16x2 (lo in bits [15:0])
__device__ __forceinline__ uint32_t h2pack(float lo, float hi) {
    uint32_t r;
    asm("cvt.rn.f16x2.f32 %0, %1, %2;" : "=r"(r) : "f"(hi), "f"(lo));
    return r;
}

// split (x,y) into fp16 hi-pair and fp16 lo-pair (error compensation)
__device__ __forceinline__ void splitpack(float x, float y, uint32_t& ph, uint32_t& pl) {
    ph = h2pack(x, y);
    float hx = __half2float(__ushort_as_half((unsigned short)(ph & 0xffffu)));
    float hy = __half2float(__ushort_as_half((unsigned short)(ph >> 16)));
    pl = h2pack(x - hx, y - hy);
}

#define CPA16(saddr, gptr) \
    asm volatile("cp.async.cg.shared.global [%0], [%1], 16;" :: "r"(saddr), "l"(gptr))

// ====================================================================
// one-time converters
// ====================================================================
__global__ void convert_x(const float* __restrict__ x, uint32_t* __restrict__ xp) {
    int row = blockIdx.x, t = threadIdx.x;
    const float* src = x + (size_t)row * 2048;
    uint32_t* dst = xp + (size_t)row * 1024;
#pragma unroll
    for (int j = 0; j < 2; j++) {
        int c = (t + 256 * j) * 4;
        float4 v = *(const float4*)(src + c);
        int p = c >> 1;
        dst[ppos(p)]     = h2pack(v.x, v.y);
        dst[ppos(p + 1)] = h2pack(v.z, v.w);
    }
}

#define WST 132
__global__ void convert_w(const float* __restrict__ W, uint32_t* __restrict__ Bp, int N) {
    __shared__ __align__(16) float stage[32 * WST];
    int kt = blockIdx.y, ntile = blockIdx.x, t = threadIdx.x;
    int NT = N >> 7;
    int r = t >> 5, c = (t & 31) * 4;
    const float* src = W + (size_t)(kt * 32) * N + ntile * 128;
#pragma unroll
    for (int i = 0; i < 4; i++)
        *(float4*)&stage[(r + 8 * i) * WST + c] =
            *(const float4*)(src + (size_t)(r + 8 * i) * N + c);
    __syncthreads();
    uint32_t* dst = Bp + ((size_t)(kt * NT + ntile) * 128) * 16;
#pragma unroll
    for (int j = 0; j < 8; j++) {
        int id = t + 256 * j;
        int n = id >> 4, s = id & 15;
        int grp = s >> 3, sw = s & 7;
        int pp = (sw & 1) ? ((sw >> 1) + 4) : (sw >> 1);
        int p = grp * 8 + pp;
        dst[n * 16 + s] = h2pack(stage[(2 * p) * WST + n], stage[(2 * p + 1) * WST + n]);
    }
}

// ====================================================================
// fp16 tensor-core GEMM: 128x128 tile, BK=32, 256 thr, 4-stage cp.async
// pipeline, 2 CTAs/SM.
// modes: 0 fp32+bias | 1 Q hi/lo scaled (natural) | 2 K fp16 (slot)
//        3 V transposed packs | 4 A-format pairs (slot)
// ====================================================================
#define GS 24   // smem u32 stride per row (16 payload + 8 pad)
#define GSTG 4  // pipeline stages

__global__ __launch_bounds__(256, 2) void f16_gemm(
    const uint32_t* __restrict__ Ap, int assw,
    const uint32_t* __restrict__ Bp,
    float* __restrict__ C, const float* __restrict__ bias,
    int M, int N, int K, int mode,
    uint32_t* __restrict__ oh, uint32_t* __restrict__ ol)
{
    extern __shared__ uint32_t gsm[];
    uint32_t* As = gsm;                    // [GSTG][128*GS]
    uint32_t* Bs = gsm + GSTG * 128 * GS;  // [GSTG][128*GS]
    const uint32_t sA = (uint32_t)__cvta_generic_to_shared(As);
    const uint32_t sB = (uint32_t)__cvta_generic_to_shared(Bs);

    const int t    = threadIdx.x;
    const int lane = t & 31;
    const int warp = t >> 5;
    const int bm   = blockIdx.y * 128;
    const int NT   = N >> 7;
    const int wm   = (warp >> 1) * 32;
    const int wn   = (warp & 1) * 64;
    const int g    = lane >> 2;
    const int tg   = lane & 3;

    const int lrow = t >> 1;
    const int lseg = (t & 1) * 2;

#define GISSUE(kt_, buf_)                                                          \
    {                                                                              \
        const uint32_t* as_ = Ap + (size_t)(bm + lrow) * assw + (kt_) * 16 + lseg * 4; \
        uint32_t ad_ = sA + ((buf_) * 128 * GS + lrow * GS + lseg * 4) * 4;        \
        CPA16(ad_, as_); CPA16(ad_ + 16, as_ + 4);                                 \
        const uint32_t* bs_ = Bp + ((size_t)((kt_) * NT + blockIdx.x) * 128 + lrow) * 16 + lseg * 4; \
        uint32_t bd_ = sB + ((buf_) * 128 * GS + lrow * GS + lseg * 4) * 4;        \
        CPA16(bd_, bs_); CPA16(bd_ + 16, bs_ + 4);                                 \
        asm volatile("cp.async.commit_group;");                                    \
    }

    float acc[2][8][4];
#pragma unroll
    for (int mt = 0; mt < 2; mt++)
#pragma unroll
        for (int nt = 0; nt < 8; nt++)
#pragma unroll
            for (int r = 0; r < 4; r++) acc[mt][nt][r] = 0.f;

    const int nkt = K >> 5;
    GISSUE(0, 0);
    if (nkt > 1) GISSUE(1, 1);
    if (nkt > 2) GISSUE(2, 2);

    int buf = 0;
    for (int kt = 0; kt < nkt; kt++) {
        if (kt + 3 < nkt) {
            int nb = (kt + 3) % GSTG;
            GISSUE(kt + 3, nb);
            asm volatile("cp.async.wait_group 3;");
        } else if (kt + 2 < nkt) {
            asm volatile("cp.async.wait_group 2;");
        } else if (kt + 1 < nkt) {
            asm volatile("cp.async.wait_group 1;");
        } else {
            asm volatile("cp.async.wait_group 0;");
        }
        __syncthreads();

        const uint32_t* A0 = As + buf * 128 * GS;
        const uint32_t* B0 = Bs + buf * 128 * GS;
#pragma unroll
        for (int kk = 0; kk < 2; kk++) {
            uint32_t af[2][4], bf[8][2];
#pragma unroll
            for (int mt = 0; mt < 2; mt++) {
                uint2 v0 = *(const uint2*)&A0[(wm + mt * 16 + g) * GS + kk * 8 + 2 * tg];
                uint2 v1 = *(const uint2*)&A0[(wm + mt * 16 + g + 8) * GS + kk * 8 + 2 * tg];
                af[mt][0] = v0.x; af[mt][1] = v1.x;
                af[mt][2] = v0.y; af[mt][3] = v1.y;
            }
#pragma unroll
            for (int nt = 0; nt < 8; nt++) {
                uint2 vb = *(const uint2*)&B0[(wn + nt * 8 + g) * GS + kk * 8 + 2 * tg];
                bf[nt][0] = vb.x; bf[nt][1] = vb.y;
            }
#pragma unroll
            for (int mt = 0; mt < 2; mt++)
#pragma unroll
                for (int nt = 0; nt < 8; nt++)
                    mma_f16(acc[mt][nt], af[mt], bf[nt]);
        }
        __syncthreads();
        buf = (buf + 1 == GSTG) ? 0 : buf + 1;
    }

    // ---------------- epilogues ----------------
    if (mode == 0) {
#pragma unroll
        for (int mt = 0; mt < 2; mt++) {
            int row0 = bm + wm + mt * 16 + g;
#pragma unroll
            for (int nt = 0; nt < 8; nt++) {
                int col = blockIdx.x * 128 + wn + nt * 8 + tg * 2;
                float b0 = 0.f, b1 = 0.f;
                if (bias) { b0 = bias[col]; b1 = bias[col + 1]; }
                float2 v0, v1;
                v0.x = acc[mt][nt][0] + b0;
                v0.y = acc[mt][nt][1] + b1;
                v1.x = acc[mt][nt][2] + b0;
                v1.y = acc[mt][nt][3] + b1;
                *(float2*)(C + (size_t)row0 * N + col)       = v0;
                *(float2*)(C + (size_t)(row0 + 8) * N + col) = v1;
            }
        }
    } else if (mode == 1) {   // Q: hi/lo split, scaled
#pragma unroll
        for (int mt = 0; mt < 2; mt++) {
            int row0 = bm + wm + mt * 16 + g;
            int bb = row0 >> 11, seq = row0 & 2047;
#pragma unroll
            for (int nt = 0; nt < 8; nt++) {
                int col  = blockIdx.x * 128 + wn + nt * 8 + tg * 2;
                int hh   = col >> 7;
                int slot = (col & 127) >> 1;
                size_t base = ((size_t)(bb * NH + hh) * 2048 + seq) * 64 + slot;
                uint32_t ph, pl;
                splitpack(acc[mt][nt][0] * QK_SCALE, acc[mt][nt][1] * QK_SCALE, ph, pl);
                oh[base] = ph; ol[base] = pl;
                splitpack(acc[mt][nt][2] * QK_SCALE, acc[mt][nt][3] * QK_SCALE, ph, pl);
                oh[base + 8 * 64] = ph; ol[base + 8 * 64] = pl;
            }
        }
    } else if (mode == 2) {   // K: single fp16, slot order
#pragma unroll
        for (int mt = 0; mt < 2; mt++) {
            int row0 = bm + wm + mt * 16 + g;
            int bb = row0 >> 11, seq = row0 & 2047;
#pragma unroll
            for (int nt = 0; nt < 8; nt++) {
                int col  = blockIdx.x * 128 + wn + nt * 8 + tg * 2;
                int hh   = col >> 7;
                int slot = ppos((col & 127) >> 1);
                size_t base = ((size_t)(bb * NH + hh) * 2048 + seq) * 64 + slot;
                oh[base]          = h2pack(acc[mt][nt][0], acc[mt][nt][1]);
                oh[base + 8 * 64] = h2pack(acc[mt][nt][2], acc[mt][nt][3]);
            }
        }
    } else if (mode == 3) {  // V transposed row-pair packs
#pragma unroll
        for (int mt = 0; mt < 2; mt++) {
            int row0 = bm + wm + mt * 16 + g;
            int bb = row0 >> 11, seq0 = row0 & 2047;
            int ppA = seq0 >> 1;
            int ppB = (seq0 + 8) >> 1;
            int slotA = (ppA >> 4) * 16 + ppos(ppA & 15);
            int slotB = (ppB >> 4) * 16 + ppos(ppB & 15);
#pragma unroll
            for (int nt = 0; nt < 8; nt++) {
                float o0 = acc[mt][nt][0], o1 = acc[mt][nt][1];
                float o2 = acc[mt][nt][2], o3 = acc[mt][nt][3];
                float q0 = __shfl_xor_sync(0xffffffffu, o0, 4);
                float q1 = __shfl_xor_sync(0xffffffffu, o1, 4);
                float q2 = __shfl_xor_sync(0xffffffffu, o2, 4);
                float q3 = __shfl_xor_sync(0xffffffffu, o3, 4);
                if (!(g & 1)) {
                    int col  = blockIdx.x * 128 + wn + nt * 8 + tg * 2;
                    int hh   = col >> 7;
                    int wcol = col & 127;
                    uint32_t* vb = oh + ((size_t)(bb * NH + hh) * 128 + wcol) * 1024;
                    vb[slotA]        = h2pack(o0, q0);
                    vb[1024 + slotA] = h2pack(o1, q1);
                    vb[slotB]        = h2pack(o2, q2);
                    vb[1024 + slotB] = h2pack(o3, q3);
                }
            }
        }
    } else {  // mode 4: A-format pairs (slot order), row width N/2
        const int sw = N >> 1;
#pragma unroll
        for (int mt = 0; mt < 2; mt++) {
            int row0 = bm + wm + mt * 16 + g;
#pragma unroll
            for (int nt = 0; nt < 8; nt++) {
                int col = blockIdx.x * 128 + wn + nt * 8 + tg * 2;
                int slot = ppos(col >> 1);
                oh[(size_t)row0 * sw + slot]       = h2pack(acc[mt][nt][0], acc[mt][nt][1]);
                oh[(size_t)(row0 + 8) * sw + slot] = h2pack(acc[mt][nt][2], acc[mt][nt][3]);
            }
        }
    }
#undef GISSUE
}

// ====================================================================
// fp16 register-resident causal flash attention.
// QK^T fp16x2: (qh + ql)·kh — K-side lo dropped (error ~2.8e-4, inside
// budget). K single buffer per tile; cp.async double-buffered.
// ====================================================================
#define FBM 128
#define FBN 32
#define KS 72
#define VS 20
#define FA_U32 (2*32*KS + 2*128*VS)
#define FA_SMEM_BYTES (FA_U32 * 4)

__global__ __launch_bounds__(256) void flash_attn_cp(
    const uint32_t* __restrict__ Qh_g, const uint32_t* __restrict__ Ql_g,
    const uint32_t* __restrict__ Kh_g,
    const uint32_t* __restrict__ Vt_g, uint32_t* __restrict__ Ctxp)
{
    extern __shared__ uint32_t smu[];
    uint32_t* Khs = smu;                    // [2][32][KS]
    uint32_t* Vts = smu + 2 * 32 * KS;      // [2][128][VS]
    const uint32_t sbase = (uint32_t)__cvta_generic_to_shared(smu);
    const uint32_t sKh = sbase;
    const uint32_t sVt = sbase + 2 * 32 * KS * 4;

    const int t    = threadIdx.x;
    const int lane = t & 31;
    const int warp = t >> 5;
    const int g    = lane >> 2;
    const int tg   = lane & 3;

    const int qt = gridDim.x - 1 - blockIdx.x;
    const int qb = qt * FBM;
    const int bh = blockIdx.y;
    const int b  = bh >> 4;
    const int h  = bh & 15;

    const uint32_t* Khg = Kh_g + (size_t)bh * 2048 * 64;
    const uint32_t* Vgg = Vt_g + (size_t)bh * 128 * 1024;

    const int gr0  = qb + warp * 16 + g;
    const int wmax = qb + warp * 16 + 15;

    uint32_t qh[8][4], ql[8][4];
    {
        const uint32_t* qhg = Qh_g + ((size_t)bh * 2048 + gr0) * 64;
        const uint32_t* qlg = Ql_g + ((size_t)bh * 2048 + gr0) * 64;
#pragma unroll
        for (int kk = 0; kk < 8; kk++) {
            qh[kk][0] = qhg[8 * kk + tg];
            qh[kk][1] = qhg[8 * 64 + 8 * kk + tg];
            qh[kk][2] = qhg[8 * kk + tg + 4];
            qh[kk][3] = qhg[8 * 64 + 8 * kk + tg + 4];
            ql[kk][0] = qlg[8 * kk + tg];
            ql[kk][1] = qlg[8 * 64 + 8 * kk + tg];
            ql[kk][2] = qlg[8 * kk + tg + 4];
            ql[kk][3] = qlg[8 * 64 + 8 * kk + tg + 4];
        }
    }

    float oacc[16][4];
#pragma unroll
    for (int nt = 0; nt < 16; nt++)
#pragma unroll
        for (int r = 0; r < 4; r++) oacc[nt][r] = 0.f;
    float m0 = -INFINITY, m1 = -INFINITY;
    float l0 = 0.f, l1 = 0.f;

    const int kr = t >> 4, kc = t & 15;
    const int vl = t >> 2, vc = t & 3;

#define ISSUE_KV(kb_, buf)                                                        \
    {                                                                             \
        const uint32_t* s1 = Khg + (size_t)((kb_) + kr) * 64 + kc * 4;            \
        const uint32_t* s2 = s1 + 16 * 64;                                        \
        uint32_t d1 = sKh + (buf) * (32 * KS * 4) + kr * (KS * 4) + kc * 16;      \
        CPA16(d1, s1);                                                            \
        CPA16(d1 + 16 * (KS * 4), s2);                                            \
        const uint32_t* s5 = Vgg + (size_t)vl * 1024 + ((kb_) >> 1) + vc * 4;     \
        const uint32_t* s6 = s5 + (size_t)64 * 1024;                              \
        uint32_t d5 = sVt + (buf) * (128 * VS * 4) + vl * (VS * 4) + vc * 16;     \
        CPA16(d5, s5);                                                            \
        CPA16(d5 + 64 * (VS * 4), s6);                                            \
        asm volatile("cp.async.commit_group;");                                   \
    }

    const int nkt = qb / FBN + 4;

    ISSUE_KV(0, 0);
    asm volatile("cp.async.wait_group 0;");
    __syncthreads();

    for (int kt = 0; kt < nkt; kt++) {
        const int kb  = kt * FBN;
        const int cur = kt & 1;
        const bool more = (kt + 1 < nkt);
        if (more) ISSUE_KV(kb + FBN, cur ^ 1);

        if (kb <= wmax) {
            const uint32_t* khb = Khs + cur * 32 * KS;

            // ---- S = Q K^T, fp16x2: hh + lo·hi chains ----
            float shh[4][4], sxa[4][4];
#pragma unroll
            for (int nt = 0; nt < 4; nt++)
#pragma unroll
                for (int r = 0; r < 4; r++) { shh[nt][r] = 0.f; sxa[nt][r] = 0.f; }

#pragma unroll
            for (int kk = 0; kk < 8; kk++) {
                uint32_t bhv[4][2];
#pragma unroll
                for (int nt = 0; nt < 4; nt++) {
                    uint2 bh2 = *(const uint2*)&khb[(nt * 8 + g) * KS + kk * 8 + 2 * tg];
                    bhv[nt][0] = bh2.x; bhv[nt][1] = bh2.y;
                }
#pragma unroll
                for (int nt = 0; nt < 4; nt++) mma_f16(shh[nt], qh[kk], bhv[nt]);
#pragma unroll
                for (int nt = 0; nt < 4; nt++) mma_f16(sxa[nt], ql[kk], bhv[nt]);
            }

            float s[4][4];
#pragma unroll
            for (int nt = 0; nt < 4; nt++) {
#pragma unroll
                for (int r = 0; r < 4; r++) s[nt][r] = shh[nt][r] + sxa[nt][r];
                if (kb + FBN - 1 > qb + warp * 16) {
                    int cb = kb + nt * 8 + 2 * tg;
                    if (cb     > gr0)     s[nt][0] = -INFINITY;
                    if (cb + 1 > gr0)     s[nt][1] = -INFINITY;
                    if (cb     > gr0 + 8) s[nt][2] = -INFINITY;
                    if (cb + 1 > gr0 + 8) s[nt][3] = -INFINITY;
                }
            }

            float mx0 = -INFINITY, mx1 = -INFINITY;
#pragma unroll
            for (int nt = 0; nt < 4; nt++) {
                mx0 = fmaxf(mx0, fmaxf(s[nt][0], s[nt][1]));
                mx1 = fmaxf(mx1, fmaxf(s[nt][2], s[nt][3]));
            }
            mx0 = fmaxf(mx0, __shfl_xor_sync(0xffffffffu, mx0, 1));
            mx0 = fmaxf(mx0, __shfl_xor_sync(0xffffffffu, mx0, 2));
            mx1 = fmaxf(mx1, __shfl_xor_sync(0xffffffffu, mx1, 1));
            mx1 = fmaxf(mx1, __shfl_xor_sync(0xffffffffu, mx1, 2));

            float nm0 = fmaxf(m0, mx0), nm1 = fmaxf(m1, mx1);
            float f0 = exp2f(m0 - nm0), f1 = exp2f(m1 - nm1);
            m0 = nm0; m1 = nm1;

            uint32_t pa[2][4];
            float s0 = 0.f, s1 = 0.f;
#pragma unroll
            for (int nt = 0; nt < 4; nt++) {
                float p0 = exp2f(s[nt][0] - nm0);
                float p1 = exp2f(s[nt][1] - nm0);
                float p2 = exp2f(s[nt][2] - nm1);
                float p3 = exp2f(s[nt][3] - nm1);
                s0 += p0 + p1;
                s1 += p2 + p3;
                pa[nt >> 1][(nt & 1) * 2 + 0] = h2pack(p0, p1);
                pa[nt >> 1][(nt & 1) * 2 + 1] = h2pack(p2, p3);
            }
            l0 = l0 * f0 + s0;
            l1 = l1 * f1 + s1;

            if (!__all_sync(0xffffffffu, (f0 == 1.f) && (f1 == 1.f))) {
#pragma unroll
                for (int nt = 0; nt < 16; nt++) {
                    oacc[nt][0] *= f0; oacc[nt][1] *= f0;
                    oacc[nt][2] *= f1; oacc[nt][3] *= f1;
                }
            }

            const uint32_t* vpb = Vts + cur * 128 * VS;
#pragma unroll
            for (int kk = 0; kk < 2; kk++) {
#pragma unroll
                for (int nt = 0; nt < 16; nt++) {
                    uint2 bv = *(const uint2*)&vpb[(nt * 8 + g) * VS + kk * 8 + 2 * tg];
                    uint32_t bb[2] = {bv.x, bv.y};
                    mma_f16(oacc[nt], pa[kk], bb);
                }
            }
        }

        if (more) asm volatile("cp.async.wait_group 0;");
        __syncthreads();
    }

    // ---- epilogue: write ctx as fp16 pairs in A-format ----
    l0 += __shfl_xor_sync(0xffffffffu, l0, 1);
    l0 += __shfl_xor_sync(0xffffffffu, l0, 2);
    l1 += __shfl_xor_sync(0xffffffffu, l1, 1);
    l1 += __shfl_xor_sync(0xffffffffu, l1, 2);
    float inv0 = 1.f / l0, inv1 = 1.f / l1;
    uint32_t* c0 = Ctxp + ((size_t)b * S_ + gr0) * 1024;
    uint32_t* c1 = Ctxp + ((size_t)b * S_ + gr0 + 8) * 1024;
#pragma unroll
    for (int nt = 0; nt < 16; nt++) {
        int colg = h * HD + nt * 8 + 2 * tg;
        int slot = ppos(colg >> 1);
        c0[slot] = h2pack(oacc[nt][0] * inv0, oacc[nt][1] * inv0);
        c1[slot] = h2pack(oacc[nt][2] * inv1, oacc[nt][3] * inv1);
    }
#undef ISSUE_KV
}

// ====================================================================
// launch
// ====================================================================
#define GEMM_SMEM (2 * GSTG * 128 * GS * 4)

extern "C" void kernel_launch(void* const* d_in, const int* in_sizes, int n_in,
                              void* d_out, int out_size)
{
    const float* x    = (const float*)d_in[0];
    const float* Wq   = (const float*)d_in[1];
    const float* Wdkv = (const float*)d_in[2];
    const float* Wuk  = (const float*)d_in[3];
    const float* Wuv  = (const float*)d_in[4];
    const float* Wout = (const float*)d_in[5];
    const float* bout = (const float*)d_in[6];
    float* out = (float*)d_out;

    uint32_t *xp, *latp, *ctxp, *qh, *ql, *kh, *vt;
    uint32_t *wqp, *wdkvp, *wukp, *wuvp, *woutp;
    cudaGetSymbolAddress((void**)&xp,    g_xp);
    cudaGetSymbolAddress((void**)&latp,  g_latp);
    cudaGetSymbolAddress((void**)&ctxp,  g_ctxp);
    cudaGetSymbolAddress((void**)&qh,    g_qh16);
    cudaGetSymbolAddress((void**)&ql,    g_ql16);
    cudaGetSymbolAddress((void**)&kh,    g_kh16);
    cudaGetSymbolAddress((void**)&vt,    g_vt16);
    cudaGetSymbolAddress((void**)&wqp,   g_wqp);
    cudaGetSymbolAddress((void**)&wdkvp, g_wdkvp);
    cudaGetSymbolAddress((void**)&wukp,  g_wukp);
    cudaGetSymbolAddress((void**)&wuvp,  g_wuvp);
    cudaGetSymbolAddress((void**)&woutp, g_woutp);

    cudaFuncSetAttribute(flash_attn_cp,
                         cudaFuncAttributeMaxDynamicSharedMemorySize, FA_SMEM_BYTES);
    cudaFuncSetAttribute(f16_gemm,
                         cudaFuncAttributeMaxDynamicSharedMemorySize, GEMM_SMEM);

    // one-time conversions
    convert_x<<<ROWS, 256>>>(x, xp);
    convert_w<<<dim3(16, 64), 256>>>(Wq,   wqp,   DOUT);
    convert_w<<<dim3(2, 64),  256>>>(Wdkv, wdkvp, LAT);
    convert_w<<<dim3(16, 8),  256>>>(Wuk,  wukp,  DOUT);
    convert_w<<<dim3(16, 8),  256>>>(Wuv,  wuvp,  DOUT);
    convert_w<<<dim3(16, 64), 256>>>(Wout, woutp, DOUT);

    // q = x @ Wq -> Q hi/lo (scaled)
    f16_gemm<<<dim3(16, 32), 256, GEMM_SMEM>>>(
        xp, 1024, wqp, nullptr, nullptr, ROWS, DOUT, DIN, 1, qh, ql);
    // latent = x @ Wdkv -> A-format pairs
    f16_gemm<<<dim3(2, 32), 256, GEMM_SMEM>>>(
        xp, 1024, wdkvp, nullptr, nullptr, ROWS, LAT, DIN, 4, latp, nullptr);
    // k = lat @ Wuk -> K fp16 (slot order)
    f16_gemm<<<dim3(16, 32), 256, GEMM_SMEM>>>(
        latp, 128, wukp, nullptr, nullptr, ROWS, DOUT, LAT, 2, kh, nullptr);
    // v = lat @ Wuv -> V transposed packs
    f16_gemm<<<dim3(16, 32), 256, GEMM_SMEM>>>(
        latp, 128, wuvp, nullptr, nullptr, ROWS, DOUT, LAT, 3, vt, nullptr);
    // attention -> ctx pairs
    flash_attn_cp<<<dim3(S_ / FBM, B_ * NH), 256, FA_SMEM_BYTES>>>(
        qh, ql, kh, vt, ctxp);
    // out = ctx @ Wout + bias (fp32)
    f16_gemm<<<dim3(16, 32), 256, GEMM_SMEM>>>(
        ctxp, 1024, woutp, out, bout, ROWS, DOUT, DOUT, 0, nullptr, nullptr);
}

// round 16
// speedup vs baseline: 1.8016x; 1.0177x over previous
#include <cuda_runtime.h>
#include <cuda_fp16.h>
#include <math.h>
#include <stdint.h>

// ---------------- problem constants ----------------
#define B_    2
#define S_    2048
#define DIN   2048
#define DOUT  2048
#define NH    16
#define HD    128
#define LAT   256
#define ROWS  (B_ * S_)            // 4096
#define QK_SCALE  (0.08838834764831845f * 1.4426950408889634f)  // 1/sqrt(hd) * log2(e)

// ---------------- scratch ----------------
__device__ uint32_t g_xp[ROWS * 1024];        // x as fp16 pairs, slot order
__device__ uint32_t g_latp[ROWS * 128];       // latent pairs, slot order
__device__ uint32_t g_ctxp[ROWS * 1024];      // ctx pairs, slot order
__device__ uint32_t g_qh16[32 * 2048 * 64];   // Q fp16 pairs (natural order, scaled)
__device__ uint32_t g_kh16[32 * 2048 * 64];   // K fp16 pairs (slot order per row)
__device__ uint32_t g_vt16[32 * 128 * 1024];  // V transposed row-pair packs
// weights as fp16 pairs, blocked [kt][ntile][n 128][slot 16]
__device__ uint32_t g_wqp[64 * 16 * 128 * 16];
__device__ uint32_t g_wdkvp[64 * 2 * 128 * 16];
__device__ uint32_t g_wukp[8 * 16 * 128 * 16];
__device__ uint32_t g_wuvp[8 * 16 * 128 * 16];
__device__ uint32_t g_woutp[64 * 16 * 128 * 16];

__device__ __forceinline__ void mma_f16(float* d, const uint32_t* a, const uint32_t* b) {
    asm volatile(
        "mma.sync.aligned.m16n8k16.row.col.f32.f16.f16.f32 "
        "{%0,%1,%2,%3}, {%4,%5,%6,%7}, {%8,%9}, {%0,%1,%2,%3};"
        : "+f"(d[0]), "+f"(d[1]), "+f"(d[2]), "+f"(d[3])
        : "r"(a[0]), "r"(a[1]), "r"(a[2]), "r"(a[3]), "r"(b[0]), "r"(b[1]));
}

// packed-pair slot: pair p -> u32 index so LDS.64 at (kk*8 + 2*tg) yields
// (pair tg, pair tg+4) = mma b0/b1 (or a0/a2).
__device__ __host__ __forceinline__ int ppos(int p) {
    int pp = p & 7;
    int slot = (pp < 4) ? (2 * pp) : (2 * (pp - 4) + 1);
    return ((p >> 3) << 3) + slot;
}

// single-instruction pack: {lo, hi} -> f16x2 (lo in bits [15:0])
__device__ __forceinline__ uint32_t h2pack(float lo, float hi) {
    uint32_t r;
    asm("cvt.rn.f16x2.f32 %0, %1, %2;" : "=r"(r) : "f"(hi), "f"(lo));
    return r;
}

#define CPA16(saddr, gptr) \
    asm volatile("cp.async.cg.shared.global [%0], [%1], 16;" :: "r"(saddr), "l"(gptr))

// ====================================================================
// one-time converters
// ====================================================================
__global__ void convert_x(const float* __restrict__ x, uint32_t* __restrict__ xp) {
    int row = blockIdx.x, t = threadIdx.x;
    const float* src = x + (size_t)row * 2048;
    uint32_t* dst = xp + (size_t)row * 1024;
#pragma unroll
    for (int j = 0; j < 2; j++) {
        int c = (t + 256 * j) * 4;
        float4 v = *(const float4*)(src + c);
        int p = c >> 1;
        dst[ppos(p)]     = h2pack(v.x, v.y);
        dst[ppos(p + 1)] = h2pack(v.z, v.w);
    }
}

#define WST 132
__global__ void convert_w(const float* __restrict__ W, uint32_t* __restrict__ Bp, int N) {
    __shared__ __align__(16) float stage[32 * WST];
    int kt = blockIdx.y, ntile = blockIdx.x, t = threadIdx.x;
    int NT = N >> 7;
    int r = t >> 5, c = (t & 31) * 4;
    const float* src = W + (size_t)(kt * 32) * N + ntile * 128;
#pragma unroll
    for (int i = 0; i < 4; i++)
        *(float4*)&stage[(r + 8 * i) * WST + c] =
            *(const float4*)(src + (size_t)(r + 8 * i) * N + c);
    __syncthreads();
    uint32_t* dst = Bp + ((size_t)(kt * NT + ntile) * 128) * 16;
#pragma unroll
    for (int j = 0; j < 8; j++) {
        int id = t + 256 * j;
        int n = id >> 4, s = id & 15;
        int grp = s >> 3, sw = s & 7;
        int pp = (sw & 1) ? ((sw >> 1) + 4) : (sw >> 1);
        int p = grp * 8 + pp;
        dst[n * 16 + s] = h2pack(stage[(2 * p) * WST + n], stage[(2 * p + 1) * WST + n]);
    }
}

// ====================================================================
// fp16 tensor-core GEMM: 128x128 tile, BK=32, 256 thr, 4-stage cp.async
// pipeline, 2 CTAs/SM.
// modes: 0 fp32+bias | 1 Q fp16 scaled (natural order) | 2 K fp16 (slot)
//        3 V transposed packs | 4 A-format pairs (slot)
// ====================================================================
#define GS 24   // smem u32 stride per row (16 payload + 8 pad)
#define GSTG 4  // pipeline stages

__global__ __launch_bounds__(256, 2) void f16_gemm(
    const uint32_t* __restrict__ Ap, int assw,
    const uint32_t* __restrict__ Bp,
    float* __restrict__ C, const float* __restrict__ bias,
    int M, int N, int K, int mode,
    uint32_t* __restrict__ oh)
{
    extern __shared__ uint32_t gsm[];
    uint32_t* As = gsm;                    // [GSTG][128*GS]
    uint32_t* Bs = gsm + GSTG * 128 * GS;  // [GSTG][128*GS]
    const uint32_t sA = (uint32_t)__cvta_generic_to_shared(As);
    const uint32_t sB = (uint32_t)__cvta_generic_to_shared(Bs);

    const int t    = threadIdx.x;
    const int lane = t & 31;
    const int warp = t >> 5;
    const int bm   = blockIdx.y * 128;
    const int NT   = N >> 7;
    const int wm   = (warp >> 1) * 32;
    const int wn   = (warp & 1) * 64;
    const int g    = lane >> 2;
    const int tg   = lane & 3;

    const int lrow = t >> 1;
    const int lseg = (t & 1) * 2;

#define GISSUE(kt_, buf_)                                                          \
    {                                                                              \
        const uint32_t* as_ = Ap + (size_t)(bm + lrow) * assw + (kt_) * 16 + lseg * 4; \
        uint32_t ad_ = sA + ((buf_) * 128 * GS + lrow * GS + lseg * 4) * 4;        \
        CPA16(ad_, as_); CPA16(ad_ + 16, as_ + 4);                                 \
        const uint32_t* bs_ = Bp + ((size_t)((kt_) * NT + blockIdx.x) * 128 + lrow) * 16 + lseg * 4; \
        uint32_t bd_ = sB + ((buf_) * 128 * GS + lrow * GS + lseg * 4) * 4;        \
        CPA16(bd_, bs_); CPA16(bd_ + 16, bs_ + 4);                                 \
        asm volatile("cp.async.commit_group;");                                    \
    }

    float acc[2][8][4];
#pragma unroll
    for (int mt = 0; mt < 2; mt++)
#pragma unroll
        for (int nt = 0; nt < 8; nt++)
#pragma unroll
            for (int r = 0; r < 4; r++) acc[mt][nt][r] = 0.f;

    const int nkt = K >> 5;
    GISSUE(0, 0);
    if (nkt > 1) GISSUE(1, 1);
    if (nkt > 2) GISSUE(2, 2);

    int buf = 0;
    for (int kt = 0; kt < nkt; kt++) {
        if (kt + 3 < nkt) {
            int nb = (kt + 3) % GSTG;
            GISSUE(kt + 3, nb);
            asm volatile("cp.async.wait_group 3;");
        } else if (kt + 2 < nkt) {
            asm volatile("cp.async.wait_group 2;");
        } else if (kt + 1 < nkt) {
            asm volatile("cp.async.wait_group 1;");
        } else {
            asm volatile("cp.async.wait_group 0;");
        }
        __syncthreads();

        const uint32_t* A0 = As + buf * 128 * GS;
        const uint32_t* B0 = Bs + buf * 128 * GS;
#pragma unroll
        for (int kk = 0; kk < 2; kk++) {
            uint32_t af[2][4], bf[8][2];
#pragma unroll
            for (int mt = 0; mt < 2; mt++) {
                uint2 v0 = *(const uint2*)&A0[(wm + mt * 16 + g) * GS + kk * 8 + 2 * tg];
                uint2 v1 = *(const uint2*)&A0[(wm + mt * 16 + g + 8) * GS + kk * 8 + 2 * tg];
                af[mt][0] = v0.x; af[mt][1] = v1.x;
                af[mt][2] = v0.y; af[mt][3] = v1.y;
            }
#pragma unroll
            for (int nt = 0; nt < 8; nt++) {
                uint2 vb = *(const uint2*)&B0[(wn + nt * 8 + g) * GS + kk * 8 + 2 * tg];
                bf[nt][0] = vb.x; bf[nt][1] = vb.y;
            }
#pragma unroll
            for (int mt = 0; mt < 2; mt++)
#pragma unroll
                for (int nt = 0; nt < 8; nt++)
                    mma_f16(acc[mt][nt], af[mt], bf[nt]);
        }
        __syncthreads();
        buf = (buf + 1 == GSTG) ? 0 : buf + 1;
    }

    // ---------------- epilogues ----------------
    if (mode == 0) {
#pragma unroll
        for (int mt = 0; mt < 2; mt++) {
            int row0 = bm + wm + mt * 16 + g;
#pragma unroll
            for (int nt = 0; nt < 8; nt++) {
                int col = blockIdx.x * 128 + wn + nt * 8 + tg * 2;
                float b0 = 0.f, b1 = 0.f;
                if (bias) { b0 = bias[col]; b1 = bias[col + 1]; }
                float2 v0, v1;
                v0.x = acc[mt][nt][0] + b0;
                v0.y = acc[mt][nt][1] + b1;
                v1.x = acc[mt][nt][2] + b0;
                v1.y = acc[mt][nt][3] + b1;
                *(float2*)(C + (size_t)row0 * N + col)       = v0;
                *(float2*)(C + (size_t)(row0 + 8) * N + col) = v1;
            }
        }
    } else if (mode == 1) {   // Q: single fp16, scaled, natural order
#pragma unroll
        for (int mt = 0; mt < 2; mt++) {
            int row0 = bm + wm + mt * 16 + g;
            int bb = row0 >> 11, seq = row0 & 2047;
#pragma unroll
            for (int nt = 0; nt < 8; nt++) {
                int col  = blockIdx.x * 128 + wn + nt * 8 + tg * 2;
                int hh   = col >> 7;
                int slot = (col & 127) >> 1;
                size_t base = ((size_t)(bb * NH + hh) * 2048 + seq) * 64 + slot;
                oh[base]          = h2pack(acc[mt][nt][0] * QK_SCALE, acc[mt][nt][1] * QK_SCALE);
                oh[base + 8 * 64] = h2pack(acc[mt][nt][2] * QK_SCALE, acc[mt][nt][3] * QK_SCALE);
            }
        }
    } else if (mode == 2) {   // K: single fp16, slot order
#pragma unroll
        for (int mt = 0; mt < 2; mt++) {
            int row0 = bm + wm + mt * 16 + g;
            int bb = row0 >> 11, seq = row0 & 2047;
#pragma unroll
            for (int nt = 0; nt < 8; nt++) {
                int col  = blockIdx.x * 128 + wn + nt * 8 + tg * 2;
                int hh   = col >> 7;
                int slot = ppos((col & 127) >> 1);
                size_t base = ((size_t)(bb * NH + hh) * 2048 + seq) * 64 + slot;
                oh[base]          = h2pack(acc[mt][nt][0], acc[mt][nt][1]);
                oh[base + 8 * 64] = h2pack(acc[mt][nt][2], acc[mt][nt][3]);
            }
        }
    } else if (mode == 3) {  // V transposed row-pair packs
#pragma unroll
        for (int mt = 0; mt < 2; mt++) {
            int row0 = bm + wm + mt * 16 + g;
            int bb = row0 >> 11, seq0 = row0 & 2047;
            int ppA = seq0 >> 1;
            int ppB = (seq0 + 8) >> 1;
            int slotA = (ppA >> 4) * 16 + ppos(ppA & 15);
            int slotB = (ppB >> 4) * 16 + ppos(ppB & 15);
#pragma unroll
            for (int nt = 0; nt < 8; nt++) {
                float o0 = acc[mt][nt][0], o1 = acc[mt][nt][1];
                float o2 = acc[mt][nt][2], o3 = acc[mt][nt][3];
                float q0 = __shfl_xor_sync(0xffffffffu, o0, 4);
                float q1 = __shfl_xor_sync(0xffffffffu, o1, 4);
                float q2 = __shfl_xor_sync(0xffffffffu, o2, 4);
                float q3 = __shfl_xor_sync(0xffffffffu, o3, 4);
                if (!(g & 1)) {
                    int col  = blockIdx.x * 128 + wn + nt * 8 + tg * 2;
                    int hh   = col >> 7;
                    int wcol = col & 127;
                    uint32_t* vb = oh + ((size_t)(bb * NH + hh) * 128 + wcol) * 1024;
                    vb[slotA]        = h2pack(o0, q0);
                    vb[1024 + slotA] = h2pack(o1, q1);
                    vb[slotB]        = h2pack(o2, q2);
                    vb[1024 + slotB] = h2pack(o3, q3);
                }
            }
        }
    } else {  // mode 4: A-format pairs (slot order), row width N/2
        const int sw = N >> 1;
#pragma unroll
        for (int mt = 0; mt < 2; mt++) {
            int row0 = bm + wm + mt * 16 + g;
#pragma unroll
            for (int nt = 0; nt < 8; nt++) {
                int col = blockIdx.x * 128 + wn + nt * 8 + tg * 2;
                int slot = ppos(col >> 1);
                oh[(size_t)row0 * sw + slot]       = h2pack(acc[mt][nt][0], acc[mt][nt][1]);
                oh[(size_t)(row0 + 8) * sw + slot] = h2pack(acc[mt][nt][2], acc[mt][nt][3]);
            }
        }
    }
#undef GISSUE
}

// ====================================================================
// fp16 register-resident causal flash attention.
// QK^T single-pass fp16 (Q and K both plain fp16; calibrated error OK).
// Two accumulator chain sets routed by kk parity keep reuse distance 8.
// ====================================================================
#define FBM 128
#define FBN 32
#define KS 72
#define VS 20
#define FA_U32 (2*32*KS + 2*128*VS)
#define FA_SMEM_BYTES (FA_U32 * 4)

__global__ __launch_bounds__(256) void flash_attn_cp(
    const uint32_t* __restrict__ Qh_g,
    const uint32_t* __restrict__ Kh_g,
    const uint32_t* __restrict__ Vt_g, uint32_t* __restrict__ Ctxp)
{
    extern __shared__ uint32_t smu[];
    uint32_t* Khs = smu;                    // [2][32][KS]
    uint32_t* Vts = smu + 2 * 32 * KS;      // [2][128][VS]
    const uint32_t sbase = (uint32_t)__cvta_generic_to_shared(smu);
    const uint32_t sKh = sbase;
    const uint32_t sVt = sbase + 2 * 32 * KS * 4;

    const int t    = threadIdx.x;
    const int lane = t & 31;
    const int warp = t >> 5;
    const int g    = lane >> 2;
    const int tg   = lane & 3;

    const int qt = gridDim.x - 1 - blockIdx.x;
    const int qb = qt * FBM;
    const int bh = blockIdx.y;
    const int b  = bh >> 4;
    const int h  = bh & 15;

    const uint32_t* Khg = Kh_g + (size_t)bh * 2048 * 64;
    const uint32_t* Vgg = Vt_g + (size_t)bh * 128 * 1024;

    const int gr0  = qb + warp * 16 + g;
    const int wmax = qb + warp * 16 + 15;

    uint32_t qh[8][4];
    {
        const uint32_t* qhg = Qh_g + ((size_t)bh * 2048 + gr0) * 64;
#pragma unroll
        for (int kk = 0; kk < 8; kk++) {
            qh[kk][0] = qhg[8 * kk + tg];
            qh[kk][1] = qhg[8 * 64 + 8 * kk + tg];
            qh[kk][2] = qhg[8 * kk + tg + 4];
            qh[kk][3] = qhg[8 * 64 + 8 * kk + tg + 4];
        }
    }

    float oacc[16][4];
#pragma unroll
    for (int nt = 0; nt < 16; nt++)
#pragma unroll
        for (int r = 0; r < 4; r++) oacc[nt][r] = 0.f;
    float m0 = -INFINITY, m1 = -INFINITY;
    float l0 = 0.f, l1 = 0.f;

    const int kr = t >> 4, kc = t & 15;
    const int vl = t >> 2, vc = t & 3;

#define ISSUE_KV(kb_, buf)                                                        \
    {                                                                             \
        const uint32_t* s1 = Khg + (size_t)((kb_) + kr) * 64 + kc * 4;            \
        const uint32_t* s2 = s1 + 16 * 64;                                        \
        uint32_t d1 = sKh + (buf) * (32 * KS * 4) + kr * (KS * 4) + kc * 16;      \
        CPA16(d1, s1);                                                            \
        CPA16(d1 + 16 * (KS * 4), s2);                                            \
        const uint32_t* s5 = Vgg + (size_t)vl * 1024 + ((kb_) >> 1) + vc * 4;     \
        const uint32_t* s6 = s5 + (size_t)64 * 1024;                              \
        uint32_t d5 = sVt + (buf) * (128 * VS * 4) + vl * (VS * 4) + vc * 16;     \
        CPA16(d5, s5);                                                            \
        CPA16(d5 + 64 * (VS * 4), s6);                                            \
        asm volatile("cp.async.commit_group;");                                   \
    }

    const int nkt = qb / FBN + 4;

    ISSUE_KV(0, 0);
    asm volatile("cp.async.wait_group 0;");
    __syncthreads();

    for (int kt = 0; kt < nkt; kt++) {
        const int kb  = kt * FBN;
        const int cur = kt & 1;
        const bool more = (kt + 1 < nkt);
        if (more) ISSUE_KV(kb + FBN, cur ^ 1);

        if (kb <= wmax) {
            const uint32_t* khb = Khs + cur * 32 * KS;

            // ---- S = Q K^T, single fp16; kk-parity chain split for ILP ----
            float shh[4][4], sxa[4][4];
#pragma unroll
            for (int nt = 0; nt < 4; nt++)
#pragma unroll
                for (int r = 0; r < 4; r++) { shh[nt][r] = 0.f; sxa[nt][r] = 0.f; }

#pragma unroll
            for (int kk = 0; kk < 8; kk++) {
                uint32_t bhv[4][2];
#pragma unroll
                for (int nt = 0; nt < 4; nt++) {
                    uint2 bh2 = *(const uint2*)&khb[(nt * 8 + g) * KS + kk * 8 + 2 * tg];
                    bhv[nt][0] = bh2.x; bhv[nt][1] = bh2.y;
                }
                if (kk & 1) {
#pragma unroll
                    for (int nt = 0; nt < 4; nt++) mma_f16(sxa[nt], qh[kk], bhv[nt]);
                } else {
#pragma unroll
                    for (int nt = 0; nt < 4; nt++) mma_f16(shh[nt], qh[kk], bhv[nt]);
                }
            }

            float s[4][4];
#pragma unroll
            for (int nt = 0; nt < 4; nt++) {
#pragma unroll
                for (int r = 0; r < 4; r++) s[nt][r] = shh[nt][r] + sxa[nt][r];
                if (kb + FBN - 1 > qb + warp * 16) {
                    int cb = kb + nt * 8 + 2 * tg;
                    if (cb     > gr0)     s[nt][0] = -INFINITY;
                    if (cb + 1 > gr0)     s[nt][1] = -INFINITY;
                    if (cb     > gr0 + 8) s[nt][2] = -INFINITY;
                    if (cb + 1 > gr0 + 8) s[nt][3] = -INFINITY;
                }
            }

            float mx0 = -INFINITY, mx1 = -INFINITY;
#pragma unroll
            for (int nt = 0; nt < 4; nt++) {
                mx0 = fmaxf(mx0, fmaxf(s[nt][0], s[nt][1]));
                mx1 = fmaxf(mx1, fmaxf(s[nt][2], s[nt][3]));
            }
            mx0 = fmaxf(mx0, __shfl_xor_sync(0xffffffffu, mx0, 1));
            mx0 = fmaxf(mx0, __shfl_xor_sync(0xffffffffu, mx0, 2));
            mx1 = fmaxf(mx1, __shfl_xor_sync(0xffffffffu, mx1, 1));
            mx1 = fmaxf(mx1, __shfl_xor_sync(0xffffffffu, mx1, 2));

            float nm0 = fmaxf(m0, mx0), nm1 = fmaxf(m1, mx1);
            float f0 = exp2f(m0 - nm0), f1 = exp2f(m1 - nm1);
            m0 = nm0; m1 = nm1;

            uint32_t pa[2][4];
            float s0 = 0.f, s1 = 0.f;
#pragma unroll
            for (int nt = 0; nt < 4; nt++) {
                float p0 = exp2f(s[nt][0] - nm0);
                float p1 = exp2f(s[nt][1] - nm0);
                float p2 = exp2f(s[nt][2] - nm1);
                float p3 = exp2f(s[nt][3] - nm1);
                s0 += p0 + p1;
                s1 += p2 + p3;
                pa[nt >> 1][(nt & 1) * 2 + 0] = h2pack(p0, p1);
                pa[nt >> 1][(nt & 1) * 2 + 1] = h2pack(p2, p3);
            }
            l0 = l0 * f0 + s0;
            l1 = l1 * f1 + s1;

            if (!__all_sync(0xffffffffu, (f0 == 1.f) && (f1 == 1.f))) {
#pragma unroll
                for (int nt = 0; nt < 16; nt++) {
                    oacc[nt][0] *= f0; oacc[nt][1] *= f0;
                    oacc[nt][2] *= f1; oacc[nt][3] *= f1;
                }
            }

            const uint32_t* vpb = Vts + cur * 128 * VS;
#pragma unroll
            for (int kk = 0; kk < 2; kk++) {
#pragma unroll
                for (int nt = 0; nt < 16; nt++) {
                    uint2 bv = *(const uint2*)&vpb[(nt * 8 + g) * VS + kk * 8 + 2 * tg];
                    uint32_t bb[2] = {bv.x, bv.y};
                    mma_f16(oacc[nt], pa[kk], bb);
                }
            }
        }

        if (more) asm volatile("cp.async.wait_group 0;");
        __syncthreads();
    }

    // ---- epilogue: write ctx as fp16 pairs in A-format ----
    l0 += __shfl_xor_sync(0xffffffffu, l0, 1);
    l0 += __shfl_xor_sync(0xffffffffu, l0, 2);
    l1 += __shfl_xor_sync(0xffffffffu, l1, 1);
    l1 += __shfl_xor_sync(0xffffffffu, l1, 2);
    float inv0 = 1.f / l0, inv1 = 1.f / l1;
    uint32_t* c0 = Ctxp + ((size_t)b * S_ + gr0) * 1024;
    uint32_t* c1 = Ctxp + ((size_t)b * S_ + gr0 + 8) * 1024;
#pragma unroll
    for (int nt = 0; nt < 16; nt++) {
        int colg = h * HD + nt * 8 + 2 * tg;
        int slot = ppos(colg >> 1);
        c0[slot] = h2pack(oacc[nt][0] * inv0, oacc[nt][1] * inv0);
        c1[slot] = h2pack(oacc[nt][2] * inv1, oacc[nt][3] * inv1);
    }
#undef ISSUE_KV
}

// ====================================================================
// launch
// ====================================================================
#define GEMM_SMEM (2 * GSTG * 128 * GS * 4)

extern "C" void kernel_launch(void* const* d_in, const int* in_sizes, int n_in,
                              void* d_out, int out_size)
{
    const float* x    = (const float*)d_in[0];
    const float* Wq   = (const float*)d_in[1];
    const float* Wdkv = (const float*)d_in[2];
    const float* Wuk  = (const float*)d_in[3];
    const float* Wuv  = (const float*)d_in[4];
    const float* Wout = (const float*)d_in[5];
    const float* bout = (const float*)d_in[6];
    float* out = (float*)d_out;

    uint32_t *xp, *latp, *ctxp, *qh, *kh, *vt;
    uint32_t *wqp, *wdkvp, *wukp, *wuvp, *woutp;
    cudaGetSymbolAddress((void**)&xp,    g_xp);
    cudaGetSymbolAddress((void**)&latp,  g_latp);
    cudaGetSymbolAddress((void**)&ctxp,  g_ctxp);
    cudaGetSymbolAddress((void**)&qh,    g_qh16);
    cudaGetSymbolAddress((void**)&kh,    g_kh16);
    cudaGetSymbolAddress((void**)&vt,    g_vt16);
    cudaGetSymbolAddress((void**)&wqp,   g_wqp);
    cudaGetSymbolAddress((void**)&wdkvp, g_wdkvp);
    cudaGetSymbolAddress((void**)&wukp,  g_wukp);
    cudaGetSymbolAddress((void**)&wuvp,  g_wuvp);
    cudaGetSymbolAddress((void**)&woutp, g_woutp);

    cudaFuncSetAttribute(flash_attn_cp,
                         cudaFuncAttributeMaxDynamicSharedMemorySize, FA_SMEM_BYTES);
    cudaFuncSetAttribute(f16_gemm,
                         cudaFuncAttributeMaxDynamicSharedMemorySize, GEMM_SMEM);

    // one-time conversions
    convert_x<<<ROWS, 256>>>(x, xp);
    convert_w<<<dim3(16, 64), 256>>>(Wq,   wqp,   DOUT);
    convert_w<<<dim3(2, 64),  256>>>(Wdkv, wdkvp, LAT);
    convert_w<<<dim3(16, 8),  256>>>(Wuk,  wukp,  DOUT);
    convert_w<<<dim3(16, 8),  256>>>(Wuv,  wuvp,  DOUT);
    convert_w<<<dim3(16, 64), 256>>>(Wout, woutp, DOUT);

    // q = x @ Wq -> Q fp16 (scaled, natural order)
    f16_gemm<<<dim3(16, 32), 256, GEMM_SMEM>>>(
        xp, 1024, wqp, nullptr, nullptr, ROWS, DOUT, DIN, 1, qh);
    // latent = x @ Wdkv -> A-format pairs
    f16_gemm<<<dim3(2, 32), 256, GEMM_SMEM>>>(
        xp, 1024, wdkvp, nullptr, nullptr, ROWS, LAT, DIN, 4, latp);
    // k = lat @ Wuk -> K fp16 (slot order)
    f16_gemm<<<dim3(16, 32), 256, GEMM_SMEM>>>(
        latp, 128, wukp, nullptr, nullptr, ROWS, DOUT, LAT, 2, kh);
    // v = lat @ Wuv -> V transposed packs
    f16_gemm<<<dim3(16, 32), 256, GEMM_SMEM>>>(
        latp, 128, wuvp, nullptr, nullptr, ROWS, DOUT, LAT, 3, vt);
    // attention -> ctx pairs
    flash_attn_cp<<<dim3(S_ / FBM, B_ * NH), 256, FA_SMEM_BYTES>>>(
        qh, kh, vt, ctxp);
    // out = ctx @ Wout + bias (fp32)
    f16_gemm<<<dim3(16, 32), 256, GEMM_SMEM>>>(
        ctxp, 1024, woutp, out, bout, ROWS, DOUT, DOUT, 0, nullptr);
}